// round 4
// baseline (speedup 1.0000x reference)
#include <cuda_runtime.h>
#include <cuda_bf16.h>

#define MAX_N 100000
#define MAX_E 1600000
#define MAX_G 4096
#define FDIM 128
#define BN_EPS 1e-5f

// ---------------- scratch (device globals; no allocation allowed) -------------
__device__ float g_H[(size_t)MAX_N * FDIM];     // GEMM output h
__device__ float g_AGG[(size_t)MAX_N * FDIM];   // aggregation buffer
__device__ float g_X[(size_t)MAX_N * FDIM];     // layer activation (next input)
__device__ float g_dinv[MAX_N];
__device__ int   g_deg[MAX_N];
__device__ float g_stats[2 * FDIM];             // sum[128], sumsq[128]
__device__ float g_scale[FDIM];
__device__ float g_shift[FDIM];
__device__ float g_pool[(size_t)MAX_G * FDIM];
__device__ float g_cnt[MAX_G];

// ---------------- helpers -----------------------------------------------------
__device__ __forceinline__ void red_add_f32(float* p, float v) {
    asm volatile("red.global.add.f32 [%0], %1;" :: "l"(p), "f"(v) : "memory");
}

// ---------------- init: zero deg / pool / cnt ---------------------------------
__global__ void k_zero(int n_nodes, int n_graphs) {
    int i = blockIdx.x * blockDim.x + threadIdx.x;
    if (i < n_nodes) g_deg[i] = 0;
    if (i < n_graphs * FDIM) g_pool[i] = 0.f;
    if (i < n_graphs) g_cnt[i] = 0.f;
}

__global__ void k_deg(const int* __restrict__ dst, int n_edges) {
    int e = blockIdx.x * blockDim.x + threadIdx.x;
    if (e < n_edges) atomicAdd(&g_deg[dst[e]], 1);
}

__global__ void k_dinv(int n_nodes) {
    int i = blockIdx.x * blockDim.x + threadIdx.x;
    if (i < n_nodes) g_dinv[i] = rsqrtf((float)g_deg[i] + 1.0f);
}

// ---------------- GEMM: H = Xin @ W ; AGG = H*dinv^2 + b ----------------------
// block: 64 rows x 128 cols (full width), 256 threads, 8x4 micro-tile per thread
// use_gx: 0 -> input is Xin (harness pointer), 1 -> input is g_X (device global)
__global__ void __launch_bounds__(256)
k_gemm(const float* __restrict__ Xin, int use_gx,
       const float* __restrict__ W, const float* __restrict__ b, int n_nodes) {
    __shared__ float sX[64][33];
    __shared__ float sW[32][128];

    const float* __restrict__ in = use_gx ? (const float*)g_X : Xin;

    const int row0 = blockIdx.x * 64;
    const int ct = threadIdx.x & 31;   // column group: cols [ct*4, ct*4+4)
    const int rt = threadIdx.x >> 5;   // warp id 0..7: rows r*8 + rt

    float acc[8][4];
#pragma unroll
    for (int r = 0; r < 8; r++)
#pragma unroll
        for (int c = 0; c < 4; c++) acc[r][c] = 0.f;

    for (int kb = 0; kb < FDIM; kb += 32) {
        // load 64x32 slab of input
        for (int l = threadIdx.x; l < 64 * 32; l += 256) {
            int r = l >> 5, c = l & 31;
            int gr = row0 + r;
            sX[r][c] = (gr < n_nodes) ? in[(size_t)gr * FDIM + kb + c] : 0.f;
        }
        // load 32x128 slab of W
        for (int l = threadIdx.x; l < 32 * 128; l += 256) {
            int r = l >> 7, c = l & 127;
            sW[r][c] = W[(size_t)(kb + r) * FDIM + c];
        }
        __syncthreads();

#pragma unroll
        for (int k = 0; k < 32; k++) {
            float4 w4 = *reinterpret_cast<const float4*>(&sW[k][ct * 4]);
#pragma unroll
            for (int r = 0; r < 8; r++) {
                float xv = sX[r * 8 + rt][k];
                acc[r][0] += xv * w4.x;
                acc[r][1] += xv * w4.y;
                acc[r][2] += xv * w4.z;
                acc[r][3] += xv * w4.w;
            }
        }
        __syncthreads();
    }

    float4 b4 = *reinterpret_cast<const float4*>(&b[ct * 4]);
#pragma unroll
    for (int r = 0; r < 8; r++) {
        int gr = row0 + r * 8 + rt;
        if (gr < n_nodes) {
            float di = g_dinv[gr];
            float d2 = di * di;
            float4 h4 = make_float4(acc[r][0], acc[r][1], acc[r][2], acc[r][3]);
            *reinterpret_cast<float4*>(&g_H[(size_t)gr * FDIM + ct * 4]) = h4;
            float4 a4 = make_float4(h4.x * d2 + b4.x, h4.y * d2 + b4.y,
                                    h4.z * d2 + b4.z, h4.w * d2 + b4.w);
            *reinterpret_cast<float4*>(&g_AGG[(size_t)gr * FDIM + ct * 4]) = a4;
        }
    }
}

// ---------------- edge scatter: AGG[dst] += H[src]*norm, warp per edge --------
__global__ void __launch_bounds__(256)
k_scatter(const int* __restrict__ src, const int* __restrict__ dst, int n_edges) {
    int w = (blockIdx.x * blockDim.x + threadIdx.x) >> 5;
    int lane = threadIdx.x & 31;
    if (w >= n_edges) return;
    int s = src[w];
    int d = dst[w];
    float nrm = g_dinv[s] * g_dinv[d];
    float4 v = reinterpret_cast<const float4*>(g_H)[(size_t)s * 32 + lane];
    float* p = &g_AGG[(size_t)d * FDIM + lane * 4];
    red_add_f32(p + 0, v.x * nrm);
    red_add_f32(p + 1, v.y * nrm);
    red_add_f32(p + 2, v.z * nrm);
    red_add_f32(p + 3, v.w * nrm);
}

// ---------------- BN stats ----------------------------------------------------
__global__ void k_zero_stats() {
    if (threadIdx.x < 2 * FDIM) g_stats[threadIdx.x] = 0.f;
}

__global__ void __launch_bounds__(256)
k_stats(int n_nodes) {
    __shared__ float ssum[FDIM];
    __shared__ float ssq[FDIM];
    int lane = threadIdx.x & 31;
    int warp = threadIdx.x >> 5;
    int nwarps = gridDim.x * 8;

    float4 s = make_float4(0.f, 0.f, 0.f, 0.f);
    float4 q = make_float4(0.f, 0.f, 0.f, 0.f);
    for (int r = blockIdx.x * 8 + warp; r < n_nodes; r += nwarps) {
        float4 v = reinterpret_cast<const float4*>(g_AGG)[(size_t)r * 32 + lane];
        s.x += v.x; s.y += v.y; s.z += v.z; s.w += v.w;
        q.x += v.x * v.x; q.y += v.y * v.y; q.z += v.z * v.z; q.w += v.w * v.w;
    }
    if (threadIdx.x < FDIM) { ssum[threadIdx.x] = 0.f; ssq[threadIdx.x] = 0.f; }
    __syncthreads();
    int c = lane * 4;
    atomicAdd(&ssum[c + 0], s.x); atomicAdd(&ssum[c + 1], s.y);
    atomicAdd(&ssum[c + 2], s.z); atomicAdd(&ssum[c + 3], s.w);
    atomicAdd(&ssq[c + 0], q.x);  atomicAdd(&ssq[c + 1], q.y);
    atomicAdd(&ssq[c + 2], q.z);  atomicAdd(&ssq[c + 3], q.w);
    __syncthreads();
    if (threadIdx.x < FDIM) {
        atomicAdd(&g_stats[threadIdx.x], ssum[threadIdx.x]);
        atomicAdd(&g_stats[FDIM + threadIdx.x], ssq[threadIdx.x]);
    }
}

__global__ void k_bnfin(const float* __restrict__ gma, const float* __restrict__ bta,
                        int n_nodes) {
    int c = threadIdx.x;  // 128 threads
    float inv_n = 1.0f / (float)n_nodes;
    float mu = g_stats[c] * inv_n;
    float var = g_stats[FDIM + c] * inv_n - mu * mu;
    float rstd = rsqrtf(var + BN_EPS);
    float sc = rstd * gma[c];
    g_scale[c] = sc;
    g_shift[c] = bta[c] - mu * sc;
}

__global__ void __launch_bounds__(256)
k_bnrelu(int n_nodes) {
    int i = blockIdx.x * blockDim.x + threadIdx.x;  // over n_nodes*32 float4s
    if (i >= n_nodes * 32) return;
    int c = (i & 31) * 4;
    float4 v = reinterpret_cast<const float4*>(g_AGG)[i];
    float4 sc = *reinterpret_cast<const float4*>(&g_scale[c]);
    float4 sh = *reinterpret_cast<const float4*>(&g_shift[c]);
    v.x = fmaxf(v.x * sc.x + sh.x, 0.f);
    v.y = fmaxf(v.y * sc.y + sh.y, 0.f);
    v.z = fmaxf(v.z * sc.z + sh.z, 0.f);
    v.w = fmaxf(v.w * sc.w + sh.w, 0.f);
    reinterpret_cast<float4*>(g_X)[i] = v;
}

// ---------------- global mean pool (warp per node) -----------------------------
__global__ void __launch_bounds__(256)
k_pool(const int* __restrict__ batch, int n_nodes) {
    int w = (blockIdx.x * blockDim.x + threadIdx.x) >> 5;
    int lane = threadIdx.x & 31;
    if (w >= n_nodes) return;
    int g = batch[w];
    float4 v = reinterpret_cast<const float4*>(g_X)[(size_t)w * 32 + lane];
    float* p = &g_pool[(size_t)g * FDIM + lane * 4];
    red_add_f32(p + 0, v.x);
    red_add_f32(p + 1, v.y);
    red_add_f32(p + 2, v.z);
    red_add_f32(p + 3, v.w);
    if (lane == 0) atomicAdd(&g_cnt[g], 1.0f);
}

// ---------------- final FC: out = (pool/cnt) @ fcW + fcb ----------------------
__global__ void __launch_bounds__(256)
k_fc(const float* __restrict__ fcW, const float* __restrict__ fcb,
     float* __restrict__ out, int n_graphs) {
    __shared__ float sW[FDIM * 64];
    for (int l = threadIdx.x; l < FDIM * 64; l += 256) sW[l] = fcW[l];
    __syncthreads();
    int g = blockIdx.x * 4 + (threadIdx.x >> 6);
    int c = threadIdx.x & 63;
    if (g >= n_graphs) return;
    float inv = 1.0f / fmaxf(g_cnt[g], 1.0f);
    float acc = 0.f;
#pragma unroll 16
    for (int k = 0; k < FDIM; k++) acc += g_pool[(size_t)g * FDIM + k] * sW[k * 64 + c];
    out[(size_t)g * 64 + c] = acc * inv + fcb[c];
}

// ---------------- launch ------------------------------------------------------
extern "C" void kernel_launch(void* const* d_in, const int* in_sizes, int n_in,
                              void* d_out, int out_size) {
    const float* x     = (const float*)d_in[0];
    const int*   ei    = (const int*)d_in[1];     // int32! (JAX x64 disabled)
    const int*   batch = (const int*)d_in[2];     // int32!
    const float* W1 = (const float*)d_in[3];
    const float* b1 = (const float*)d_in[4];
    const float* g1 = (const float*)d_in[5];
    const float* be1 = (const float*)d_in[6];
    const float* W2 = (const float*)d_in[7];
    const float* b2 = (const float*)d_in[8];
    const float* g2 = (const float*)d_in[9];
    const float* be2 = (const float*)d_in[10];
    const float* W3 = (const float*)d_in[11];
    const float* b3 = (const float*)d_in[12];
    const float* g3 = (const float*)d_in[13];
    const float* be3 = (const float*)d_in[14];
    const float* fcW = (const float*)d_in[15];
    const float* fcb = (const float*)d_in[16];
    float* out = (float*)d_out;

    const int n_nodes  = in_sizes[0] / FDIM;
    const int n_edges  = in_sizes[1] / 2;
    const int n_graphs = out_size / 64;
    const int* src = ei;
    const int* dst = ei + n_edges;

    // init: degrees + pool accumulators
    {
        int work = n_graphs * FDIM;
        if (n_nodes > work) work = n_nodes;
        k_zero<<<(work + 255) / 256, 256>>>(n_nodes, n_graphs);
    }
    k_deg<<<(n_edges + 255) / 256, 256>>>(dst, n_edges);
    k_dinv<<<(n_nodes + 255) / 256, 256>>>(n_nodes);

    const int gemm_grid    = (n_nodes + 63) / 64;
    const int scatter_grid = (int)(((long long)n_edges * 32 + 255) / 256);
    const int elem_grid    = (n_nodes * 32 + 255) / 256;  // float4 per thread

    const float* Ws[3]  = {W1, W2, W3};
    const float* bs[3]  = {b1, b2, b3};
    const float* gs[3]  = {g1, g2, g3};
    const float* bes[3] = {be1, be2, be3};

    for (int layer = 0; layer < 3; layer++) {
        k_gemm<<<gemm_grid, 256>>>(layer == 0 ? x : nullptr, layer == 0 ? 0 : 1,
                                   Ws[layer], bs[layer], n_nodes);
        k_scatter<<<scatter_grid, 256>>>(src, dst, n_edges);
        k_zero_stats<<<1, 256>>>();
        k_stats<<<592, 256>>>(n_nodes);
        k_bnfin<<<1, 128>>>(gs[layer], bes[layer], n_nodes);
        k_bnrelu<<<elem_grid, 256>>>(n_nodes);
    }

    k_pool<<<(n_nodes * 32 + 255) / 256, 256>>>(batch, n_nodes);
    k_fc<<<(n_graphs + 3) / 4, 256>>>(fcW, fcb, out, n_graphs);
}

// round 5
// speedup vs baseline: 2.1116x; 2.1116x over previous
#include <cuda_runtime.h>
#include <cuda_bf16.h>

#define MAX_N 100000
#define MAX_E 1600000
#define MAX_G 4096
#define FDIM 128
#define BN_EPS 1e-5f

// ---------------- scratch (device globals; no allocation allowed) -------------
__device__ float g_H[(size_t)MAX_N * FDIM];     // GEMM output h
__device__ float g_AGG[(size_t)MAX_N * FDIM];   // aggregation buffer
__device__ float g_X[(size_t)MAX_N * FDIM];     // layer activation (next input)
__device__ float g_dinv[MAX_N];
__device__ int   g_deg[MAX_N];
__device__ int   g_rowptr[MAX_N + 1];
__device__ int   g_cursor[MAX_N];
__device__ int   g_csr_src[MAX_E];
__device__ float g_csr_nrm[MAX_E];
__device__ float g_stats[2 * FDIM];             // sum[128], sumsq[128]
__device__ float g_scale[FDIM];
__device__ float g_shift[FDIM];
__device__ float g_pool[(size_t)MAX_G * FDIM];
__device__ float g_cnt[MAX_G];

// ---------------- helpers -----------------------------------------------------
__device__ __forceinline__ void red_add_f32(float* p, float v) {
    asm volatile("red.global.add.f32 [%0], %1;" :: "l"(p), "f"(v) : "memory");
}

// ---------------- init: zero deg / pool / cnt ---------------------------------
__global__ void k_zero(int n_nodes, int n_graphs) {
    int i = blockIdx.x * blockDim.x + threadIdx.x;
    if (i < n_nodes) g_deg[i] = 0;
    if (i < n_graphs * FDIM) g_pool[i] = 0.f;
    if (i < n_graphs) g_cnt[i] = 0.f;
}

__global__ void k_deg(const int* __restrict__ dst, int n_edges) {
    int e = blockIdx.x * blockDim.x + threadIdx.x;
    if (e < n_edges) atomicAdd(&g_deg[dst[e]], 1);
}

__global__ void k_dinv(int n_nodes) {
    int i = blockIdx.x * blockDim.x + threadIdx.x;
    if (i < n_nodes) g_dinv[i] = rsqrtf((float)g_deg[i] + 1.0f);
}

// ---------------- single-block chunked exclusive scan of degrees --------------
__global__ void k_scan(int n_nodes) {
    __shared__ int s[1024];
    __shared__ int carry;
    if (threadIdx.x == 0) carry = 0;
    __syncthreads();
    for (int base = 0; base < n_nodes; base += 1024) {
        int i = base + threadIdx.x;
        int v = (i < n_nodes) ? g_deg[i] : 0;
        s[threadIdx.x] = v;
        __syncthreads();
#pragma unroll
        for (int off = 1; off < 1024; off <<= 1) {
            int t = (threadIdx.x >= off) ? s[threadIdx.x - off] : 0;
            __syncthreads();
            s[threadIdx.x] += t;
            __syncthreads();
        }
        if (i < n_nodes) g_rowptr[i + 1] = carry + s[threadIdx.x];
        int tot = s[1023];
        __syncthreads();
        if (threadIdx.x == 0) carry += tot;
        __syncthreads();
    }
    if (threadIdx.x == 0) g_rowptr[0] = 0;
}

__global__ void k_cursor(int n_nodes) {
    int i = blockIdx.x * blockDim.x + threadIdx.x;
    if (i < n_nodes) g_cursor[i] = g_rowptr[i];
}

__global__ void k_fill(const int* __restrict__ src, const int* __restrict__ dst,
                       int n_edges) {
    int e = blockIdx.x * blockDim.x + threadIdx.x;
    if (e >= n_edges) return;
    int s = src[e];
    int d = dst[e];
    int pos = atomicAdd(&g_cursor[d], 1);
    g_csr_src[pos] = s;
    g_csr_nrm[pos] = g_dinv[s] * g_dinv[d];
}

// ---------------- GEMM: H = Xin @ W -------------------------------------------
// block: 64 rows x 128 cols, 256 threads, 8x4 micro-tile per thread
__global__ void __launch_bounds__(256)
k_gemm(const float* __restrict__ Xin, int use_gx,
       const float* __restrict__ W, int n_nodes) {
    __shared__ float sX[64][33];
    __shared__ float sW[32][128];

    const float* __restrict__ in = use_gx ? (const float*)g_X : Xin;

    const int row0 = blockIdx.x * 64;
    const int ct = threadIdx.x & 31;
    const int rt = threadIdx.x >> 5;

    float acc[8][4];
#pragma unroll
    for (int r = 0; r < 8; r++)
#pragma unroll
        for (int c = 0; c < 4; c++) acc[r][c] = 0.f;

    for (int kb = 0; kb < FDIM; kb += 32) {
        for (int l = threadIdx.x; l < 64 * 32; l += 256) {
            int r = l >> 5, c = l & 31;
            int gr = row0 + r;
            sX[r][c] = (gr < n_nodes) ? in[(size_t)gr * FDIM + kb + c] : 0.f;
        }
        for (int l = threadIdx.x; l < 32 * 128; l += 256) {
            int r = l >> 7, c = l & 127;
            sW[r][c] = W[(size_t)(kb + r) * FDIM + c];
        }
        __syncthreads();

#pragma unroll
        for (int k = 0; k < 32; k++) {
            float4 w4 = *reinterpret_cast<const float4*>(&sW[k][ct * 4]);
#pragma unroll
            for (int r = 0; r < 8; r++) {
                float xv = sX[r * 8 + rt][k];
                acc[r][0] += xv * w4.x;
                acc[r][1] += xv * w4.y;
                acc[r][2] += xv * w4.z;
                acc[r][3] += xv * w4.w;
            }
        }
        __syncthreads();
    }

#pragma unroll
    for (int r = 0; r < 8; r++) {
        int gr = row0 + r * 8 + rt;
        if (gr < n_nodes) {
            float4 h4 = make_float4(acc[r][0], acc[r][1], acc[r][2], acc[r][3]);
            *reinterpret_cast<float4*>(&g_H[(size_t)gr * FDIM + ct * 4]) = h4;
        }
    }
}

// ---------------- gather: AGG[d] = sum_in H[s]*nrm + H[d]*dinv^2 + b ----------
// one warp per dst node (grid-stride); fuses BN sum/sumsq accumulation
__global__ void k_zero_stats() {
    if (threadIdx.x < 2 * FDIM) g_stats[threadIdx.x] = 0.f;
}

__global__ void __launch_bounds__(256)
k_gather(const float* __restrict__ b, int n_nodes) {
    __shared__ float ssum[FDIM];
    __shared__ float ssq[FDIM];
    if (threadIdx.x < FDIM) { ssum[threadIdx.x] = 0.f; ssq[threadIdx.x] = 0.f; }
    __syncthreads();

    const int lane = threadIdx.x & 31;
    const int warp = threadIdx.x >> 5;
    const int nwarps = gridDim.x * 8;
    const float4 b4 = *reinterpret_cast<const float4*>(&b[lane * 4]);

    float4 sacc = make_float4(0.f, 0.f, 0.f, 0.f);
    float4 qacc = make_float4(0.f, 0.f, 0.f, 0.f);

    for (int d = blockIdx.x * 8 + warp; d < n_nodes; d += nwarps) {
        const int rs = g_rowptr[d];
        const int re = g_rowptr[d + 1];
        const float di = g_dinv[d];
        const float d2 = di * di;

        float4 h = reinterpret_cast<const float4*>(g_H)[(size_t)d * 32 + lane];
        float4 acc = make_float4(h.x * d2 + b4.x, h.y * d2 + b4.y,
                                 h.z * d2 + b4.z, h.w * d2 + b4.w);

        int e0 = rs;
        // full 32-edge chunks: static inner loop so ptxas pipelines the gathers
        for (; e0 + 32 <= re; e0 += 32) {
            int   sl = g_csr_src[e0 + lane];
            float nl = g_csr_nrm[e0 + lane];
#pragma unroll
            for (int j = 0; j < 32; j++) {
                int   sj = __shfl_sync(0xffffffffu, sl, j);
                float nj = __shfl_sync(0xffffffffu, nl, j);
                float4 v = reinterpret_cast<const float4*>(g_H)[(size_t)sj * 32 + lane];
                acc.x += v.x * nj; acc.y += v.y * nj;
                acc.z += v.z * nj; acc.w += v.w * nj;
            }
        }
        // remainder
        if (e0 < re) {
            int cnt = re - e0;
            int   sl = (lane < cnt) ? g_csr_src[e0 + lane] : 0;
            float nl = (lane < cnt) ? g_csr_nrm[e0 + lane] : 0.f;
            for (int j = 0; j < cnt; j++) {
                int   sj = __shfl_sync(0xffffffffu, sl, j);
                float nj = __shfl_sync(0xffffffffu, nl, j);
                float4 v = reinterpret_cast<const float4*>(g_H)[(size_t)sj * 32 + lane];
                acc.x += v.x * nj; acc.y += v.y * nj;
                acc.z += v.z * nj; acc.w += v.w * nj;
            }
        }

        reinterpret_cast<float4*>(g_AGG)[(size_t)d * 32 + lane] = acc;
        sacc.x += acc.x; sacc.y += acc.y; sacc.z += acc.z; sacc.w += acc.w;
        qacc.x += acc.x * acc.x; qacc.y += acc.y * acc.y;
        qacc.z += acc.z * acc.z; qacc.w += acc.w * acc.w;
    }

    int c = lane * 4;
    atomicAdd(&ssum[c + 0], sacc.x); atomicAdd(&ssum[c + 1], sacc.y);
    atomicAdd(&ssum[c + 2], sacc.z); atomicAdd(&ssum[c + 3], sacc.w);
    atomicAdd(&ssq[c + 0], qacc.x);  atomicAdd(&ssq[c + 1], qacc.y);
    atomicAdd(&ssq[c + 2], qacc.z);  atomicAdd(&ssq[c + 3], qacc.w);
    __syncthreads();
    if (threadIdx.x < FDIM) {
        atomicAdd(&g_stats[threadIdx.x], ssum[threadIdx.x]);
        atomicAdd(&g_stats[FDIM + threadIdx.x], ssq[threadIdx.x]);
    }
}

// ---------------- BN finalize + apply ------------------------------------------
__global__ void k_bnfin(const float* __restrict__ gma, const float* __restrict__ bta,
                        int n_nodes) {
    int c = threadIdx.x;  // 128 threads
    float inv_n = 1.0f / (float)n_nodes;
    float mu = g_stats[c] * inv_n;
    float var = g_stats[FDIM + c] * inv_n - mu * mu;
    float rstd = rsqrtf(var + BN_EPS);
    float sc = rstd * gma[c];
    g_scale[c] = sc;
    g_shift[c] = bta[c] - mu * sc;
}

__global__ void __launch_bounds__(256)
k_bnrelu(int n_nodes) {
    int i = blockIdx.x * blockDim.x + threadIdx.x;
    if (i >= n_nodes * 32) return;
    int c = (i & 31) * 4;
    float4 v = reinterpret_cast<const float4*>(g_AGG)[i];
    float4 sc = *reinterpret_cast<const float4*>(&g_scale[c]);
    float4 sh = *reinterpret_cast<const float4*>(&g_shift[c]);
    v.x = fmaxf(v.x * sc.x + sh.x, 0.f);
    v.y = fmaxf(v.y * sc.y + sh.y, 0.f);
    v.z = fmaxf(v.z * sc.z + sh.z, 0.f);
    v.w = fmaxf(v.w * sc.w + sh.w, 0.f);
    reinterpret_cast<float4*>(g_X)[i] = v;
}

// ---------------- global mean pool (warp per node) -----------------------------
__global__ void __launch_bounds__(256)
k_pool(const int* __restrict__ batch, int n_nodes) {
    int w = (blockIdx.x * blockDim.x + threadIdx.x) >> 5;
    int lane = threadIdx.x & 31;
    if (w >= n_nodes) return;
    int g = batch[w];
    float4 v = reinterpret_cast<const float4*>(g_X)[(size_t)w * 32 + lane];
    float* p = &g_pool[(size_t)g * FDIM + lane * 4];
    red_add_f32(p + 0, v.x);
    red_add_f32(p + 1, v.y);
    red_add_f32(p + 2, v.z);
    red_add_f32(p + 3, v.w);
    if (lane == 0) atomicAdd(&g_cnt[g], 1.0f);
}

// ---------------- final FC: out = (pool/cnt) @ fcW + fcb ----------------------
__global__ void __launch_bounds__(256)
k_fc(const float* __restrict__ fcW, const float* __restrict__ fcb,
     float* __restrict__ out, int n_graphs) {
    __shared__ float sW[FDIM * 64];
    for (int l = threadIdx.x; l < FDIM * 64; l += 256) sW[l] = fcW[l];
    __syncthreads();
    int g = blockIdx.x * 4 + (threadIdx.x >> 6);
    int c = threadIdx.x & 63;
    if (g >= n_graphs) return;
    float inv = 1.0f / fmaxf(g_cnt[g], 1.0f);
    float acc = 0.f;
#pragma unroll 16
    for (int k = 0; k < FDIM; k++) acc += g_pool[(size_t)g * FDIM + k] * sW[k * 64 + c];
    out[(size_t)g * 64 + c] = acc * inv + fcb[c];
}

// ---------------- launch ------------------------------------------------------
extern "C" void kernel_launch(void* const* d_in, const int* in_sizes, int n_in,
                              void* d_out, int out_size) {
    const float* x     = (const float*)d_in[0];
    const int*   ei    = (const int*)d_in[1];     // int32 (JAX x64 disabled)
    const int*   batch = (const int*)d_in[2];
    const float* W1 = (const float*)d_in[3];
    const float* b1 = (const float*)d_in[4];
    const float* g1 = (const float*)d_in[5];
    const float* be1 = (const float*)d_in[6];
    const float* W2 = (const float*)d_in[7];
    const float* b2 = (const float*)d_in[8];
    const float* g2 = (const float*)d_in[9];
    const float* be2 = (const float*)d_in[10];
    const float* W3 = (const float*)d_in[11];
    const float* b3 = (const float*)d_in[12];
    const float* g3 = (const float*)d_in[13];
    const float* be3 = (const float*)d_in[14];
    const float* fcW = (const float*)d_in[15];
    const float* fcb = (const float*)d_in[16];
    float* out = (float*)d_out;

    const int n_nodes  = in_sizes[0] / FDIM;
    const int n_edges  = in_sizes[1] / 2;
    const int n_graphs = out_size / 64;
    const int* src = ei;
    const int* dst = ei + n_edges;

    // ---- CSR build (once per call) ----
    {
        int work = n_graphs * FDIM;
        if (n_nodes > work) work = n_nodes;
        k_zero<<<(work + 255) / 256, 256>>>(n_nodes, n_graphs);
    }
    k_deg<<<(n_edges + 255) / 256, 256>>>(dst, n_edges);
    k_dinv<<<(n_nodes + 255) / 256, 256>>>(n_nodes);
    k_scan<<<1, 1024>>>(n_nodes);
    k_cursor<<<(n_nodes + 255) / 256, 256>>>(n_nodes);
    k_fill<<<(n_edges + 255) / 256, 256>>>(src, dst, n_edges);

    const int gemm_grid   = (n_nodes + 63) / 64;
    const int gather_grid = 1184;   // 148 SMs * 8 blocks
    const int elem_grid   = (n_nodes * 32 + 255) / 256;

    const float* Ws[3]  = {W1, W2, W3};
    const float* bs[3]  = {b1, b2, b3};
    const float* gs[3]  = {g1, g2, g3};
    const float* bes[3] = {be1, be2, be3};

    for (int layer = 0; layer < 3; layer++) {
        k_gemm<<<gemm_grid, 256>>>(layer == 0 ? x : nullptr, layer == 0 ? 0 : 1,
                                   Ws[layer], n_nodes);
        k_zero_stats<<<1, 256>>>();
        k_gather<<<gather_grid, 256>>>(bs[layer], n_nodes);
        k_bnfin<<<1, 128>>>(gs[layer], bes[layer], n_nodes);
        k_bnrelu<<<elem_grid, 256>>>(n_nodes);
    }

    k_pool<<<(n_nodes * 32 + 255) / 256, 256>>>(batch, n_nodes);
    k_fc<<<(n_graphs + 3) / 4, 256>>>(fcW, fcb, out, n_graphs);
}

// round 6
// speedup vs baseline: 2.4618x; 1.1659x over previous
#include <cuda_runtime.h>
#include <cuda_bf16.h>

#define MAX_N 100000
#define MAX_E 1600000
#define MAX_G 4096
#define FDIM 128
#define BN_EPS 1e-5f
#define SCAN_B 1024
#define MAX_BLK 128   // ceil(MAX_N/1024) = 98 <= 128

// ---------------- scratch (device globals; no allocation allowed) -------------
__device__ float g_H[(size_t)MAX_N * FDIM];     // GEMM output h
__device__ float g_AGG[(size_t)MAX_N * FDIM];   // aggregation buffer
__device__ float g_X[(size_t)MAX_N * FDIM];     // post BN+ReLU (pool input)
__device__ float g_dinv[MAX_N];
__device__ int   g_deg[MAX_N];
__device__ int   g_rowptr[MAX_N + 1];
__device__ int   g_cursor[MAX_N];
__device__ int   g_bsum[MAX_BLK];
__device__ int   g_boff[MAX_BLK];
__device__ int   g_csr_src[MAX_E];
__device__ float g_csr_nrm[MAX_E];
__device__ float g_stats[2 * FDIM];             // sum[128], sumsq[128]
__device__ float g_scale[FDIM];
__device__ float g_shift[FDIM];
__device__ float g_pool[(size_t)MAX_G * FDIM];
__device__ float g_cnt[MAX_G];

// ---------------- helpers -----------------------------------------------------
__device__ __forceinline__ void red_add_f32(float* p, float v) {
    asm volatile("red.global.add.f32 [%0], %1;" :: "l"(p), "f"(v) : "memory");
}

// ---------------- init: zero deg / pool / cnt ---------------------------------
__global__ void k_zero(int n_nodes, int n_graphs) {
    int i = blockIdx.x * blockDim.x + threadIdx.x;
    if (i < n_nodes) g_deg[i] = 0;
    if (i < n_graphs * FDIM) g_pool[i] = 0.f;
    if (i < n_graphs) g_cnt[i] = 0.f;
}

__global__ void k_deg(const int* __restrict__ dst, int n_edges) {
    int e = blockIdx.x * blockDim.x + threadIdx.x;
    if (e < n_edges) atomicAdd(&g_deg[dst[e]], 1);
}

__global__ void k_dinv(int n_nodes) {
    int i = blockIdx.x * blockDim.x + threadIdx.x;
    if (i < n_nodes) g_dinv[i] = rsqrtf((float)g_deg[i] + 1.0f);
}

// ---------------- parallel scan: phase 1 — per-block sums ---------------------
__global__ void __launch_bounds__(SCAN_B)
k_bsum(int n_nodes) {
    int i = blockIdx.x * SCAN_B + threadIdx.x;
    int v = (i < n_nodes) ? g_deg[i] : 0;
    // warp reduce
    for (int off = 16; off > 0; off >>= 1) v += __shfl_down_sync(0xffffffffu, v, off);
    __shared__ int ws[32];
    int lane = threadIdx.x & 31, w = threadIdx.x >> 5;
    if (lane == 0) ws[w] = v;
    __syncthreads();
    if (w == 0) {
        int s = ws[lane];
        for (int off = 16; off > 0; off >>= 1) s += __shfl_down_sync(0xffffffffu, s, off);
        if (lane == 0) g_bsum[blockIdx.x] = s;
    }
}

// ---------------- phase 2 — scan block sums (single small block) --------------
__global__ void k_bscan(int nblocks) {
    __shared__ int s[MAX_BLK];
    int tid = threadIdx.x;
    int v = (tid < nblocks) ? g_bsum[tid] : 0;
    s[tid] = v;
    __syncthreads();
#pragma unroll
    for (int off = 1; off < MAX_BLK; off <<= 1) {
        int t = (tid >= off) ? s[tid - off] : 0;
        __syncthreads();
        s[tid] += t;
        __syncthreads();
    }
    g_boff[tid] = (tid > 0) ? s[tid - 1] : 0;  // exclusive
}

// ---------------- phase 3 — per-block local scan + offset; fills cursor -------
__global__ void __launch_bounds__(SCAN_B)
k_scanfin(int n_nodes) {
    int i = blockIdx.x * SCAN_B + threadIdx.x;
    int v = (i < n_nodes) ? g_deg[i] : 0;
    int lane = threadIdx.x & 31, w = threadIdx.x >> 5;
    // warp inclusive scan
    int x = v;
#pragma unroll
    for (int off = 1; off < 32; off <<= 1) {
        int t = __shfl_up_sync(0xffffffffu, x, off);
        if (lane >= off) x += t;
    }
    __shared__ int ws[32];
    if (lane == 31) ws[w] = x;
    __syncthreads();
    if (w == 0) {
        int s = ws[lane];
#pragma unroll
        for (int off = 1; off < 32; off <<= 1) {
            int t = __shfl_up_sync(0xffffffffu, s, off);
            if (lane >= off) s += t;
        }
        ws[lane] = s;
    }
    __syncthreads();
    int incl = x + ((w > 0) ? ws[w - 1] : 0) + g_boff[blockIdx.x];
    if (i < n_nodes) {
        g_rowptr[i + 1] = incl;
        g_cursor[i] = incl - v;  // exclusive = start of row
    }
    if (i == 0) g_rowptr[0] = 0;
}

__global__ void k_fill(const int* __restrict__ src, const int* __restrict__ dst,
                       int n_edges) {
    int e = blockIdx.x * blockDim.x + threadIdx.x;
    if (e >= n_edges) return;
    int s = src[e];
    int d = dst[e];
    int pos = atomicAdd(&g_cursor[d], 1);
    g_csr_src[pos] = s;
    g_csr_nrm[pos] = g_dinv[s] * g_dinv[d];
}

// ---------------- GEMM: H = act(Xin) @ W --------------------------------------
// mode 0: in = Xin raw. mode 1: in = g_AGG with fused BN(scale,shift)+ReLU.
__global__ void __launch_bounds__(256)
k_gemm(const float* __restrict__ Xin, int mode,
       const float* __restrict__ W, int n_nodes) {
    __shared__ float sX[64][33];
    __shared__ float sW[32][128];
    __shared__ float sSc[FDIM];
    __shared__ float sSh[FDIM];

    const float* __restrict__ in = mode ? (const float*)g_AGG : Xin;

    if (mode && threadIdx.x < FDIM) {
        sSc[threadIdx.x] = g_scale[threadIdx.x];
        sSh[threadIdx.x] = g_shift[threadIdx.x];
    }
    if (mode) __syncthreads();

    const int row0 = blockIdx.x * 64;
    const int ct = threadIdx.x & 31;
    const int rt = threadIdx.x >> 5;

    float acc[8][4];
#pragma unroll
    for (int r = 0; r < 8; r++)
#pragma unroll
        for (int c = 0; c < 4; c++) acc[r][c] = 0.f;

    for (int kb = 0; kb < FDIM; kb += 32) {
        for (int l = threadIdx.x; l < 64 * 32; l += 256) {
            int r = l >> 5, c = l & 31;
            int gr = row0 + r;
            float v = 0.f;
            if (gr < n_nodes) {
                v = in[(size_t)gr * FDIM + kb + c];
                if (mode) v = fmaxf(v * sSc[kb + c] + sSh[kb + c], 0.f);
            }
            sX[r][c] = v;
        }
        for (int l = threadIdx.x; l < 32 * 128; l += 256) {
            int r = l >> 7, c = l & 127;
            sW[r][c] = W[(size_t)(kb + r) * FDIM + c];
        }
        __syncthreads();

#pragma unroll
        for (int k = 0; k < 32; k++) {
            float4 w4 = *reinterpret_cast<const float4*>(&sW[k][ct * 4]);
#pragma unroll
            for (int r = 0; r < 8; r++) {
                float xv = sX[r * 8 + rt][k];
                acc[r][0] += xv * w4.x;
                acc[r][1] += xv * w4.y;
                acc[r][2] += xv * w4.z;
                acc[r][3] += xv * w4.w;
            }
        }
        __syncthreads();
    }

#pragma unroll
    for (int r = 0; r < 8; r++) {
        int gr = row0 + r * 8 + rt;
        if (gr < n_nodes) {
            float4 h4 = make_float4(acc[r][0], acc[r][1], acc[r][2], acc[r][3]);
            *reinterpret_cast<float4*>(&g_H[(size_t)gr * FDIM + ct * 4]) = h4;
        }
    }
}

// ---------------- gather: AGG[d] = sum_in H[s]*nrm + H[d]*dinv^2 + b ----------
__global__ void k_zero_stats() {
    if (threadIdx.x < 2 * FDIM) g_stats[threadIdx.x] = 0.f;
}

__global__ void __launch_bounds__(256)
k_gather(const float* __restrict__ b, int n_nodes) {
    __shared__ float ssum[FDIM];
    __shared__ float ssq[FDIM];
    if (threadIdx.x < FDIM) { ssum[threadIdx.x] = 0.f; ssq[threadIdx.x] = 0.f; }
    __syncthreads();

    const int lane = threadIdx.x & 31;
    const int warp = threadIdx.x >> 5;
    const int nwarps = gridDim.x * 8;
    const float4 b4 = *reinterpret_cast<const float4*>(&b[lane * 4]);

    float4 sacc = make_float4(0.f, 0.f, 0.f, 0.f);
    float4 qacc = make_float4(0.f, 0.f, 0.f, 0.f);

    for (int d = blockIdx.x * 8 + warp; d < n_nodes; d += nwarps) {
        const int rs = g_rowptr[d];
        const int re = g_rowptr[d + 1];
        const float di = g_dinv[d];
        const float d2 = di * di;

        float4 h = reinterpret_cast<const float4*>(g_H)[(size_t)d * 32 + lane];
        float4 acc = make_float4(h.x * d2 + b4.x, h.y * d2 + b4.y,
                                 h.z * d2 + b4.z, h.w * d2 + b4.w);

        int e0 = rs;
        for (; e0 + 32 <= re; e0 += 32) {
            int   sl = g_csr_src[e0 + lane];
            float nl = g_csr_nrm[e0 + lane];
#pragma unroll
            for (int j = 0; j < 32; j++) {
                int   sj = __shfl_sync(0xffffffffu, sl, j);
                float nj = __shfl_sync(0xffffffffu, nl, j);
                float4 v = reinterpret_cast<const float4*>(g_H)[(size_t)sj * 32 + lane];
                acc.x += v.x * nj; acc.y += v.y * nj;
                acc.z += v.z * nj; acc.w += v.w * nj;
            }
        }
        if (e0 < re) {
            int cnt = re - e0;
            int   sl = (lane < cnt) ? g_csr_src[e0 + lane] : 0;
            float nl = (lane < cnt) ? g_csr_nrm[e0 + lane] : 0.f;
            for (int j = 0; j < cnt; j++) {
                int   sj = __shfl_sync(0xffffffffu, sl, j);
                float nj = __shfl_sync(0xffffffffu, nl, j);
                float4 v = reinterpret_cast<const float4*>(g_H)[(size_t)sj * 32 + lane];
                acc.x += v.x * nj; acc.y += v.y * nj;
                acc.z += v.z * nj; acc.w += v.w * nj;
            }
        }

        reinterpret_cast<float4*>(g_AGG)[(size_t)d * 32 + lane] = acc;
        sacc.x += acc.x; sacc.y += acc.y; sacc.z += acc.z; sacc.w += acc.w;
        qacc.x += acc.x * acc.x; qacc.y += acc.y * acc.y;
        qacc.z += acc.z * acc.z; qacc.w += acc.w * acc.w;
    }

    int c = lane * 4;
    atomicAdd(&ssum[c + 0], sacc.x); atomicAdd(&ssum[c + 1], sacc.y);
    atomicAdd(&ssum[c + 2], sacc.z); atomicAdd(&ssum[c + 3], sacc.w);
    atomicAdd(&ssq[c + 0], qacc.x);  atomicAdd(&ssq[c + 1], qacc.y);
    atomicAdd(&ssq[c + 2], qacc.z);  atomicAdd(&ssq[c + 3], qacc.w);
    __syncthreads();
    if (threadIdx.x < FDIM) {
        atomicAdd(&g_stats[threadIdx.x], ssum[threadIdx.x]);
        atomicAdd(&g_stats[FDIM + threadIdx.x], ssq[threadIdx.x]);
    }
}

// ---------------- BN finalize ---------------------------------------------------
__global__ void k_bnfin(const float* __restrict__ gma, const float* __restrict__ bta,
                        int n_nodes) {
    int c = threadIdx.x;  // 128 threads
    float inv_n = 1.0f / (float)n_nodes;
    float mu = g_stats[c] * inv_n;
    float var = g_stats[FDIM + c] * inv_n - mu * mu;
    float rstd = rsqrtf(var + BN_EPS);
    float sc = rstd * gma[c];
    g_scale[c] = sc;
    g_shift[c] = bta[c] - mu * sc;
}

// BN+ReLU materialize (only needed before pool)
__global__ void __launch_bounds__(256)
k_bnrelu(int n_nodes) {
    int i = blockIdx.x * blockDim.x + threadIdx.x;
    if (i >= n_nodes * 32) return;
    int c = (i & 31) * 4;
    float4 v = reinterpret_cast<const float4*>(g_AGG)[i];
    float4 sc = *reinterpret_cast<const float4*>(&g_scale[c]);
    float4 sh = *reinterpret_cast<const float4*>(&g_shift[c]);
    v.x = fmaxf(v.x * sc.x + sh.x, 0.f);
    v.y = fmaxf(v.y * sc.y + sh.y, 0.f);
    v.z = fmaxf(v.z * sc.z + sh.z, 0.f);
    v.w = fmaxf(v.w * sc.w + sh.w, 0.f);
    reinterpret_cast<float4*>(g_X)[i] = v;
}

// ---------------- global mean pool (warp per node) -----------------------------
__global__ void __launch_bounds__(256)
k_pool(const int* __restrict__ batch, int n_nodes) {
    int w = (blockIdx.x * blockDim.x + threadIdx.x) >> 5;
    int lane = threadIdx.x & 31;
    if (w >= n_nodes) return;
    int g = batch[w];
    float4 v = reinterpret_cast<const float4*>(g_X)[(size_t)w * 32 + lane];
    float* p = &g_pool[(size_t)g * FDIM + lane * 4];
    red_add_f32(p + 0, v.x);
    red_add_f32(p + 1, v.y);
    red_add_f32(p + 2, v.z);
    red_add_f32(p + 3, v.w);
    if (lane == 0) atomicAdd(&g_cnt[g], 1.0f);
}

// ---------------- final FC: out = (pool/cnt) @ fcW + fcb ----------------------
__global__ void __launch_bounds__(256)
k_fc(const float* __restrict__ fcW, const float* __restrict__ fcb,
     float* __restrict__ out, int n_graphs) {
    __shared__ float sW[FDIM * 64];
    for (int l = threadIdx.x; l < FDIM * 64; l += 256) sW[l] = fcW[l];
    __syncthreads();
    int g = blockIdx.x * 4 + (threadIdx.x >> 6);
    int c = threadIdx.x & 63;
    if (g >= n_graphs) return;
    float inv = 1.0f / fmaxf(g_cnt[g], 1.0f);
    float acc = 0.f;
#pragma unroll 16
    for (int k = 0; k < FDIM; k++) acc += g_pool[(size_t)g * FDIM + k] * sW[k * 64 + c];
    out[(size_t)g * 64 + c] = acc * inv + fcb[c];
}

// ---------------- launch ------------------------------------------------------
extern "C" void kernel_launch(void* const* d_in, const int* in_sizes, int n_in,
                              void* d_out, int out_size) {
    const float* x     = (const float*)d_in[0];
    const int*   ei    = (const int*)d_in[1];     // int32 (JAX x64 disabled)
    const int*   batch = (const int*)d_in[2];
    const float* W1 = (const float*)d_in[3];
    const float* b1 = (const float*)d_in[4];
    const float* g1 = (const float*)d_in[5];
    const float* be1 = (const float*)d_in[6];
    const float* W2 = (const float*)d_in[7];
    const float* b2 = (const float*)d_in[8];
    const float* g2 = (const float*)d_in[9];
    const float* be2 = (const float*)d_in[10];
    const float* W3 = (const float*)d_in[11];
    const float* b3 = (const float*)d_in[12];
    const float* g3 = (const float*)d_in[13];
    const float* be3 = (const float*)d_in[14];
    const float* fcW = (const float*)d_in[15];
    const float* fcb = (const float*)d_in[16];
    float* out = (float*)d_out;

    const int n_nodes  = in_sizes[0] / FDIM;
    const int n_edges  = in_sizes[1] / 2;
    const int n_graphs = out_size / 64;
    const int* src = ei;
    const int* dst = ei + n_edges;
    const int nblocks = (n_nodes + SCAN_B - 1) / SCAN_B;

    // ---- CSR build (once per call) ----
    {
        int work = n_graphs * FDIM;
        if (n_nodes > work) work = n_nodes;
        k_zero<<<(work + 255) / 256, 256>>>(n_nodes, n_graphs);
    }
    k_deg<<<(n_edges + 255) / 256, 256>>>(dst, n_edges);
    k_dinv<<<(n_nodes + 255) / 256, 256>>>(n_nodes);
    k_bsum<<<nblocks, SCAN_B>>>(n_nodes);
    k_bscan<<<1, MAX_BLK>>>(nblocks);
    k_scanfin<<<nblocks, SCAN_B>>>(n_nodes);
    k_fill<<<(n_edges + 255) / 256, 256>>>(src, dst, n_edges);

    const int gemm_grid   = (n_nodes + 63) / 64;
    const int gather_grid = 1184;   // 148 SMs * 8 blocks
    const int elem_grid   = (n_nodes * 32 + 255) / 256;

    const float* Ws[3]  = {W1, W2, W3};
    const float* bs[3]  = {b1, b2, b3};
    const float* gs[3]  = {g1, g2, g3};
    const float* bes[3] = {be1, be2, be3};

    for (int layer = 0; layer < 3; layer++) {
        // layer 0 reads x; layers 1,2 read g_AGG with fused BN+ReLU
        k_gemm<<<gemm_grid, 256>>>(layer == 0 ? x : nullptr, layer == 0 ? 0 : 1,
                                   Ws[layer], n_nodes);
        k_zero_stats<<<1, 256>>>();
        k_gather<<<gather_grid, 256>>>(bs[layer], n_nodes);
        k_bnfin<<<1, 128>>>(gs[layer], bes[layer], n_nodes);
    }

    // materialize BN+ReLU of layer 3 for pooling
    k_bnrelu<<<elem_grid, 256>>>(n_nodes);
    k_pool<<<(n_nodes * 32 + 255) / 256, 256>>>(batch, n_nodes);
    k_fc<<<(n_graphs + 3) / 4, 256>>>(fcW, fcb, out, n_graphs);
}

// round 7
// speedup vs baseline: 2.4759x; 1.0057x over previous
#include <cuda_runtime.h>
#include <cuda_bf16.h>

#define MAX_N 100000
#define MAX_E 1600000
#define MAX_G 4096
#define FDIM 128
#define BN_EPS 1e-5f
#define SCAN_B 1024
#define MAX_BLK 128   // ceil(MAX_N/1024) = 98 <= 128

typedef unsigned long long u64;

// ---------------- scratch (device globals; no allocation allowed) -------------
__device__ float g_H[(size_t)MAX_N * FDIM];     // GEMM output h
__device__ float g_AGG[(size_t)MAX_N * FDIM];   // aggregation buffer
__device__ float g_dinv[MAX_N];
__device__ int   g_deg[MAX_N];
__device__ int   g_rowptr[MAX_N + 1];
__device__ int   g_cursor[MAX_N];
__device__ int   g_bsum[MAX_BLK];
__device__ int   g_boff[MAX_BLK];
__device__ int   g_csr_src[MAX_E];
__device__ float g_csr_nrm[MAX_E];
__device__ float g_stats[2 * FDIM];             // sum[128], sumsq[128]
__device__ float g_scale[FDIM];
__device__ float g_shift[FDIM];
__device__ float g_pool[(size_t)MAX_G * FDIM];
__device__ float g_cnt[MAX_G];

// ---------------- helpers -----------------------------------------------------
__device__ __forceinline__ void red_add_f32(float* p, float v) {
    asm volatile("red.global.add.f32 [%0], %1;" :: "l"(p), "f"(v) : "memory");
}
__device__ __forceinline__ u64 pack2(float a, float b) {
    u64 r; asm("mov.b64 %0, {%1,%2};" : "=l"(r) : "f"(a), "f"(b)); return r;
}
__device__ __forceinline__ u64 fma2(u64 a, u64 b, u64 c) {
    u64 d; asm("fma.rn.f32x2 %0, %1, %2, %3;" : "=l"(d) : "l"(a), "l"(b), "l"(c));
    return d;
}
__device__ __forceinline__ float2 unpack2(u64 v) {
    float2 r; asm("mov.b64 {%0,%1}, %2;" : "=f"(r.x), "=f"(r.y) : "l"(v)); return r;
}

// ---------------- init: zero deg / pool / cnt ---------------------------------
__global__ void k_zero(int n_nodes, int n_graphs) {
    int i = blockIdx.x * blockDim.x + threadIdx.x;
    if (i < n_nodes) g_deg[i] = 0;
    if (i < n_graphs * FDIM) g_pool[i] = 0.f;
    if (i < n_graphs) g_cnt[i] = 0.f;
}

__global__ void k_deg(const int* __restrict__ dst, int n_edges) {
    int e = blockIdx.x * blockDim.x + threadIdx.x;
    if (e < n_edges) atomicAdd(&g_deg[dst[e]], 1);
}

__global__ void k_dinv(int n_nodes) {
    int i = blockIdx.x * blockDim.x + threadIdx.x;
    if (i < n_nodes) g_dinv[i] = rsqrtf((float)g_deg[i] + 1.0f);
}

// ---------------- parallel scan: phase 1 — per-block sums ---------------------
__global__ void __launch_bounds__(SCAN_B)
k_bsum(int n_nodes) {
    int i = blockIdx.x * SCAN_B + threadIdx.x;
    int v = (i < n_nodes) ? g_deg[i] : 0;
    for (int off = 16; off > 0; off >>= 1) v += __shfl_down_sync(0xffffffffu, v, off);
    __shared__ int ws[32];
    int lane = threadIdx.x & 31, w = threadIdx.x >> 5;
    if (lane == 0) ws[w] = v;
    __syncthreads();
    if (w == 0) {
        int s = ws[lane];
        for (int off = 16; off > 0; off >>= 1) s += __shfl_down_sync(0xffffffffu, s, off);
        if (lane == 0) g_bsum[blockIdx.x] = s;
    }
}

// ---------------- phase 2 — scan block sums (single small block) --------------
__global__ void k_bscan(int nblocks) {
    __shared__ int s[MAX_BLK];
    int tid = threadIdx.x;
    int v = (tid < nblocks) ? g_bsum[tid] : 0;
    s[tid] = v;
    __syncthreads();
#pragma unroll
    for (int off = 1; off < MAX_BLK; off <<= 1) {
        int t = (tid >= off) ? s[tid - off] : 0;
        __syncthreads();
        s[tid] += t;
        __syncthreads();
    }
    g_boff[tid] = (tid > 0) ? s[tid - 1] : 0;  // exclusive
}

// ---------------- phase 3 — per-block local scan + offset; fills cursor -------
__global__ void __launch_bounds__(SCAN_B)
k_scanfin(int n_nodes) {
    int i = blockIdx.x * SCAN_B + threadIdx.x;
    int v = (i < n_nodes) ? g_deg[i] : 0;
    int lane = threadIdx.x & 31, w = threadIdx.x >> 5;
    int x = v;
#pragma unroll
    for (int off = 1; off < 32; off <<= 1) {
        int t = __shfl_up_sync(0xffffffffu, x, off);
        if (lane >= off) x += t;
    }
    __shared__ int ws[32];
    if (lane == 31) ws[w] = x;
    __syncthreads();
    if (w == 0) {
        int s = ws[lane];
#pragma unroll
        for (int off = 1; off < 32; off <<= 1) {
            int t = __shfl_up_sync(0xffffffffu, s, off);
            if (lane >= off) s += t;
        }
        ws[lane] = s;
    }
    __syncthreads();
    int incl = x + ((w > 0) ? ws[w - 1] : 0) + g_boff[blockIdx.x];
    if (i < n_nodes) {
        g_rowptr[i + 1] = incl;
        g_cursor[i] = incl - v;
    }
    if (i == 0) g_rowptr[0] = 0;
}

__global__ void k_fill(const int* __restrict__ src, const int* __restrict__ dst,
                       int n_edges) {
    int e = blockIdx.x * blockDim.x + threadIdx.x;
    if (e >= n_edges) return;
    int s = src[e];
    int d = dst[e];
    int pos = atomicAdd(&g_cursor[d], 1);
    g_csr_src[pos] = s;
    g_csr_nrm[pos] = g_dinv[s] * g_dinv[d];
}

// ---------------- GEMM: H = act(Xin) @ W, f32x2 packed FMA --------------------
// mode 0: in = Xin raw. mode 1: in = g_AGG with fused BN(scale,shift)+ReLU.
__global__ void __launch_bounds__(256)
k_gemm(const float* __restrict__ Xin, int mode,
       const float* __restrict__ W, int n_nodes) {
    __shared__ float sX[64][33];
    __shared__ float sW[32][128];
    __shared__ float sSc[FDIM];
    __shared__ float sSh[FDIM];

    const float* __restrict__ in = mode ? (const float*)g_AGG : Xin;

    if (mode && threadIdx.x < FDIM) {
        sSc[threadIdx.x] = g_scale[threadIdx.x];
        sSh[threadIdx.x] = g_shift[threadIdx.x];
    }
    if (mode) __syncthreads();

    const int row0 = blockIdx.x * 64;
    const int ct = threadIdx.x & 31;
    const int rt = threadIdx.x >> 5;

    u64 acc2[8][2];
#pragma unroll
    for (int r = 0; r < 8; r++) { acc2[r][0] = 0ull; acc2[r][1] = 0ull; }

    for (int kb = 0; kb < FDIM; kb += 32) {
        for (int l = threadIdx.x; l < 64 * 32; l += 256) {
            int r = l >> 5, c = l & 31;
            int gr = row0 + r;
            float v = 0.f;
            if (gr < n_nodes) {
                v = in[(size_t)gr * FDIM + kb + c];
                if (mode) v = fmaxf(v * sSc[kb + c] + sSh[kb + c], 0.f);
            }
            sX[r][c] = v;
        }
        for (int l = threadIdx.x; l < 32 * 128; l += 256) {
            int r = l >> 7, c = l & 127;
            sW[r][c] = W[(size_t)(kb + r) * FDIM + c];
        }
        __syncthreads();

#pragma unroll
        for (int k = 0; k < 32; k++) {
            float4 w4 = *reinterpret_cast<const float4*>(&sW[k][ct * 4]);
            u64 w01 = pack2(w4.x, w4.y);
            u64 w23 = pack2(w4.z, w4.w);
#pragma unroll
            for (int r = 0; r < 8; r++) {
                float xv = sX[r * 8 + rt][k];
                u64 xp = pack2(xv, xv);
                acc2[r][0] = fma2(w01, xp, acc2[r][0]);
                acc2[r][1] = fma2(w23, xp, acc2[r][1]);
            }
        }
        __syncthreads();
    }

#pragma unroll
    for (int r = 0; r < 8; r++) {
        int gr = row0 + r * 8 + rt;
        if (gr < n_nodes) {
            float2 a = unpack2(acc2[r][0]);
            float2 b = unpack2(acc2[r][1]);
            float4 h4 = make_float4(a.x, a.y, b.x, b.y);
            *reinterpret_cast<float4*>(&g_H[(size_t)gr * FDIM + ct * 4]) = h4;
        }
    }
}

// ---------------- gather: AGG[d] = sum_in H[s]*nrm + H[d]*dinv^2 + b ----------
__global__ void k_zero_stats() {
    if (threadIdx.x < 2 * FDIM) g_stats[threadIdx.x] = 0.f;
}

__global__ void __launch_bounds__(256)
k_gather(const float* __restrict__ b, int n_nodes) {
    __shared__ float ssum[FDIM];
    __shared__ float ssq[FDIM];
    if (threadIdx.x < FDIM) { ssum[threadIdx.x] = 0.f; ssq[threadIdx.x] = 0.f; }
    __syncthreads();

    const int lane = threadIdx.x & 31;
    const int warp = threadIdx.x >> 5;
    const int nwarps = gridDim.x * 8;
    const float4 b4 = *reinterpret_cast<const float4*>(&b[lane * 4]);

    float4 sacc = make_float4(0.f, 0.f, 0.f, 0.f);
    float4 qacc = make_float4(0.f, 0.f, 0.f, 0.f);

    for (int d = blockIdx.x * 8 + warp; d < n_nodes; d += nwarps) {
        const int rs = g_rowptr[d];
        const int re = g_rowptr[d + 1];
        const float di = g_dinv[d];
        const float d2 = di * di;

        float4 h = reinterpret_cast<const float4*>(g_H)[(size_t)d * 32 + lane];
        float4 acc = make_float4(h.x * d2 + b4.x, h.y * d2 + b4.y,
                                 h.z * d2 + b4.z, h.w * d2 + b4.w);

        int e0 = rs;
        for (; e0 + 32 <= re; e0 += 32) {
            int   sl = g_csr_src[e0 + lane];
            float nl = g_csr_nrm[e0 + lane];
#pragma unroll
            for (int j = 0; j < 32; j++) {
                int   sj = __shfl_sync(0xffffffffu, sl, j);
                float nj = __shfl_sync(0xffffffffu, nl, j);
                float4 v = reinterpret_cast<const float4*>(g_H)[(size_t)sj * 32 + lane];
                acc.x += v.x * nj; acc.y += v.y * nj;
                acc.z += v.z * nj; acc.w += v.w * nj;
            }
        }
        if (e0 < re) {
            int cnt = re - e0;  // 1..31
            int   sl = (lane < cnt) ? g_csr_src[e0 + lane] : 0;
            float nl = (lane < cnt) ? g_csr_nrm[e0 + lane] : 0.f;
            for (int j0 = 0; j0 < cnt; j0 += 8) {
#pragma unroll
                for (int jj = 0; jj < 8; jj++) {
                    int j = j0 + jj;
                    int   sj = __shfl_sync(0xffffffffu, sl, j & 31);
                    float nj = __shfl_sync(0xffffffffu, nl, j & 31);
                    if (j < cnt) {
                        float4 v = reinterpret_cast<const float4*>(g_H)[(size_t)sj * 32 + lane];
                        acc.x += v.x * nj; acc.y += v.y * nj;
                        acc.z += v.z * nj; acc.w += v.w * nj;
                    }
                }
            }
        }

        reinterpret_cast<float4*>(g_AGG)[(size_t)d * 32 + lane] = acc;
        sacc.x += acc.x; sacc.y += acc.y; sacc.z += acc.z; sacc.w += acc.w;
        qacc.x += acc.x * acc.x; qacc.y += acc.y * acc.y;
        qacc.z += acc.z * acc.z; qacc.w += acc.w * acc.w;
    }

    int c = lane * 4;
    atomicAdd(&ssum[c + 0], sacc.x); atomicAdd(&ssum[c + 1], sacc.y);
    atomicAdd(&ssum[c + 2], sacc.z); atomicAdd(&ssum[c + 3], sacc.w);
    atomicAdd(&ssq[c + 0], qacc.x);  atomicAdd(&ssq[c + 1], qacc.y);
    atomicAdd(&ssq[c + 2], qacc.z);  atomicAdd(&ssq[c + 3], qacc.w);
    __syncthreads();
    if (threadIdx.x < FDIM) {
        atomicAdd(&g_stats[threadIdx.x], ssum[threadIdx.x]);
        atomicAdd(&g_stats[FDIM + threadIdx.x], ssq[threadIdx.x]);
    }
}

// ---------------- BN finalize ---------------------------------------------------
__global__ void k_bnfin(const float* __restrict__ gma, const float* __restrict__ bta,
                        int n_nodes) {
    int c = threadIdx.x;  // 128 threads
    float inv_n = 1.0f / (float)n_nodes;
    float mu = g_stats[c] * inv_n;
    float var = g_stats[FDIM + c] * inv_n - mu * mu;
    float rstd = rsqrtf(var + BN_EPS);
    float sc = rstd * gma[c];
    g_scale[c] = sc;
    g_shift[c] = bta[c] - mu * sc;
}

// ---------------- pool with fused BN+ReLU (warp per node) ----------------------
__global__ void __launch_bounds__(256)
k_pool(const int* __restrict__ batch, int n_nodes) {
    int w = (blockIdx.x * blockDim.x + threadIdx.x) >> 5;
    int lane = threadIdx.x & 31;
    if (w >= n_nodes) return;
    int g = batch[w];
    int c = lane * 4;
    float4 v = reinterpret_cast<const float4*>(g_AGG)[(size_t)w * 32 + lane];
    float4 sc = *reinterpret_cast<const float4*>(&g_scale[c]);
    float4 sh = *reinterpret_cast<const float4*>(&g_shift[c]);
    v.x = fmaxf(v.x * sc.x + sh.x, 0.f);
    v.y = fmaxf(v.y * sc.y + sh.y, 0.f);
    v.z = fmaxf(v.z * sc.z + sh.z, 0.f);
    v.w = fmaxf(v.w * sc.w + sh.w, 0.f);
    float* p = &g_pool[(size_t)g * FDIM + c];
    red_add_f32(p + 0, v.x);
    red_add_f32(p + 1, v.y);
    red_add_f32(p + 2, v.z);
    red_add_f32(p + 3, v.w);
    if (lane == 0) atomicAdd(&g_cnt[g], 1.0f);
}

// ---------------- final FC: out = (pool/cnt) @ fcW + fcb ----------------------
__global__ void __launch_bounds__(256)
k_fc(const float* __restrict__ fcW, const float* __restrict__ fcb,
     float* __restrict__ out, int n_graphs) {
    __shared__ float sW[FDIM * 64];
    for (int l = threadIdx.x; l < FDIM * 64; l += 256) sW[l] = fcW[l];
    __syncthreads();
    int g = blockIdx.x * 4 + (threadIdx.x >> 6);
    int c = threadIdx.x & 63;
    if (g >= n_graphs) return;
    float inv = 1.0f / fmaxf(g_cnt[g], 1.0f);
    float acc = 0.f;
#pragma unroll 16
    for (int k = 0; k < FDIM; k++) acc += g_pool[(size_t)g * FDIM + k] * sW[k * 64 + c];
    out[(size_t)g * 64 + c] = acc * inv + fcb[c];
}

// ---------------- launch ------------------------------------------------------
extern "C" void kernel_launch(void* const* d_in, const int* in_sizes, int n_in,
                              void* d_out, int out_size) {
    const float* x     = (const float*)d_in[0];
    const int*   ei    = (const int*)d_in[1];
    const int*   batch = (const int*)d_in[2];
    const float* W1 = (const float*)d_in[3];
    const float* b1 = (const float*)d_in[4];
    const float* g1 = (const float*)d_in[5];
    const float* be1 = (const float*)d_in[6];
    const float* W2 = (const float*)d_in[7];
    const float* b2 = (const float*)d_in[8];
    const float* g2 = (const float*)d_in[9];
    const float* be2 = (const float*)d_in[10];
    const float* W3 = (const float*)d_in[11];
    const float* b3 = (const float*)d_in[12];
    const float* g3 = (const float*)d_in[13];
    const float* be3 = (const float*)d_in[14];
    const float* fcW = (const float*)d_in[15];
    const float* fcb = (const float*)d_in[16];
    float* out = (float*)d_out;

    const int n_nodes  = in_sizes[0] / FDIM;
    const int n_edges  = in_sizes[1] / 2;
    const int n_graphs = out_size / 64;
    const int* src = ei;
    const int* dst = ei + n_edges;
    const int nblocks = (n_nodes + SCAN_B - 1) / SCAN_B;

    // ---- CSR build (once per call) ----
    {
        int work = n_graphs * FDIM;
        if (n_nodes > work) work = n_nodes;
        k_zero<<<(work + 255) / 256, 256>>>(n_nodes, n_graphs);
    }
    k_deg<<<(n_edges + 255) / 256, 256>>>(dst, n_edges);
    k_dinv<<<(n_nodes + 255) / 256, 256>>>(n_nodes);
    k_bsum<<<nblocks, SCAN_B>>>(n_nodes);
    k_bscan<<<1, MAX_BLK>>>(nblocks);
    k_scanfin<<<nblocks, SCAN_B>>>(n_nodes);
    k_fill<<<(n_edges + 255) / 256, 256>>>(src, dst, n_edges);

    const int gemm_grid   = (n_nodes + 63) / 64;
    const int gather_grid = 1184;   // 148 SMs * 8 blocks

    const float* Ws[3]  = {W1, W2, W3};
    const float* bs[3]  = {b1, b2, b3};
    const float* gs[3]  = {g1, g2, g3};
    const float* bes[3] = {be1, be2, be3};

    for (int layer = 0; layer < 3; layer++) {
        k_gemm<<<gemm_grid, 256>>>(layer == 0 ? x : nullptr, layer == 0 ? 0 : 1,
                                   Ws[layer], n_nodes);
        k_zero_stats<<<1, 256>>>();
        k_gather<<<gather_grid, 256>>>(bs[layer], n_nodes);
        k_bnfin<<<1, 128>>>(gs[layer], bes[layer], n_nodes);
    }

    // pool applies layer-3 BN+ReLU inline
    k_pool<<<(n_nodes * 32 + 255) / 256, 256>>>(batch, n_nodes);
    k_fc<<<(n_graphs + 3) / 4, 256>>>(fcW, fcb, out, n_graphs);
}

// round 8
// speedup vs baseline: 2.5210x; 1.0182x over previous
#include <cuda_runtime.h>
#include <cuda_bf16.h>

#define MAX_N 100000
#define MAX_E 1600000
#define MAX_G 4096
#define FDIM 128
#define BN_EPS 1e-5f
#define SCAN_B 1024
#define MAX_BLK 128   // ceil(MAX_N/1024) = 98 <= 128

typedef unsigned long long u64;

// ---------------- scratch (device globals; no allocation allowed) -------------
__device__ float g_H[(size_t)MAX_N * FDIM];     // GEMM output h
__device__ float g_AGG[(size_t)MAX_N * FDIM];   // aggregation buffer
__device__ float g_dinv[MAX_N];
__device__ int   g_deg[MAX_N];
__device__ int   g_rowptr[MAX_N + 1];
__device__ int   g_cursor[MAX_N];
__device__ int   g_bsum[MAX_BLK];
__device__ int   g_boff[MAX_BLK];
__device__ int   g_csr_src[MAX_E];
__device__ float g_csr_nrm[MAX_E];
__device__ float g_stats[2 * FDIM];             // sum[128], sumsq[128]
__device__ float g_scale[FDIM];
__device__ float g_shift[FDIM];
__device__ float g_pool[(size_t)MAX_G * FDIM];
__device__ float g_cnt[MAX_G];

// ---------------- helpers -----------------------------------------------------
__device__ __forceinline__ void red_add_f32(float* p, float v) {
    asm volatile("red.global.add.f32 [%0], %1;" :: "l"(p), "f"(v) : "memory");
}
__device__ __forceinline__ u64 pack2(float a, float b) {
    u64 r; asm("mov.b64 %0, {%1,%2};" : "=l"(r) : "f"(a), "f"(b)); return r;
}
__device__ __forceinline__ u64 fma2(u64 a, u64 b, u64 c) {
    u64 d; asm("fma.rn.f32x2 %0, %1, %2, %3;" : "=l"(d) : "l"(a), "l"(b), "l"(c));
    return d;
}
__device__ __forceinline__ float2 unpack2(u64 v) {
    float2 r; asm("mov.b64 {%0,%1}, %2;" : "=f"(r.x), "=f"(r.y) : "l"(v)); return r;
}

// ---------------- init: zero deg / pool / cnt ---------------------------------
__global__ void k_zero(int n_nodes, int n_graphs) {
    int i = blockIdx.x * blockDim.x + threadIdx.x;
    if (i < n_nodes) g_deg[i] = 0;
    if (i < n_graphs * FDIM) g_pool[i] = 0.f;
    if (i < n_graphs) g_cnt[i] = 0.f;
}

__global__ void k_deg(const int* __restrict__ dst, int n_edges) {
    int e = blockIdx.x * blockDim.x + threadIdx.x;
    if (e < n_edges) atomicAdd(&g_deg[dst[e]], 1);
}

__global__ void k_dinv(int n_nodes) {
    int i = blockIdx.x * blockDim.x + threadIdx.x;
    if (i < n_nodes) g_dinv[i] = rsqrtf((float)g_deg[i] + 1.0f);
}

// ---------------- parallel scan: phase 1 — per-block sums ---------------------
__global__ void __launch_bounds__(SCAN_B)
k_bsum(int n_nodes) {
    int i = blockIdx.x * SCAN_B + threadIdx.x;
    int v = (i < n_nodes) ? g_deg[i] : 0;
    for (int off = 16; off > 0; off >>= 1) v += __shfl_down_sync(0xffffffffu, v, off);
    __shared__ int ws[32];
    int lane = threadIdx.x & 31, w = threadIdx.x >> 5;
    if (lane == 0) ws[w] = v;
    __syncthreads();
    if (w == 0) {
        int s = ws[lane];
        for (int off = 16; off > 0; off >>= 1) s += __shfl_down_sync(0xffffffffu, s, off);
        if (lane == 0) g_bsum[blockIdx.x] = s;
    }
}

// ---------------- phase 2 — scan block sums -----------------------------------
__global__ void k_bscan(int nblocks) {
    __shared__ int s[MAX_BLK];
    int tid = threadIdx.x;
    int v = (tid < nblocks) ? g_bsum[tid] : 0;
    s[tid] = v;
    __syncthreads();
#pragma unroll
    for (int off = 1; off < MAX_BLK; off <<= 1) {
        int t = (tid >= off) ? s[tid - off] : 0;
        __syncthreads();
        s[tid] += t;
        __syncthreads();
    }
    g_boff[tid] = (tid > 0) ? s[tid - 1] : 0;  // exclusive
}

// ---------------- phase 3 — per-block local scan + offset; fills cursor -------
__global__ void __launch_bounds__(SCAN_B)
k_scanfin(int n_nodes) {
    int i = blockIdx.x * SCAN_B + threadIdx.x;
    int v = (i < n_nodes) ? g_deg[i] : 0;
    int lane = threadIdx.x & 31, w = threadIdx.x >> 5;
    int x = v;
#pragma unroll
    for (int off = 1; off < 32; off <<= 1) {
        int t = __shfl_up_sync(0xffffffffu, x, off);
        if (lane >= off) x += t;
    }
    __shared__ int ws[32];
    if (lane == 31) ws[w] = x;
    __syncthreads();
    if (w == 0) {
        int s = ws[lane];
#pragma unroll
        for (int off = 1; off < 32; off <<= 1) {
            int t = __shfl_up_sync(0xffffffffu, s, off);
            if (lane >= off) s += t;
        }
        ws[lane] = s;
    }
    __syncthreads();
    int incl = x + ((w > 0) ? ws[w - 1] : 0) + g_boff[blockIdx.x];
    if (i < n_nodes) {
        g_rowptr[i + 1] = incl;
        g_cursor[i] = incl - v;
    }
    if (i == 0) g_rowptr[0] = 0;
}

__global__ void k_fill(const int* __restrict__ src, const int* __restrict__ dst,
                       int n_edges) {
    int e = blockIdx.x * blockDim.x + threadIdx.x;
    if (e >= n_edges) return;
    int s = src[e];
    int d = dst[e];
    int pos = atomicAdd(&g_cursor[d], 1);
    g_csr_src[pos] = s;
    g_csr_nrm[pos] = g_dinv[s] * g_dinv[d];
}

// ---------------- GEMM: H = act(Xin) @ W, LDS.128 a-frag + f32x2 --------------
// mode 0: in = Xin raw. mode 1: in = g_AGG with fused BN(scale,shift)+ReLU.
// thread (ct=lane, rt=warp): rows rt*8..rt*8+7 (contiguous), cols ct*4..ct*4+3
__global__ void __launch_bounds__(256)
k_gemm(const float* __restrict__ Xin, int mode,
       const float* __restrict__ W, int n_nodes) {
    __shared__ float sX[64][36];   // row-major; 36*4=144B stride (16B aligned)
    __shared__ float sW[32][128];
    __shared__ float sSc[FDIM];
    __shared__ float sSh[FDIM];

    const float* __restrict__ in = mode ? (const float*)g_AGG : Xin;

    if (mode && threadIdx.x < FDIM) {
        sSc[threadIdx.x] = g_scale[threadIdx.x];
        sSh[threadIdx.x] = g_shift[threadIdx.x];
    }
    if (mode) __syncthreads();

    const int row0 = blockIdx.x * 64;
    const int ct = threadIdx.x & 31;
    const int rt = threadIdx.x >> 5;

    u64 acc2[8][2];
#pragma unroll
    for (int r = 0; r < 8; r++) { acc2[r][0] = 0ull; acc2[r][1] = 0ull; }

    for (int kb = 0; kb < FDIM; kb += 32) {
        // load 64x32 slab of input (coalesced; conflict-free stores: bank = c)
        for (int l = threadIdx.x; l < 64 * 32; l += 256) {
            int r = l >> 5, c = l & 31;
            int gr = row0 + r;
            float v = 0.f;
            if (gr < n_nodes) {
                v = in[(size_t)gr * FDIM + kb + c];
                if (mode) v = fmaxf(v * sSc[kb + c] + sSh[kb + c], 0.f);
            }
            sX[r][c] = v;
        }
        for (int l = threadIdx.x; l < 32 * 128; l += 256) {
            int r = l >> 7, c = l & 127;
            sW[r][c] = W[(size_t)(kb + r) * FDIM + c];
        }
        __syncthreads();

#pragma unroll
        for (int k4 = 0; k4 < 32; k4 += 4) {
            // 8 LDS.128 broadcasts: this thread's 8 row-fragments for k4..k4+3
            float4 a4[8];
#pragma unroll
            for (int r = 0; r < 8; r++)
                a4[r] = *reinterpret_cast<const float4*>(&sX[rt * 8 + r][k4]);
#pragma unroll
            for (int kk = 0; kk < 4; kk++) {
                float4 w4 = *reinterpret_cast<const float4*>(&sW[k4 + kk][ct * 4]);
                u64 w01 = pack2(w4.x, w4.y);
                u64 w23 = pack2(w4.z, w4.w);
#pragma unroll
                for (int r = 0; r < 8; r++) {
                    float xv = (kk == 0) ? a4[r].x : (kk == 1) ? a4[r].y
                             : (kk == 2) ? a4[r].z : a4[r].w;
                    u64 xp = pack2(xv, xv);
                    acc2[r][0] = fma2(w01, xp, acc2[r][0]);
                    acc2[r][1] = fma2(w23, xp, acc2[r][1]);
                }
            }
        }
        __syncthreads();
    }

#pragma unroll
    for (int r = 0; r < 8; r++) {
        int gr = row0 + rt * 8 + r;
        if (gr < n_nodes) {
            float2 a = unpack2(acc2[r][0]);
            float2 b = unpack2(acc2[r][1]);
            float4 h4 = make_float4(a.x, a.y, b.x, b.y);
            *reinterpret_cast<float4*>(&g_H[(size_t)gr * FDIM + ct * 4]) = h4;
        }
    }
}

// ---------------- gather: AGG[d] = sum_in H[s]*nrm + H[d]*dinv^2 + b ----------
__global__ void k_zero_stats() {
    if (threadIdx.x < 2 * FDIM) g_stats[threadIdx.x] = 0.f;
}

__global__ void __launch_bounds__(256)
k_gather(const float* __restrict__ b, int n_nodes) {
    __shared__ float ssum[FDIM];
    __shared__ float ssq[FDIM];
    if (threadIdx.x < FDIM) { ssum[threadIdx.x] = 0.f; ssq[threadIdx.x] = 0.f; }
    __syncthreads();

    const int lane = threadIdx.x & 31;
    const int warp = threadIdx.x >> 5;
    const int nwarps = gridDim.x * 8;
    const float4 b4 = *reinterpret_cast<const float4*>(&b[lane * 4]);

    float4 sacc = make_float4(0.f, 0.f, 0.f, 0.f);
    float4 qacc = make_float4(0.f, 0.f, 0.f, 0.f);

    for (int d = blockIdx.x * 8 + warp; d < n_nodes; d += nwarps) {
        const int rs = g_rowptr[d];
        const int re = g_rowptr[d + 1];
        const float di = g_dinv[d];
        const float d2 = di * di;

        float4 h = reinterpret_cast<const float4*>(g_H)[(size_t)d * 32 + lane];
        float4 acc = make_float4(h.x * d2 + b4.x, h.y * d2 + b4.y,
                                 h.z * d2 + b4.z, h.w * d2 + b4.w);

        int e0 = rs;
        for (; e0 + 32 <= re; e0 += 32) {
            int   sl = g_csr_src[e0 + lane];
            float nl = g_csr_nrm[e0 + lane];
#pragma unroll
            for (int j = 0; j < 32; j++) {
                int   sj = __shfl_sync(0xffffffffu, sl, j);
                float nj = __shfl_sync(0xffffffffu, nl, j);
                float4 v = reinterpret_cast<const float4*>(g_H)[(size_t)sj * 32 + lane];
                acc.x += v.x * nj; acc.y += v.y * nj;
                acc.z += v.z * nj; acc.w += v.w * nj;
            }
        }
        if (e0 < re) {
            int cnt = re - e0;  // 1..31
            int   sl = (lane < cnt) ? g_csr_src[e0 + lane] : 0;
            float nl = (lane < cnt) ? g_csr_nrm[e0 + lane] : 0.f;
            for (int j0 = 0; j0 < cnt; j0 += 8) {
#pragma unroll
                for (int jj = 0; jj < 8; jj++) {
                    int j = j0 + jj;
                    int   sj = __shfl_sync(0xffffffffu, sl, j & 31);
                    float nj = __shfl_sync(0xffffffffu, nl, j & 31);
                    if (j < cnt) {
                        float4 v = reinterpret_cast<const float4*>(g_H)[(size_t)sj * 32 + lane];
                        acc.x += v.x * nj; acc.y += v.y * nj;
                        acc.z += v.z * nj; acc.w += v.w * nj;
                    }
                }
            }
        }

        reinterpret_cast<float4*>(g_AGG)[(size_t)d * 32 + lane] = acc;
        sacc.x += acc.x; sacc.y += acc.y; sacc.z += acc.z; sacc.w += acc.w;
        qacc.x += acc.x * acc.x; qacc.y += acc.y * acc.y;
        qacc.z += acc.z * acc.z; qacc.w += acc.w * acc.w;
    }

    int c = lane * 4;
    atomicAdd(&ssum[c + 0], sacc.x); atomicAdd(&ssum[c + 1], sacc.y);
    atomicAdd(&ssum[c + 2], sacc.z); atomicAdd(&ssum[c + 3], sacc.w);
    atomicAdd(&ssq[c + 0], qacc.x);  atomicAdd(&ssq[c + 1], qacc.y);
    atomicAdd(&ssq[c + 2], qacc.z);  atomicAdd(&ssq[c + 3], qacc.w);
    __syncthreads();
    if (threadIdx.x < FDIM) {
        atomicAdd(&g_stats[threadIdx.x], ssum[threadIdx.x]);
        atomicAdd(&g_stats[FDIM + threadIdx.x], ssq[threadIdx.x]);
    }
}

// ---------------- BN finalize ---------------------------------------------------
__global__ void k_bnfin(const float* __restrict__ gma, const float* __restrict__ bta,
                        int n_nodes) {
    int c = threadIdx.x;  // 128 threads
    float inv_n = 1.0f / (float)n_nodes;
    float mu = g_stats[c] * inv_n;
    float var = g_stats[FDIM + c] * inv_n - mu * mu;
    float rstd = rsqrtf(var + BN_EPS);
    float sc = rstd * gma[c];
    g_scale[c] = sc;
    g_shift[c] = bta[c] - mu * sc;
}

// ---------------- pool with fused BN+ReLU (warp per node) ----------------------
__global__ void __launch_bounds__(256)
k_pool(const int* __restrict__ batch, int n_nodes) {
    int w = (blockIdx.x * blockDim.x + threadIdx.x) >> 5;
    int lane = threadIdx.x & 31;
    if (w >= n_nodes) return;
    int g = batch[w];
    int c = lane * 4;
    float4 v = reinterpret_cast<const float4*>(g_AGG)[(size_t)w * 32 + lane];
    float4 sc = *reinterpret_cast<const float4*>(&g_scale[c]);
    float4 sh = *reinterpret_cast<const float4*>(&g_shift[c]);
    v.x = fmaxf(v.x * sc.x + sh.x, 0.f);
    v.y = fmaxf(v.y * sc.y + sh.y, 0.f);
    v.z = fmaxf(v.z * sc.z + sh.z, 0.f);
    v.w = fmaxf(v.w * sc.w + sh.w, 0.f);
    float* p = &g_pool[(size_t)g * FDIM + c];
    red_add_f32(p + 0, v.x);
    red_add_f32(p + 1, v.y);
    red_add_f32(p + 2, v.z);
    red_add_f32(p + 3, v.w);
    if (lane == 0) atomicAdd(&g_cnt[g], 1.0f);
}

// ---------------- final FC: out = (pool/cnt) @ fcW + fcb ----------------------
__global__ void __launch_bounds__(256)
k_fc(const float* __restrict__ fcW, const float* __restrict__ fcb,
     float* __restrict__ out, int n_graphs) {
    __shared__ float sW[FDIM * 64];
    for (int l = threadIdx.x; l < FDIM * 64; l += 256) sW[l] = fcW[l];
    __syncthreads();
    int g = blockIdx.x * 4 + (threadIdx.x >> 6);
    int c = threadIdx.x & 63;
    if (g >= n_graphs) return;
    float inv = 1.0f / fmaxf(g_cnt[g], 1.0f);
    float acc = 0.f;
#pragma unroll 16
    for (int k = 0; k < FDIM; k++) acc += g_pool[(size_t)g * FDIM + k] * sW[k * 64 + c];
    out[(size_t)g * 64 + c] = acc * inv + fcb[c];
}

// ---------------- launch ------------------------------------------------------
extern "C" void kernel_launch(void* const* d_in, const int* in_sizes, int n_in,
                              void* d_out, int out_size) {
    const float* x     = (const float*)d_in[0];
    const int*   ei    = (const int*)d_in[1];
    const int*   batch = (const int*)d_in[2];
    const float* W1 = (const float*)d_in[3];
    const float* b1 = (const float*)d_in[4];
    const float* g1 = (const float*)d_in[5];
    const float* be1 = (const float*)d_in[6];
    const float* W2 = (const float*)d_in[7];
    const float* b2 = (const float*)d_in[8];
    const float* g2 = (const float*)d_in[9];
    const float* be2 = (const float*)d_in[10];
    const float* W3 = (const float*)d_in[11];
    const float* b3 = (const float*)d_in[12];
    const float* g3 = (const float*)d_in[13];
    const float* be3 = (const float*)d_in[14];
    const float* fcW = (const float*)d_in[15];
    const float* fcb = (const float*)d_in[16];
    float* out = (float*)d_out;

    const int n_nodes  = in_sizes[0] / FDIM;
    const int n_edges  = in_sizes[1] / 2;
    const int n_graphs = out_size / 64;
    const int* src = ei;
    const int* dst = ei + n_edges;
    const int nblocks = (n_nodes + SCAN_B - 1) / SCAN_B;

    // ---- CSR build (once per call) ----
    {
        int work = n_graphs * FDIM;
        if (n_nodes > work) work = n_nodes;
        k_zero<<<(work + 255) / 256, 256>>>(n_nodes, n_graphs);
    }
    k_deg<<<(n_edges + 255) / 256, 256>>>(dst, n_edges);
    k_dinv<<<(n_nodes + 255) / 256, 256>>>(n_nodes);
    k_bsum<<<nblocks, SCAN_B>>>(n_nodes);
    k_bscan<<<1, MAX_BLK>>>(nblocks);
    k_scanfin<<<nblocks, SCAN_B>>>(n_nodes);
    k_fill<<<(n_edges + 255) / 256, 256>>>(src, dst, n_edges);

    const int gemm_grid   = (n_nodes + 63) / 64;
    const int gather_grid = 1184;   // 148 SMs * 8 blocks

    const float* Ws[3]  = {W1, W2, W3};
    const float* bs[3]  = {b1, b2, b3};
    const float* gs[3]  = {g1, g2, g3};
    const float* bes[3] = {be1, be2, be3};

    for (int layer = 0; layer < 3; layer++) {
        k_gemm<<<gemm_grid, 256>>>(layer == 0 ? x : nullptr, layer == 0 ? 0 : 1,
                                   Ws[layer], n_nodes);
        k_zero_stats<<<1, 256>>>();
        k_gather<<<gather_grid, 256>>>(bs[layer], n_nodes);
        k_bnfin<<<1, 128>>>(gs[layer], bes[layer], n_nodes);
    }

    // pool applies layer-3 BN+ReLU inline
    k_pool<<<(n_nodes * 32 + 255) / 256, 256>>>(batch, n_nodes);
    k_fc<<<(n_graphs + 3) / 4, 256>>>(fcW, fcb, out, n_graphs);
}

// round 10
// speedup vs baseline: 2.6010x; 1.0317x over previous
#include <cuda_runtime.h>
#include <cuda_bf16.h>
#include <mma.h>
#include <cstdint>

using namespace nvcuda;

#define MAX_N 100000
#define MAX_E 1600000
#define MAX_G 4096
#define FDIM 128
#define BN_EPS 1e-5f
#define SCAN_B 1024
#define MAX_BLK 128
#define LDS_T 136   // smem row stride in bf16 elements (272B, conflict-shifting)

// ---------------- scratch (device globals; no allocation allowed) -------------
__device__ float g_H[(size_t)(MAX_N + 128) * FDIM];   // padded for full-tile wmma stores
__device__ float g_AGG[(size_t)MAX_N * FDIM];
__device__ float g_dinv[MAX_N];
__device__ int   g_deg[MAX_N];
__device__ int   g_rowptr[MAX_N + 1];
__device__ int   g_cursor[MAX_N];
__device__ int   g_bsum[MAX_BLK];
__device__ int   g_boff[MAX_BLK];
__device__ int   g_csr_src[MAX_E];
__device__ float g_csr_nrm[MAX_E];
__device__ float g_stats[2 * FDIM];
__device__ float g_scale[FDIM];
__device__ float g_shift[FDIM];
__device__ float g_pool[(size_t)MAX_G * FDIM];
__device__ float g_cnt[MAX_G];
// W bf16 hi/lo images, plain row-major [k][n]
__device__ __align__(16) __nv_bfloat16 g_Bimg[3][2][FDIM * FDIM];

// ---------------- helpers -----------------------------------------------------
__device__ __forceinline__ void red_add_f32(float* p, float v) {
    asm volatile("red.global.add.f32 [%0], %1;" :: "l"(p), "f"(v) : "memory");
}

// ---------------- init ----------------------------------------------------------
__global__ void k_zero(int n_nodes, int n_graphs) {
    int i = blockIdx.x * blockDim.x + threadIdx.x;
    if (i < n_nodes) g_deg[i] = 0;
    if (i < n_graphs * FDIM) g_pool[i] = 0.f;
    if (i < n_graphs) g_cnt[i] = 0.f;
}
__global__ void k_deg(const int* __restrict__ dst, int n_edges) {
    int e = blockIdx.x * blockDim.x + threadIdx.x;
    if (e < n_edges) atomicAdd(&g_deg[dst[e]], 1);
}
__global__ void k_dinv(int n_nodes) {
    int i = blockIdx.x * blockDim.x + threadIdx.x;
    if (i < n_nodes) g_dinv[i] = rsqrtf((float)g_deg[i] + 1.0f);
}

// ---------------- W split: bf16 hi/lo, row-major [k][n] ------------------------
__global__ void k_wsplit(const float* __restrict__ W0, const float* __restrict__ W1,
                         const float* __restrict__ W2) {
    const float* W = (blockIdx.x == 0) ? W0 : (blockIdx.x == 1) ? W1 : W2;
    __nv_bfloat16* bh = g_Bimg[blockIdx.x][0];
    __nv_bfloat16* bl = g_Bimg[blockIdx.x][1];
    for (int idx = threadIdx.x; idx < FDIM * FDIM; idx += 256) {
        float w = W[idx];
        __nv_bfloat16 hi = __float2bfloat16(w);
        __nv_bfloat16 lo = __float2bfloat16(w - __bfloat162float(hi));
        bh[idx] = hi;
        bl[idx] = lo;
    }
}

// ---------------- parallel scan --------------------------------------------------
__global__ void __launch_bounds__(SCAN_B)
k_bsum(int n_nodes) {
    int i = blockIdx.x * SCAN_B + threadIdx.x;
    int v = (i < n_nodes) ? g_deg[i] : 0;
    for (int off = 16; off > 0; off >>= 1) v += __shfl_down_sync(0xffffffffu, v, off);
    __shared__ int ws[32];
    int lane = threadIdx.x & 31, w = threadIdx.x >> 5;
    if (lane == 0) ws[w] = v;
    __syncthreads();
    if (w == 0) {
        int s = ws[lane];
        for (int off = 16; off > 0; off >>= 1) s += __shfl_down_sync(0xffffffffu, s, off);
        if (lane == 0) g_bsum[blockIdx.x] = s;
    }
}
__global__ void k_bscan(int nblocks) {
    __shared__ int s[MAX_BLK];
    int tid = threadIdx.x;
    int v = (tid < nblocks) ? g_bsum[tid] : 0;
    s[tid] = v;
    __syncthreads();
#pragma unroll
    for (int off = 1; off < MAX_BLK; off <<= 1) {
        int t = (tid >= off) ? s[tid - off] : 0;
        __syncthreads();
        s[tid] += t;
        __syncthreads();
    }
    g_boff[tid] = (tid > 0) ? s[tid - 1] : 0;
}
__global__ void __launch_bounds__(SCAN_B)
k_scanfin(int n_nodes) {
    int i = blockIdx.x * SCAN_B + threadIdx.x;
    int v = (i < n_nodes) ? g_deg[i] : 0;
    int lane = threadIdx.x & 31, w = threadIdx.x >> 5;
    int x = v;
#pragma unroll
    for (int off = 1; off < 32; off <<= 1) {
        int t = __shfl_up_sync(0xffffffffu, x, off);
        if (lane >= off) x += t;
    }
    __shared__ int ws[32];
    if (lane == 31) ws[w] = x;
    __syncthreads();
    if (w == 0) {
        int s = ws[lane];
#pragma unroll
        for (int off = 1; off < 32; off <<= 1) {
            int t = __shfl_up_sync(0xffffffffu, s, off);
            if (lane >= off) s += t;
        }
        ws[lane] = s;
    }
    __syncthreads();
    int incl = x + ((w > 0) ? ws[w - 1] : 0) + g_boff[blockIdx.x];
    if (i < n_nodes) {
        g_rowptr[i + 1] = incl;
        g_cursor[i] = incl - v;
    }
    if (i == 0) g_rowptr[0] = 0;
}
__global__ void k_fill(const int* __restrict__ src, const int* __restrict__ dst,
                       int n_edges) {
    int e = blockIdx.x * blockDim.x + threadIdx.x;
    if (e >= n_edges) return;
    int s = src[e];
    int d = dst[e];
    int pos = atomicAdd(&g_cursor[d], 1);
    g_csr_src[pos] = s;
    g_csr_nrm[pos] = g_dinv[s] * g_dinv[d];
}

// ---------------- wmma GEMM: H = act(Xin) @ W (2-term bf16 split) --------------
// smem layout (bf16 elems): Ah[128*LDS_T], Al[...], Bh[...], Bl[...]
#define SMEM_WM (4 * 128 * LDS_T * 2)   // bytes = 139264

__global__ void __launch_bounds__(256)
k_gemm_wm(const float* __restrict__ Xin, int mode, int layer, int n_nodes) {
    extern __shared__ __align__(16) __nv_bfloat16 sm[];
    __nv_bfloat16* sAh = sm;
    __nv_bfloat16* sAl = sm + 128 * LDS_T;
    __nv_bfloat16* sBh = sm + 2 * 128 * LDS_T;
    __nv_bfloat16* sBl = sm + 3 * 128 * LDS_T;
    __shared__ float sSc[FDIM];
    __shared__ float sSh[FDIM];

    const int tid = threadIdx.x;
    const int wid = tid >> 5;
    const int row0 = blockIdx.x * 128;
    const float* __restrict__ in = mode ? (const float*)g_AGG : Xin;

    if (mode && tid < FDIM) { sSc[tid] = g_scale[tid]; sSh[tid] = g_shift[tid]; }

    // load B hi/lo (row-major [k][n]) into padded smem, 8 bf16 per uint4
    {
        const uint4* bh = reinterpret_cast<const uint4*>(g_Bimg[layer][0]);
        const uint4* bl = reinterpret_cast<const uint4*>(g_Bimg[layer][1]);
        for (int i = tid; i < FDIM * FDIM / 8; i += 256) {
            int r = i >> 4;            // 16 uint4 per 128-elem row
            int c8 = (i & 15) * 8;
            *reinterpret_cast<uint4*>(&sBh[r * LDS_T + c8]) = bh[i];
            *reinterpret_cast<uint4*>(&sBl[r * LDS_T + c8]) = bl[i];
        }
    }
    if (mode) __syncthreads();  // sSc/sSh ready before A conversion

    // load + (BN+ReLU) + split A tile
    for (int i4 = tid; i4 < 4096; i4 += 256) {
        int m = i4 >> 5;
        int q = i4 & 31;
        int k0 = q * 4;
        int gr = row0 + m;
        float4 v = make_float4(0.f, 0.f, 0.f, 0.f);
        if (gr < n_nodes) {
            v = reinterpret_cast<const float4*>(in)[(size_t)gr * 32 + q];
            if (mode) {
                v.x = fmaxf(v.x * sSc[k0 + 0] + sSh[k0 + 0], 0.f);
                v.y = fmaxf(v.y * sSc[k0 + 1] + sSh[k0 + 1], 0.f);
                v.z = fmaxf(v.z * sSc[k0 + 2] + sSh[k0 + 2], 0.f);
                v.w = fmaxf(v.w * sSc[k0 + 3] + sSh[k0 + 3], 0.f);
            }
        }
        float f[4] = {v.x, v.y, v.z, v.w};
        unsigned short hh[4], ll[4];
#pragma unroll
        for (int j = 0; j < 4; j++) {
            __nv_bfloat16 hi = __float2bfloat16(f[j]);
            __nv_bfloat16 lo = __float2bfloat16(f[j] - __bfloat162float(hi));
            hh[j] = *reinterpret_cast<unsigned short*>(&hi);
            ll[j] = *reinterpret_cast<unsigned short*>(&lo);
        }
        uint2 hp = make_uint2((uint32_t)hh[0] | ((uint32_t)hh[1] << 16),
                              (uint32_t)hh[2] | ((uint32_t)hh[3] << 16));
        uint2 lp = make_uint2((uint32_t)ll[0] | ((uint32_t)ll[1] << 16),
                              (uint32_t)ll[2] | ((uint32_t)ll[3] << 16));
        *reinterpret_cast<uint2*>(&sAh[m * LDS_T + k0]) = hp;
        *reinterpret_cast<uint2*>(&sAl[m * LDS_T + k0]) = lp;
    }
    __syncthreads();

    // warp wid: rows (wid&3)*32..+31, cols (wid>>2)*64..+63
    {
        const int rt = (wid & 3) * 32;
        const int ctb = (wid >> 2) * 64;

        wmma::fragment<wmma::accumulator, 16, 16, 16, float> acc[2][4];
#pragma unroll
        for (int r = 0; r < 2; r++)
#pragma unroll
            for (int c = 0; c < 4; c++) wmma::fill_fragment(acc[r][c], 0.f);

#pragma unroll
        for (int ks = 0; ks < 8; ks++) {
            const int k0 = ks * 16;
            wmma::fragment<wmma::matrix_a, 16, 16, 16, __nv_bfloat16, wmma::row_major> ah[2], al[2];
            wmma::load_matrix_sync(ah[0], &sAh[(rt + 0) * LDS_T + k0], LDS_T);
            wmma::load_matrix_sync(ah[1], &sAh[(rt + 16) * LDS_T + k0], LDS_T);
            wmma::load_matrix_sync(al[0], &sAl[(rt + 0) * LDS_T + k0], LDS_T);
            wmma::load_matrix_sync(al[1], &sAl[(rt + 16) * LDS_T + k0], LDS_T);
#pragma unroll
            for (int c = 0; c < 4; c++) {
                wmma::fragment<wmma::matrix_b, 16, 16, 16, __nv_bfloat16, wmma::row_major> bh, bl;
                wmma::load_matrix_sync(bh, &sBh[k0 * LDS_T + ctb + c * 16], LDS_T);
                wmma::load_matrix_sync(bl, &sBl[k0 * LDS_T + ctb + c * 16], LDS_T);
#pragma unroll
                for (int r = 0; r < 2; r++) {
                    wmma::mma_sync(acc[r][c], ah[r], bh, acc[r][c]);
                    wmma::mma_sync(acc[r][c], al[r], bh, acc[r][c]);
                    wmma::mma_sync(acc[r][c], ah[r], bl, acc[r][c]);
                }
            }
        }

#pragma unroll
        for (int r = 0; r < 2; r++)
#pragma unroll
            for (int c = 0; c < 4; c++)
                wmma::store_matrix_sync(&g_H[(size_t)(row0 + rt + r * 16) * FDIM + ctb + c * 16],
                                        acc[r][c], FDIM, wmma::mem_row_major);
    }
}

// ---------------- gather: AGG[d] = sum_in H[s]*nrm + H[d]*dinv^2 + b ----------
__global__ void k_zero_stats() {
    if (threadIdx.x < 2 * FDIM) g_stats[threadIdx.x] = 0.f;
}

__global__ void __launch_bounds__(256)
k_gather(const float* __restrict__ b, int n_nodes) {
    __shared__ float ssum[FDIM];
    __shared__ float ssq[FDIM];
    if (threadIdx.x < FDIM) { ssum[threadIdx.x] = 0.f; ssq[threadIdx.x] = 0.f; }
    __syncthreads();

    const int lane = threadIdx.x & 31;
    const int warp = threadIdx.x >> 5;
    const int nwarps = gridDim.x * 8;
    const float4 b4 = *reinterpret_cast<const float4*>(&b[lane * 4]);

    float4 sacc = make_float4(0.f, 0.f, 0.f, 0.f);
    float4 qacc = make_float4(0.f, 0.f, 0.f, 0.f);

    for (int d = blockIdx.x * 8 + warp; d < n_nodes; d += nwarps) {
        const int rs = g_rowptr[d];
        const int re = g_rowptr[d + 1];
        const float di = g_dinv[d];
        const float d2 = di * di;

        float4 h = reinterpret_cast<const float4*>(g_H)[(size_t)d * 32 + lane];
        float4 acc = make_float4(h.x * d2 + b4.x, h.y * d2 + b4.y,
                                 h.z * d2 + b4.z, h.w * d2 + b4.w);

        int e0 = rs;
        for (; e0 + 32 <= re; e0 += 32) {
            int   sl = g_csr_src[e0 + lane];
            float nl = g_csr_nrm[e0 + lane];
#pragma unroll
            for (int j = 0; j < 32; j++) {
                int   sj = __shfl_sync(0xffffffffu, sl, j);
                float nj = __shfl_sync(0xffffffffu, nl, j);
                float4 v = reinterpret_cast<const float4*>(g_H)[(size_t)sj * 32 + lane];
                acc.x += v.x * nj; acc.y += v.y * nj;
                acc.z += v.z * nj; acc.w += v.w * nj;
            }
        }
        if (e0 < re) {
            int cnt = re - e0;
            int   sl = (lane < cnt) ? g_csr_src[e0 + lane] : 0;
            float nl = (lane < cnt) ? g_csr_nrm[e0 + lane] : 0.f;
            for (int j0 = 0; j0 < cnt; j0 += 8) {
#pragma unroll
                for (int jj = 0; jj < 8; jj++) {
                    int j = j0 + jj;
                    int   sj = __shfl_sync(0xffffffffu, sl, j & 31);
                    float nj = __shfl_sync(0xffffffffu, nl, j & 31);
                    if (j < cnt) {
                        float4 v = reinterpret_cast<const float4*>(g_H)[(size_t)sj * 32 + lane];
                        acc.x += v.x * nj; acc.y += v.y * nj;
                        acc.z += v.z * nj; acc.w += v.w * nj;
                    }
                }
            }
        }

        reinterpret_cast<float4*>(g_AGG)[(size_t)d * 32 + lane] = acc;
        sacc.x += acc.x; sacc.y += acc.y; sacc.z += acc.z; sacc.w += acc.w;
        qacc.x += acc.x * acc.x; qacc.y += acc.y * acc.y;
        qacc.z += acc.z * acc.z; qacc.w += acc.w * acc.w;
    }

    int c = lane * 4;
    atomicAdd(&ssum[c + 0], sacc.x); atomicAdd(&ssum[c + 1], sacc.y);
    atomicAdd(&ssum[c + 2], sacc.z); atomicAdd(&ssum[c + 3], sacc.w);
    atomicAdd(&ssq[c + 0], qacc.x);  atomicAdd(&ssq[c + 1], qacc.y);
    atomicAdd(&ssq[c + 2], qacc.z);  atomicAdd(&ssq[c + 3], qacc.w);
    __syncthreads();
    if (threadIdx.x < FDIM) {
        atomicAdd(&g_stats[threadIdx.x], ssum[threadIdx.x]);
        atomicAdd(&g_stats[FDIM + threadIdx.x], ssq[threadIdx.x]);
    }
}

// ---------------- BN finalize ----------------------------------------------------
__global__ void k_bnfin(const float* __restrict__ gma, const float* __restrict__ bta,
                        int n_nodes) {
    int c = threadIdx.x;
    float inv_n = 1.0f / (float)n_nodes;
    float mu = g_stats[c] * inv_n;
    float var = g_stats[FDIM + c] * inv_n - mu * mu;
    float rstd = rsqrtf(var + BN_EPS);
    float sc = rstd * gma[c];
    g_scale[c] = sc;
    g_shift[c] = bta[c] - mu * sc;
}

// ---------------- pool with fused BN+ReLU (warp per node) ----------------------
__global__ void __launch_bounds__(256)
k_pool(const int* __restrict__ batch, int n_nodes) {
    int w = (blockIdx.x * blockDim.x + threadIdx.x) >> 5;
    int lane = threadIdx.x & 31;
    if (w >= n_nodes) return;
    int g = batch[w];
    int c = lane * 4;
    float4 v = reinterpret_cast<const float4*>(g_AGG)[(size_t)w * 32 + lane];
    float4 sc = *reinterpret_cast<const float4*>(&g_scale[c]);
    float4 sh = *reinterpret_cast<const float4*>(&g_shift[c]);
    v.x = fmaxf(v.x * sc.x + sh.x, 0.f);
    v.y = fmaxf(v.y * sc.y + sh.y, 0.f);
    v.z = fmaxf(v.z * sc.z + sh.z, 0.f);
    v.w = fmaxf(v.w * sc.w + sh.w, 0.f);
    float* p = &g_pool[(size_t)g * FDIM + c];
    red_add_f32(p + 0, v.x);
    red_add_f32(p + 1, v.y);
    red_add_f32(p + 2, v.z);
    red_add_f32(p + 3, v.w);
    if (lane == 0) atomicAdd(&g_cnt[g], 1.0f);
}

// ---------------- final FC ------------------------------------------------------
__global__ void __launch_bounds__(256)
k_fc(const float* __restrict__ fcW, const float* __restrict__ fcb,
     float* __restrict__ out, int n_graphs) {
    __shared__ float sW[FDIM * 64];
    for (int l = threadIdx.x; l < FDIM * 64; l += 256) sW[l] = fcW[l];
    __syncthreads();
    int g = blockIdx.x * 4 + (threadIdx.x >> 6);
    int c = threadIdx.x & 63;
    if (g >= n_graphs) return;
    float inv = 1.0f / fmaxf(g_cnt[g], 1.0f);
    float acc = 0.f;
#pragma unroll 16
    for (int k = 0; k < FDIM; k++) acc += g_pool[(size_t)g * FDIM + k] * sW[k * 64 + c];
    out[(size_t)g * 64 + c] = acc * inv + fcb[c];
}

// ---------------- launch ---------------------------------------------------------
extern "C" void kernel_launch(void* const* d_in, const int* in_sizes, int n_in,
                              void* d_out, int out_size) {
    const float* x     = (const float*)d_in[0];
    const int*   ei    = (const int*)d_in[1];
    const int*   batch = (const int*)d_in[2];
    const float* W1 = (const float*)d_in[3];
    const float* b1 = (const float*)d_in[4];
    const float* g1 = (const float*)d_in[5];
    const float* be1 = (const float*)d_in[6];
    const float* W2 = (const float*)d_in[7];
    const float* b2 = (const float*)d_in[8];
    const float* g2 = (const float*)d_in[9];
    const float* be2 = (const float*)d_in[10];
    const float* W3 = (const float*)d_in[11];
    const float* b3 = (const float*)d_in[12];
    const float* g3 = (const float*)d_in[13];
    const float* be3 = (const float*)d_in[14];
    const float* fcW = (const float*)d_in[15];
    const float* fcb = (const float*)d_in[16];
    float* out = (float*)d_out;

    const int n_nodes  = in_sizes[0] / FDIM;
    const int n_edges  = in_sizes[1] / 2;
    const int n_graphs = out_size / 64;
    const int* src = ei;
    const int* dst = ei + n_edges;
    const int nblocks = (n_nodes + SCAN_B - 1) / SCAN_B;

    static int smem_set = 0;
    if (!smem_set) {
        cudaFuncSetAttribute(k_gemm_wm, cudaFuncAttributeMaxDynamicSharedMemorySize,
                             SMEM_WM);
        smem_set = 1;
    }

    // ---- CSR build + W split (once per call) ----
    {
        int work = n_graphs * FDIM;
        if (n_nodes > work) work = n_nodes;
        k_zero<<<(work + 255) / 256, 256>>>(n_nodes, n_graphs);
    }
    k_wsplit<<<3, 256>>>(W1, W2, W3);
    k_deg<<<(n_edges + 255) / 256, 256>>>(dst, n_edges);
    k_dinv<<<(n_nodes + 255) / 256, 256>>>(n_nodes);
    k_bsum<<<nblocks, SCAN_B>>>(n_nodes);
    k_bscan<<<1, MAX_BLK>>>(nblocks);
    k_scanfin<<<nblocks, SCAN_B>>>(n_nodes);
    k_fill<<<(n_edges + 255) / 256, 256>>>(src, dst, n_edges);

    const int gemm_grid   = (n_nodes + 127) / 128;
    const int gather_grid = 1184;

    const float* bs[3]  = {b1, b2, b3};
    const float* gs[3]  = {g1, g2, g3};
    const float* bes[3] = {be1, be2, be3};

    for (int layer = 0; layer < 3; layer++) {
        k_gemm_wm<<<gemm_grid, 256, SMEM_WM>>>(layer == 0 ? x : nullptr,
                                               layer == 0 ? 0 : 1, layer, n_nodes);
        k_zero_stats<<<1, 256>>>();
        k_gather<<<gather_grid, 256>>>(bs[layer], n_nodes);
        k_bnfin<<<1, 128>>>(gs[layer], bes[layer], n_nodes);
    }

    k_pool<<<(n_nodes * 32 + 255) / 256, 256>>>(batch, n_nodes);
    k_fc<<<(n_graphs + 3) / 4, 256>>>(fcW, fcb, out, n_graphs);
}

// round 12
// speedup vs baseline: 2.9376x; 1.1294x over previous
#include <cuda_runtime.h>
#include <cuda_bf16.h>
#include <cuda_fp16.h>
#include <mma.h>
#include <cstdint>

using namespace nvcuda;

#define MAX_N 100000
#define MAX_E 1600000
#define MAX_G 4096
#define FDIM 128
#define BN_EPS 1e-5f
#define SCAN_B 1024
#define MAX_BLK 128
#define LDS_T 136   // smem row stride in bf16 elements

// ---------------- scratch (device globals; no allocation allowed) -------------
__device__ __half g_Hh[(size_t)(MAX_N + 128) * FDIM];  // fp16 H (padded tiles)
__device__ float g_AGG[(size_t)MAX_N * FDIM];
__device__ float g_dinv[MAX_N];
__device__ int   g_deg[MAX_N];
__device__ int   g_rowptr[MAX_N + 1];
__device__ int   g_cursor[MAX_N];
__device__ int   g_bsum[MAX_BLK];
__device__ int   g_boff[MAX_BLK];
__device__ int   g_csr_src[MAX_E];
__device__ float g_csr_nrm[MAX_E];
__device__ float g_stats[2 * FDIM];
__device__ float g_scale[FDIM];
__device__ float g_shift[FDIM];
__device__ float g_pool[(size_t)MAX_G * FDIM];
__device__ float g_cnt[MAX_G];
// W bf16 hi/lo images, plain row-major [k][n]
__device__ __align__(16) __nv_bfloat16 g_Bimg[3][2][FDIM * FDIM];

// ---------------- helpers -----------------------------------------------------
__device__ __forceinline__ void red_add_f32(float* p, float v) {
    asm volatile("red.global.add.f32 [%0], %1;" :: "l"(p), "f"(v) : "memory");
}

// ---------------- init ----------------------------------------------------------
__global__ void k_zero(int n_nodes, int n_graphs) {
    int i = blockIdx.x * blockDim.x + threadIdx.x;
    if (i < n_nodes) g_deg[i] = 0;
    if (i < n_graphs * FDIM) g_pool[i] = 0.f;
    if (i < n_graphs) g_cnt[i] = 0.f;
}
__global__ void k_deg(const int* __restrict__ dst, int n_edges) {
    int e = blockIdx.x * blockDim.x + threadIdx.x;
    if (e < n_edges) atomicAdd(&g_deg[dst[e]], 1);
}
__global__ void k_dinv(int n_nodes) {
    int i = blockIdx.x * blockDim.x + threadIdx.x;
    if (i < n_nodes) g_dinv[i] = rsqrtf((float)g_deg[i] + 1.0f);
}

// ---------------- W split: bf16 hi/lo, row-major [k][n] ------------------------
__global__ void k_wsplit(const float* __restrict__ W0, const float* __restrict__ W1,
                         const float* __restrict__ W2) {
    const float* W = (blockIdx.x == 0) ? W0 : (blockIdx.x == 1) ? W1 : W2;
    __nv_bfloat16* bh = g_Bimg[blockIdx.x][0];
    __nv_bfloat16* bl = g_Bimg[blockIdx.x][1];
    for (int idx = threadIdx.x; idx < FDIM * FDIM; idx += 256) {
        float w = W[idx];
        __nv_bfloat16 hi = __float2bfloat16(w);
        __nv_bfloat16 lo = __float2bfloat16(w - __bfloat162float(hi));
        bh[idx] = hi;
        bl[idx] = lo;
    }
}

// ---------------- parallel scan --------------------------------------------------
__global__ void __launch_bounds__(SCAN_B)
k_bsum(int n_nodes) {
    int i = blockIdx.x * SCAN_B + threadIdx.x;
    int v = (i < n_nodes) ? g_deg[i] : 0;
    for (int off = 16; off > 0; off >>= 1) v += __shfl_down_sync(0xffffffffu, v, off);
    __shared__ int ws[32];
    int lane = threadIdx.x & 31, w = threadIdx.x >> 5;
    if (lane == 0) ws[w] = v;
    __syncthreads();
    if (w == 0) {
        int s = ws[lane];
        for (int off = 16; off > 0; off >>= 1) s += __shfl_down_sync(0xffffffffu, s, off);
        if (lane == 0) g_bsum[blockIdx.x] = s;
    }
}
__global__ void k_bscan(int nblocks) {
    __shared__ int s[MAX_BLK];
    int tid = threadIdx.x;
    int v = (tid < nblocks) ? g_bsum[tid] : 0;
    s[tid] = v;
    __syncthreads();
#pragma unroll
    for (int off = 1; off < MAX_BLK; off <<= 1) {
        int t = (tid >= off) ? s[tid - off] : 0;
        __syncthreads();
        s[tid] += t;
        __syncthreads();
    }
    g_boff[tid] = (tid > 0) ? s[tid - 1] : 0;
}
__global__ void __launch_bounds__(SCAN_B)
k_scanfin(int n_nodes) {
    int i = blockIdx.x * SCAN_B + threadIdx.x;
    int v = (i < n_nodes) ? g_deg[i] : 0;
    int lane = threadIdx.x & 31, w = threadIdx.x >> 5;
    int x = v;
#pragma unroll
    for (int off = 1; off < 32; off <<= 1) {
        int t = __shfl_up_sync(0xffffffffu, x, off);
        if (lane >= off) x += t;
    }
    __shared__ int ws[32];
    if (lane == 31) ws[w] = x;
    __syncthreads();
    if (w == 0) {
        int s = ws[lane];
#pragma unroll
        for (int off = 1; off < 32; off <<= 1) {
            int t = __shfl_up_sync(0xffffffffu, s, off);
            if (lane >= off) s += t;
        }
        ws[lane] = s;
    }
    __syncthreads();
    int incl = x + ((w > 0) ? ws[w - 1] : 0) + g_boff[blockIdx.x];
    if (i < n_nodes) {
        g_rowptr[i + 1] = incl;
        g_cursor[i] = incl - v;
    }
    if (i == 0) g_rowptr[0] = 0;
}
__global__ void k_fill(const int* __restrict__ src, const int* __restrict__ dst,
                       int n_edges) {
    int e = blockIdx.x * blockDim.x + threadIdx.x;
    if (e >= n_edges) return;
    int s = src[e];
    int d = dst[e];
    int pos = atomicAdd(&g_cursor[d], 1);
    g_csr_src[pos] = s;
    g_csr_nrm[pos] = g_dinv[s] * g_dinv[d];
}

// ---------------- wmma GEMM: Hh = act(Xin) @ W (2-term bf16 split, fp16 out) ---
#define SMEM_WM (4 * 128 * LDS_T * 2)   // bytes = 139264

__global__ void __launch_bounds__(256)
k_gemm_wm(const float* __restrict__ Xin, int mode, int layer, int n_nodes) {
    extern __shared__ __align__(16) __nv_bfloat16 sm[];
    __nv_bfloat16* sAh = sm;
    __nv_bfloat16* sAl = sm + 128 * LDS_T;
    __nv_bfloat16* sBh = sm + 2 * 128 * LDS_T;
    __nv_bfloat16* sBl = sm + 3 * 128 * LDS_T;
    __shared__ float sSc[FDIM];
    __shared__ float sSh[FDIM];

    const int tid = threadIdx.x;
    const int wid = tid >> 5;
    const int lane = tid & 31;
    const int row0 = blockIdx.x * 128;
    const float* __restrict__ in = mode ? (const float*)g_AGG : Xin;

    if (mode && tid < FDIM) { sSc[tid] = g_scale[tid]; sSh[tid] = g_shift[tid]; }

    // load B hi/lo (row-major [k][n]) into padded smem
    {
        const uint4* bh = reinterpret_cast<const uint4*>(g_Bimg[layer][0]);
        const uint4* bl = reinterpret_cast<const uint4*>(g_Bimg[layer][1]);
        for (int i = tid; i < FDIM * FDIM / 8; i += 256) {
            int r = i >> 4;
            int c8 = (i & 15) * 8;
            *reinterpret_cast<uint4*>(&sBh[r * LDS_T + c8]) = bh[i];
            *reinterpret_cast<uint4*>(&sBl[r * LDS_T + c8]) = bl[i];
        }
    }
    if (mode) __syncthreads();

    // load + (BN+ReLU) + split A tile
    for (int i4 = tid; i4 < 4096; i4 += 256) {
        int m = i4 >> 5;
        int q = i4 & 31;
        int k0 = q * 4;
        int gr = row0 + m;
        float4 v = make_float4(0.f, 0.f, 0.f, 0.f);
        if (gr < n_nodes) {
            v = reinterpret_cast<const float4*>(in)[(size_t)gr * 32 + q];
            if (mode) {
                v.x = fmaxf(v.x * sSc[k0 + 0] + sSh[k0 + 0], 0.f);
                v.y = fmaxf(v.y * sSc[k0 + 1] + sSh[k0 + 1], 0.f);
                v.z = fmaxf(v.z * sSc[k0 + 2] + sSh[k0 + 2], 0.f);
                v.w = fmaxf(v.w * sSc[k0 + 3] + sSh[k0 + 3], 0.f);
            }
        }
        float f[4] = {v.x, v.y, v.z, v.w};
        unsigned short hh[4], ll[4];
#pragma unroll
        for (int j = 0; j < 4; j++) {
            __nv_bfloat16 hi = __float2bfloat16(f[j]);
            __nv_bfloat16 lo = __float2bfloat16(f[j] - __bfloat162float(hi));
            hh[j] = *reinterpret_cast<unsigned short*>(&hi);
            ll[j] = *reinterpret_cast<unsigned short*>(&lo);
        }
        uint2 hp = make_uint2((uint32_t)hh[0] | ((uint32_t)hh[1] << 16),
                              (uint32_t)hh[2] | ((uint32_t)hh[3] << 16));
        uint2 lp = make_uint2((uint32_t)ll[0] | ((uint32_t)ll[1] << 16),
                              (uint32_t)ll[2] | ((uint32_t)ll[3] << 16));
        *reinterpret_cast<uint2*>(&sAh[m * LDS_T + k0]) = hp;
        *reinterpret_cast<uint2*>(&sAl[m * LDS_T + k0]) = lp;
    }
    __syncthreads();

    const int rt = (wid & 3) * 32;
    const int ctb = (wid >> 2) * 64;

    wmma::fragment<wmma::accumulator, 16, 16, 16, float> acc[2][4];
#pragma unroll
    for (int r = 0; r < 2; r++)
#pragma unroll
        for (int c = 0; c < 4; c++) wmma::fill_fragment(acc[r][c], 0.f);

#pragma unroll
    for (int ks = 0; ks < 8; ks++) {
        const int k0 = ks * 16;
        wmma::fragment<wmma::matrix_a, 16, 16, 16, __nv_bfloat16, wmma::row_major> ah[2], al[2];
        wmma::load_matrix_sync(ah[0], &sAh[(rt + 0) * LDS_T + k0], LDS_T);
        wmma::load_matrix_sync(ah[1], &sAh[(rt + 16) * LDS_T + k0], LDS_T);
        wmma::load_matrix_sync(al[0], &sAl[(rt + 0) * LDS_T + k0], LDS_T);
        wmma::load_matrix_sync(al[1], &sAl[(rt + 16) * LDS_T + k0], LDS_T);
#pragma unroll
        for (int c = 0; c < 4; c++) {
            wmma::fragment<wmma::matrix_b, 16, 16, 16, __nv_bfloat16, wmma::row_major> bh, bl;
            wmma::load_matrix_sync(bh, &sBh[k0 * LDS_T + ctb + c * 16], LDS_T);
            wmma::load_matrix_sync(bl, &sBl[k0 * LDS_T + ctb + c * 16], LDS_T);
#pragma unroll
            for (int r = 0; r < 2; r++) {
                wmma::mma_sync(acc[r][c], ah[r], bh, acc[r][c]);
                wmma::mma_sync(acc[r][c], al[r], bh, acc[r][c]);
                wmma::mma_sync(acc[r][c], ah[r], bl, acc[r][c]);
            }
        }
    }

    // epilogue: stage fp32 accs through smem, emit fp16
    __syncthreads();   // all warps done reading A/B smem
    float* stage = reinterpret_cast<float*>(sm) + wid * 2048;   // 32x64 floats/warp
#pragma unroll
    for (int r = 0; r < 2; r++)
#pragma unroll
        for (int c = 0; c < 4; c++)
            wmma::store_matrix_sync(&stage[r * 16 * 64 + c * 16], acc[r][c], 64,
                                    wmma::mem_row_major);
    __syncwarp();
#pragma unroll
    for (int it = 0; it < 16; it++) {
        int r  = it * 2 + (lane >> 4);
        int c4 = (lane & 15) * 4;
        float4 v = *reinterpret_cast<const float4*>(&stage[r * 64 + c4]);
        __half2 h0 = __floats2half2_rn(v.x, v.y);
        __half2 h1 = __floats2half2_rn(v.z, v.w);
        size_t m = (size_t)(row0 + rt + r);
        *reinterpret_cast<uint2*>(&g_Hh[m * FDIM + ctb + c4]) =
            make_uint2(*reinterpret_cast<uint32_t*>(&h0), *reinterpret_cast<uint32_t*>(&h1));
    }
}

// ---------------- gather: AGG[d] = sum_in Hh[s]*nrm + Hh[d]*dinv^2 + b ---------
__global__ void k_zero_stats() {
    if (threadIdx.x < 2 * FDIM) g_stats[threadIdx.x] = 0.f;
}

__device__ __forceinline__ float4 h4_load(const __half* base, int node, int lane) {
    uint2 raw = reinterpret_cast<const uint2*>(base + (size_t)node * FDIM)[lane];
    __half2 p0 = *reinterpret_cast<__half2*>(&raw.x);
    __half2 p1 = *reinterpret_cast<__half2*>(&raw.y);
    float2 f0 = __half22float2(p0);
    float2 f1 = __half22float2(p1);
    return make_float4(f0.x, f0.y, f1.x, f1.y);
}

__global__ void __launch_bounds__(256)
k_gather(const float* __restrict__ b, int n_nodes) {
    __shared__ float ssum[FDIM];
    __shared__ float ssq[FDIM];
    if (threadIdx.x < FDIM) { ssum[threadIdx.x] = 0.f; ssq[threadIdx.x] = 0.f; }
    __syncthreads();

    const int lane = threadIdx.x & 31;
    const int warp = threadIdx.x >> 5;
    const int nwarps = gridDim.x * 8;
    const float4 b4 = *reinterpret_cast<const float4*>(&b[lane * 4]);
    const __half* H = g_Hh;

    float4 sacc = make_float4(0.f, 0.f, 0.f, 0.f);
    float4 qacc = make_float4(0.f, 0.f, 0.f, 0.f);

    for (int d = blockIdx.x * 8 + warp; d < n_nodes; d += nwarps) {
        const int rs = g_rowptr[d];
        const int re = g_rowptr[d + 1];
        const float di = g_dinv[d];
        const float d2 = di * di;

        float4 h = h4_load(H, d, lane);
        float4 acc = make_float4(h.x * d2 + b4.x, h.y * d2 + b4.y,
                                 h.z * d2 + b4.z, h.w * d2 + b4.w);

        int e0 = rs;
        for (; e0 + 32 <= re; e0 += 32) {
            int   sl = g_csr_src[e0 + lane];
            float nl = g_csr_nrm[e0 + lane];
#pragma unroll
            for (int j = 0; j < 32; j++) {
                int   sj = __shfl_sync(0xffffffffu, sl, j);
                float nj = __shfl_sync(0xffffffffu, nl, j);
                float4 v = h4_load(H, sj, lane);
                acc.x += v.x * nj; acc.y += v.y * nj;
                acc.z += v.z * nj; acc.w += v.w * nj;
            }
        }
        if (e0 < re) {
            int cnt = re - e0;
            int   sl = (lane < cnt) ? g_csr_src[e0 + lane] : 0;
            float nl = (lane < cnt) ? g_csr_nrm[e0 + lane] : 0.f;
            for (int j0 = 0; j0 < cnt; j0 += 8) {
#pragma unroll
                for (int jj = 0; jj < 8; jj++) {
                    int j = j0 + jj;
                    int   sj = __shfl_sync(0xffffffffu, sl, j & 31);
                    float nj = __shfl_sync(0xffffffffu, nl, j & 31);
                    if (j < cnt) {
                        float4 v = h4_load(H, sj, lane);
                        acc.x += v.x * nj; acc.y += v.y * nj;
                        acc.z += v.z * nj; acc.w += v.w * nj;
                    }
                }
            }
        }

        reinterpret_cast<float4*>(g_AGG)[(size_t)d * 32 + lane] = acc;
        sacc.x += acc.x; sacc.y += acc.y; sacc.z += acc.z; sacc.w += acc.w;
        qacc.x += acc.x * acc.x; qacc.y += acc.y * acc.y;
        qacc.z += acc.z * acc.z; qacc.w += acc.w * acc.w;
    }

    int c = lane * 4;
    atomicAdd(&ssum[c + 0], sacc.x); atomicAdd(&ssum[c + 1], sacc.y);
    atomicAdd(&ssum[c + 2], sacc.z); atomicAdd(&ssum[c + 3], sacc.w);
    atomicAdd(&ssq[c + 0], qacc.x);  atomicAdd(&ssq[c + 1], qacc.y);
    atomicAdd(&ssq[c + 2], qacc.z);  atomicAdd(&ssq[c + 3], qacc.w);
    __syncthreads();
    if (threadIdx.x < FDIM) {
        atomicAdd(&g_stats[threadIdx.x], ssum[threadIdx.x]);
        atomicAdd(&g_stats[FDIM + threadIdx.x], ssq[threadIdx.x]);
    }
}

// ---------------- BN finalize ----------------------------------------------------
__global__ void k_bnfin(const float* __restrict__ gma, const float* __restrict__ bta,
                        int n_nodes) {
    int c = threadIdx.x;
    float inv_n = 1.0f / (float)n_nodes;
    float mu = g_stats[c] * inv_n;
    float var = g_stats[FDIM + c] * inv_n - mu * mu;
    float rstd = rsqrtf(var + BN_EPS);
    float sc = rstd * gma[c];
    g_scale[c] = sc;
    g_shift[c] = bta[c] - mu * sc;
}

// ---------------- pool with fused BN+ReLU (warp per node) ----------------------
__global__ void __launch_bounds__(256)
k_pool(const int* __restrict__ batch, int n_nodes) {
    int w = (blockIdx.x * blockDim.x + threadIdx.x) >> 5;
    int lane = threadIdx.x & 31;
    if (w >= n_nodes) return;
    int g = batch[w];
    int c = lane * 4;
    float4 v = reinterpret_cast<const float4*>(g_AGG)[(size_t)w * 32 + lane];
    float4 sc = *reinterpret_cast<const float4*>(&g_scale[c]);
    float4 sh = *reinterpret_cast<const float4*>(&g_shift[c]);
    v.x = fmaxf(v.x * sc.x + sh.x, 0.f);
    v.y = fmaxf(v.y * sc.y + sh.y, 0.f);
    v.z = fmaxf(v.z * sc.z + sh.z, 0.f);
    v.w = fmaxf(v.w * sc.w + sh.w, 0.f);
    float* p = &g_pool[(size_t)g * FDIM + c];
    red_add_f32(p + 0, v.x);
    red_add_f32(p + 1, v.y);
    red_add_f32(p + 2, v.z);
    red_add_f32(p + 3, v.w);
    if (lane == 0) atomicAdd(&g_cnt[g], 1.0f);
}

// ---------------- final FC ------------------------------------------------------
__global__ void __launch_bounds__(256)
k_fc(const float* __restrict__ fcW, const float* __restrict__ fcb,
     float* __restrict__ out, int n_graphs) {
    __shared__ float sW[FDIM * 64];
    for (int l = threadIdx.x; l < FDIM * 64; l += 256) sW[l] = fcW[l];
    __syncthreads();
    int g = blockIdx.x * 4 + (threadIdx.x >> 6);
    int c = threadIdx.x & 63;
    if (g >= n_graphs) return;
    float inv = 1.0f / fmaxf(g_cnt[g], 1.0f);
    float acc = 0.f;
#pragma unroll 16
    for (int k = 0; k < FDIM; k++) acc += g_pool[(size_t)g * FDIM + k] * sW[k * 64 + c];
    out[(size_t)g * 64 + c] = acc * inv + fcb[c];
}

// ---------------- launch ---------------------------------------------------------
extern "C" void kernel_launch(void* const* d_in, const int* in_sizes, int n_in,
                              void* d_out, int out_size) {
    const float* x     = (const float*)d_in[0];
    const int*   ei    = (const int*)d_in[1];
    const int*   batch = (const int*)d_in[2];
    const float* W1 = (const float*)d_in[3];
    const float* b1 = (const float*)d_in[4];
    const float* g1 = (const float*)d_in[5];
    const float* be1 = (const float*)d_in[6];
    const float* W2 = (const float*)d_in[7];
    const float* b2 = (const float*)d_in[8];
    const float* g2 = (const float*)d_in[9];
    const float* be2 = (const float*)d_in[10];
    const float* W3 = (const float*)d_in[11];
    const float* b3 = (const float*)d_in[12];
    const float* g3 = (const float*)d_in[13];
    const float* be3 = (const float*)d_in[14];
    const float* fcW = (const float*)d_in[15];
    const float* fcb = (const float*)d_in[16];
    float* out = (float*)d_out;

    const int n_nodes  = in_sizes[0] / FDIM;
    const int n_edges  = in_sizes[1] / 2;
    const int n_graphs = out_size / 64;
    const int* src = ei;
    const int* dst = ei + n_edges;
    const int nblocks = (n_nodes + SCAN_B - 1) / SCAN_B;

    static int smem_set = 0;
    if (!smem_set) {
        cudaFuncSetAttribute(k_gemm_wm, cudaFuncAttributeMaxDynamicSharedMemorySize,
                             SMEM_WM);
        smem_set = 1;
    }

    // ---- CSR build + W split (once per call) ----
    {
        int work = n_graphs * FDIM;
        if (n_nodes > work) work = n_nodes;
        k_zero<<<(work + 255) / 256, 256>>>(n_nodes, n_graphs);
    }
    k_wsplit<<<3, 256>>>(W1, W2, W3);
    k_deg<<<(n_edges + 255) / 256, 256>>>(dst, n_edges);
    k_dinv<<<(n_nodes + 255) / 256, 256>>>(n_nodes);
    k_bsum<<<nblocks, SCAN_B>>>(n_nodes);
    k_bscan<<<1, MAX_BLK>>>(nblocks);
    k_scanfin<<<nblocks, SCAN_B>>>(n_nodes);
    k_fill<<<(n_edges + 255) / 256, 256>>>(src, dst, n_edges);

    const int gemm_grid   = (n_nodes + 127) / 128;
    const int gather_grid = 1184;

    const float* bs[3]  = {b1, b2, b3};
    const float* gs[3]  = {g1, g2, g3};
    const float* bes[3] = {be1, be2, be3};

    for (int layer = 0; layer < 3; layer++) {
        k_gemm_wm<<<gemm_grid, 256, SMEM_WM>>>(layer == 0 ? x : nullptr,
                                               layer == 0 ? 0 : 1, layer, n_nodes);
        k_zero_stats<<<1, 256>>>();
        k_gather<<<gather_grid, 256>>>(bs[layer], n_nodes);
        k_bnfin<<<1, 128>>>(gs[layer], bes[layer], n_nodes);
    }

    k_pool<<<(n_nodes * 32 + 255) / 256, 256>>>(batch, n_nodes);
    k_fc<<<(n_graphs + 3) / 4, 256>>>(fcW, fcb, out, n_graphs);
}

// round 13
// speedup vs baseline: 3.0316x; 1.0320x over previous
#include <cuda_runtime.h>
#include <cuda_bf16.h>
#include <cuda_fp16.h>
#include <mma.h>
#include <cstdint>

using namespace nvcuda;

#define MAX_N 100000
#define MAX_E 1600000
#define MAX_G 4096
#define FDIM 128
#define BN_EPS 1e-5f
#define SCAN_B 1024
#define MAX_BLK 128
#define LDS_T 136   // smem row stride in bf16 elements

// ---------------- scratch (device globals; no allocation allowed) -------------
__device__ __half g_Hh[(size_t)(MAX_N + 128) * FDIM];   // fp16 H (padded tiles)
__device__ __half g_AGGh[(size_t)MAX_N * FDIM];         // fp16 AGG
__device__ float g_dinv[MAX_N];
__device__ int   g_deg[MAX_N];
__device__ int   g_rowptr[MAX_N + 1];
__device__ int   g_cursor[MAX_N];
__device__ int   g_bsum[MAX_BLK];
__device__ int   g_boff[MAX_BLK];
__device__ int   g_csr_src[MAX_E];
__device__ float g_csr_nrm[MAX_E];
__device__ float g_stats[2 * FDIM];
__device__ float g_scale[FDIM];
__device__ float g_shift[FDIM];
__device__ float g_pool[(size_t)MAX_G * FDIM];
__device__ float g_cnt[MAX_G];
// W bf16 hi/lo images, plain row-major [k][n]
__device__ __align__(16) __nv_bfloat16 g_Bimg[3][2][FDIM * FDIM];

// ---------------- helpers -----------------------------------------------------
__device__ __forceinline__ void red_add_f32(float* p, float v) {
    asm volatile("red.global.add.f32 [%0], %1;" :: "l"(p), "f"(v) : "memory");
}
__device__ __forceinline__ float4 h4_from_u2(uint2 raw) {
    __half2 p0 = *reinterpret_cast<__half2*>(&raw.x);
    __half2 p1 = *reinterpret_cast<__half2*>(&raw.y);
    float2 f0 = __half22float2(p0);
    float2 f1 = __half22float2(p1);
    return make_float4(f0.x, f0.y, f1.x, f1.y);
}
__device__ __forceinline__ uint2 u2_from_f4(float4 v) {
    __half2 h0 = __floats2half2_rn(v.x, v.y);
    __half2 h1 = __floats2half2_rn(v.z, v.w);
    return make_uint2(*reinterpret_cast<uint32_t*>(&h0),
                      *reinterpret_cast<uint32_t*>(&h1));
}

// ---------------- init ----------------------------------------------------------
__global__ void k_zero(int n_nodes, int n_graphs) {
    int i = blockIdx.x * blockDim.x + threadIdx.x;
    if (i < n_nodes) g_deg[i] = 0;
    if (i < n_graphs * FDIM) g_pool[i] = 0.f;
    if (i < n_graphs) g_cnt[i] = 0.f;
}
__global__ void k_deg(const int* __restrict__ dst, int n_edges) {
    int e = blockIdx.x * blockDim.x + threadIdx.x;
    if (e < n_edges) atomicAdd(&g_deg[dst[e]], 1);
}
__global__ void k_dinv(int n_nodes) {
    int i = blockIdx.x * blockDim.x + threadIdx.x;
    if (i < n_nodes) g_dinv[i] = rsqrtf((float)g_deg[i] + 1.0f);
}

// ---------------- W split: bf16 hi/lo, row-major [k][n] ------------------------
__global__ void k_wsplit(const float* __restrict__ W0, const float* __restrict__ W1,
                         const float* __restrict__ W2) {
    const float* W = (blockIdx.x == 0) ? W0 : (blockIdx.x == 1) ? W1 : W2;
    __nv_bfloat16* bh = g_Bimg[blockIdx.x][0];
    __nv_bfloat16* bl = g_Bimg[blockIdx.x][1];
    for (int idx = threadIdx.x; idx < FDIM * FDIM; idx += 256) {
        float w = W[idx];
        __nv_bfloat16 hi = __float2bfloat16(w);
        __nv_bfloat16 lo = __float2bfloat16(w - __bfloat162float(hi));
        bh[idx] = hi;
        bl[idx] = lo;
    }
}

// ---------------- parallel scan --------------------------------------------------
__global__ void __launch_bounds__(SCAN_B)
k_bsum(int n_nodes) {
    int i = blockIdx.x * SCAN_B + threadIdx.x;
    int v = (i < n_nodes) ? g_deg[i] : 0;
    for (int off = 16; off > 0; off >>= 1) v += __shfl_down_sync(0xffffffffu, v, off);
    __shared__ int ws[32];
    int lane = threadIdx.x & 31, w = threadIdx.x >> 5;
    if (lane == 0) ws[w] = v;
    __syncthreads();
    if (w == 0) {
        int s = ws[lane];
        for (int off = 16; off > 0; off >>= 1) s += __shfl_down_sync(0xffffffffu, s, off);
        if (lane == 0) g_bsum[blockIdx.x] = s;
    }
}
__global__ void k_bscan(int nblocks) {
    __shared__ int s[MAX_BLK];
    int tid = threadIdx.x;
    int v = (tid < nblocks) ? g_bsum[tid] : 0;
    s[tid] = v;
    __syncthreads();
#pragma unroll
    for (int off = 1; off < MAX_BLK; off <<= 1) {
        int t = (tid >= off) ? s[tid - off] : 0;
        __syncthreads();
        s[tid] += t;
        __syncthreads();
    }
    g_boff[tid] = (tid > 0) ? s[tid - 1] : 0;
}
__global__ void __launch_bounds__(SCAN_B)
k_scanfin(int n_nodes) {
    int i = blockIdx.x * SCAN_B + threadIdx.x;
    int v = (i < n_nodes) ? g_deg[i] : 0;
    int lane = threadIdx.x & 31, w = threadIdx.x >> 5;
    int x = v;
#pragma unroll
    for (int off = 1; off < 32; off <<= 1) {
        int t = __shfl_up_sync(0xffffffffu, x, off);
        if (lane >= off) x += t;
    }
    __shared__ int ws[32];
    if (lane == 31) ws[w] = x;
    __syncthreads();
    if (w == 0) {
        int s = ws[lane];
#pragma unroll
        for (int off = 1; off < 32; off <<= 1) {
            int t = __shfl_up_sync(0xffffffffu, s, off);
            if (lane >= off) s += t;
        }
        ws[lane] = s;
    }
    __syncthreads();
    int incl = x + ((w > 0) ? ws[w - 1] : 0) + g_boff[blockIdx.x];
    if (i < n_nodes) {
        g_rowptr[i + 1] = incl;
        g_cursor[i] = incl - v;
    }
    if (i == 0) g_rowptr[0] = 0;
}
__global__ void k_fill(const int* __restrict__ src, const int* __restrict__ dst,
                       int n_edges) {
    int e = blockIdx.x * blockDim.x + threadIdx.x;
    if (e >= n_edges) return;
    int s = src[e];
    int d = dst[e];
    int pos = atomicAdd(&g_cursor[d], 1);
    g_csr_src[pos] = s;
    g_csr_nrm[pos] = g_dinv[s] * g_dinv[d];
}

// ---------------- wmma GEMM: Hh = act(in) @ W (2-term bf16 split, fp16 out) ----
// mode 0: in = Xin (fp32). mode 1: in = g_AGGh (fp16) with fused BN+ReLU.
#define SMEM_WM (4 * 128 * LDS_T * 2)   // bytes = 139264

__global__ void __launch_bounds__(256)
k_gemm_wm(const float* __restrict__ Xin, int mode, int layer, int n_nodes) {
    extern __shared__ __align__(16) __nv_bfloat16 sm[];
    __nv_bfloat16* sAh = sm;
    __nv_bfloat16* sAl = sm + 128 * LDS_T;
    __nv_bfloat16* sBh = sm + 2 * 128 * LDS_T;
    __nv_bfloat16* sBl = sm + 3 * 128 * LDS_T;
    __shared__ float sSc[FDIM];
    __shared__ float sSh[FDIM];

    const int tid = threadIdx.x;
    const int wid = tid >> 5;
    const int lane = tid & 31;
    const int row0 = blockIdx.x * 128;

    if (mode && tid < FDIM) { sSc[tid] = g_scale[tid]; sSh[tid] = g_shift[tid]; }

    // load B hi/lo (row-major [k][n]) into padded smem
    {
        const uint4* bh = reinterpret_cast<const uint4*>(g_Bimg[layer][0]);
        const uint4* bl = reinterpret_cast<const uint4*>(g_Bimg[layer][1]);
        for (int i = tid; i < FDIM * FDIM / 8; i += 256) {
            int r = i >> 4;
            int c8 = (i & 15) * 8;
            *reinterpret_cast<uint4*>(&sBh[r * LDS_T + c8]) = bh[i];
            *reinterpret_cast<uint4*>(&sBl[r * LDS_T + c8]) = bl[i];
        }
    }
    if (mode) __syncthreads();

    // load + (BN+ReLU) + split A tile
    for (int i4 = tid; i4 < 4096; i4 += 256) {
        int m = i4 >> 5;
        int q = i4 & 31;
        int k0 = q * 4;
        int gr = row0 + m;
        float4 v = make_float4(0.f, 0.f, 0.f, 0.f);
        if (gr < n_nodes) {
            if (mode) {
                uint2 raw = reinterpret_cast<const uint2*>(g_AGGh)[(size_t)gr * 32 + q];
                v = h4_from_u2(raw);
                v.x = fmaxf(v.x * sSc[k0 + 0] + sSh[k0 + 0], 0.f);
                v.y = fmaxf(v.y * sSc[k0 + 1] + sSh[k0 + 1], 0.f);
                v.z = fmaxf(v.z * sSc[k0 + 2] + sSh[k0 + 2], 0.f);
                v.w = fmaxf(v.w * sSc[k0 + 3] + sSh[k0 + 3], 0.f);
            } else {
                v = reinterpret_cast<const float4*>(Xin)[(size_t)gr * 32 + q];
            }
        }
        float f[4] = {v.x, v.y, v.z, v.w};
        unsigned short hh[4], ll[4];
#pragma unroll
        for (int j = 0; j < 4; j++) {
            __nv_bfloat16 hi = __float2bfloat16(f[j]);
            __nv_bfloat16 lo = __float2bfloat16(f[j] - __bfloat162float(hi));
            hh[j] = *reinterpret_cast<unsigned short*>(&hi);
            ll[j] = *reinterpret_cast<unsigned short*>(&lo);
        }
        uint2 hp = make_uint2((uint32_t)hh[0] | ((uint32_t)hh[1] << 16),
                              (uint32_t)hh[2] | ((uint32_t)hh[3] << 16));
        uint2 lp = make_uint2((uint32_t)ll[0] | ((uint32_t)ll[1] << 16),
                              (uint32_t)ll[2] | ((uint32_t)ll[3] << 16));
        *reinterpret_cast<uint2*>(&sAh[m * LDS_T + k0]) = hp;
        *reinterpret_cast<uint2*>(&sAl[m * LDS_T + k0]) = lp;
    }
    __syncthreads();

    const int rt = (wid & 3) * 32;
    const int ctb = (wid >> 2) * 64;

    wmma::fragment<wmma::accumulator, 16, 16, 16, float> acc[2][4];
#pragma unroll
    for (int r = 0; r < 2; r++)
#pragma unroll
        for (int c = 0; c < 4; c++) wmma::fill_fragment(acc[r][c], 0.f);

#pragma unroll
    for (int ks = 0; ks < 8; ks++) {
        const int k0 = ks * 16;
        wmma::fragment<wmma::matrix_a, 16, 16, 16, __nv_bfloat16, wmma::row_major> ah[2], al[2];
        wmma::load_matrix_sync(ah[0], &sAh[(rt + 0) * LDS_T + k0], LDS_T);
        wmma::load_matrix_sync(ah[1], &sAh[(rt + 16) * LDS_T + k0], LDS_T);
        wmma::load_matrix_sync(al[0], &sAl[(rt + 0) * LDS_T + k0], LDS_T);
        wmma::load_matrix_sync(al[1], &sAl[(rt + 16) * LDS_T + k0], LDS_T);
#pragma unroll
        for (int c = 0; c < 4; c++) {
            wmma::fragment<wmma::matrix_b, 16, 16, 16, __nv_bfloat16, wmma::row_major> bh, bl;
            wmma::load_matrix_sync(bh, &sBh[k0 * LDS_T + ctb + c * 16], LDS_T);
            wmma::load_matrix_sync(bl, &sBl[k0 * LDS_T + ctb + c * 16], LDS_T);
#pragma unroll
            for (int r = 0; r < 2; r++) {
                wmma::mma_sync(acc[r][c], ah[r], bh, acc[r][c]);
                wmma::mma_sync(acc[r][c], al[r], bh, acc[r][c]);
                wmma::mma_sync(acc[r][c], ah[r], bl, acc[r][c]);
            }
        }
    }

    // epilogue: stage fp32 accs through smem, emit fp16
    __syncthreads();
    float* stage = reinterpret_cast<float*>(sm) + wid * 2048;   // 32x64 floats/warp
#pragma unroll
    for (int r = 0; r < 2; r++)
#pragma unroll
        for (int c = 0; c < 4; c++)
            wmma::store_matrix_sync(&stage[r * 16 * 64 + c * 16], acc[r][c], 64,
                                    wmma::mem_row_major);
    __syncwarp();
#pragma unroll
    for (int it = 0; it < 16; it++) {
        int r  = it * 2 + (lane >> 4);
        int c4 = (lane & 15) * 4;
        float4 v = *reinterpret_cast<const float4*>(&stage[r * 64 + c4]);
        size_t m = (size_t)(row0 + rt + r);
        *reinterpret_cast<uint2*>(&g_Hh[m * FDIM + ctb + c4]) = u2_from_f4(v);
    }
}

// ---------------- gather: AGGh[d] = sum_in Hh[s]*nrm + Hh[d]*dinv^2 + b --------
__global__ void k_zero_stats() {
    if (threadIdx.x < 2 * FDIM) g_stats[threadIdx.x] = 0.f;
}

__device__ __forceinline__ float4 h4_load(const __half* base, int node, int lane) {
    return h4_from_u2(reinterpret_cast<const uint2*>(base + (size_t)node * FDIM)[lane]);
}

__global__ void __launch_bounds__(256)
k_gather(const float* __restrict__ b, int n_nodes) {
    __shared__ float ssum[FDIM];
    __shared__ float ssq[FDIM];
    if (threadIdx.x < FDIM) { ssum[threadIdx.x] = 0.f; ssq[threadIdx.x] = 0.f; }
    __syncthreads();

    const int lane = threadIdx.x & 31;
    const int warp = threadIdx.x >> 5;
    const int nwarps = gridDim.x * 8;
    const float4 b4 = *reinterpret_cast<const float4*>(&b[lane * 4]);
    const __half* H = g_Hh;

    float4 sacc = make_float4(0.f, 0.f, 0.f, 0.f);
    float4 qacc = make_float4(0.f, 0.f, 0.f, 0.f);

    for (int d = blockIdx.x * 8 + warp; d < n_nodes; d += nwarps) {
        const int rs = g_rowptr[d];
        const int re = g_rowptr[d + 1];
        const float di = g_dinv[d];
        const float d2 = di * di;

        float4 h = h4_load(H, d, lane);
        float4 acc = make_float4(h.x * d2 + b4.x, h.y * d2 + b4.y,
                                 h.z * d2 + b4.z, h.w * d2 + b4.w);

        int e0 = rs;
        for (; e0 + 32 <= re; e0 += 32) {
            int   sl = g_csr_src[e0 + lane];
            float nl = g_csr_nrm[e0 + lane];
#pragma unroll
            for (int j = 0; j < 32; j++) {
                int   sj = __shfl_sync(0xffffffffu, sl, j);
                float nj = __shfl_sync(0xffffffffu, nl, j);
                float4 v = h4_load(H, sj, lane);
                acc.x += v.x * nj; acc.y += v.y * nj;
                acc.z += v.z * nj; acc.w += v.w * nj;
            }
        }
        if (e0 < re) {
            int cnt = re - e0;
            int   sl = (lane < cnt) ? g_csr_src[e0 + lane] : 0;
            float nl = (lane < cnt) ? g_csr_nrm[e0 + lane] : 0.f;
            for (int j0 = 0; j0 < cnt; j0 += 8) {
#pragma unroll
                for (int jj = 0; jj < 8; jj++) {
                    int j = j0 + jj;
                    int   sj = __shfl_sync(0xffffffffu, sl, j & 31);
                    float nj = __shfl_sync(0xffffffffu, nl, j & 31);
                    if (j < cnt) {
                        float4 v = h4_load(H, sj, lane);
                        acc.x += v.x * nj; acc.y += v.y * nj;
                        acc.z += v.z * nj; acc.w += v.w * nj;
                    }
                }
            }
        }

        reinterpret_cast<uint2*>(g_AGGh)[(size_t)d * 32 + lane] = u2_from_f4(acc);
        sacc.x += acc.x; sacc.y += acc.y; sacc.z += acc.z; sacc.w += acc.w;
        qacc.x += acc.x * acc.x; qacc.y += acc.y * acc.y;
        qacc.z += acc.z * acc.z; qacc.w += acc.w * acc.w;
    }

    int c = lane * 4;
    atomicAdd(&ssum[c + 0], sacc.x); atomicAdd(&ssum[c + 1], sacc.y);
    atomicAdd(&ssum[c + 2], sacc.z); atomicAdd(&ssum[c + 3], sacc.w);
    atomicAdd(&ssq[c + 0], qacc.x);  atomicAdd(&ssq[c + 1], qacc.y);
    atomicAdd(&ssq[c + 2], qacc.z);  atomicAdd(&ssq[c + 3], qacc.w);
    __syncthreads();
    if (threadIdx.x < FDIM) {
        atomicAdd(&g_stats[threadIdx.x], ssum[threadIdx.x]);
        atomicAdd(&g_stats[FDIM + threadIdx.x], ssq[threadIdx.x]);
    }
}

// ---------------- BN finalize ----------------------------------------------------
__global__ void k_bnfin(const float* __restrict__ gma, const float* __restrict__ bta,
                        int n_nodes) {
    int c = threadIdx.x;
    float inv_n = 1.0f / (float)n_nodes;
    float mu = g_stats[c] * inv_n;
    float var = g_stats[FDIM + c] * inv_n - mu * mu;
    float rstd = rsqrtf(var + BN_EPS);
    float sc = rstd * gma[c];
    g_scale[c] = sc;
    g_shift[c] = bta[c] - mu * sc;
}

// ---------------- pool with fused BN+ReLU (warp per node) ----------------------
__global__ void __launch_bounds__(256)
k_pool(const int* __restrict__ batch, int n_nodes) {
    int w = (blockIdx.x * blockDim.x + threadIdx.x) >> 5;
    int lane = threadIdx.x & 31;
    if (w >= n_nodes) return;
    int g = batch[w];
    int c = lane * 4;
    float4 v = h4_from_u2(reinterpret_cast<const uint2*>(g_AGGh)[(size_t)w * 32 + lane]);
    float4 sc = *reinterpret_cast<const float4*>(&g_scale[c]);
    float4 sh = *reinterpret_cast<const float4*>(&g_shift[c]);
    v.x = fmaxf(v.x * sc.x + sh.x, 0.f);
    v.y = fmaxf(v.y * sc.y + sh.y, 0.f);
    v.z = fmaxf(v.z * sc.z + sh.z, 0.f);
    v.w = fmaxf(v.w * sc.w + sh.w, 0.f);
    float* p = &g_pool[(size_t)g * FDIM + c];
    red_add_f32(p + 0, v.x);
    red_add_f32(p + 1, v.y);
    red_add_f32(p + 2, v.z);
    red_add_f32(p + 3, v.w);
    if (lane == 0) atomicAdd(&g_cnt[g], 1.0f);
}

// ---------------- final FC ------------------------------------------------------
__global__ void __launch_bounds__(256)
k_fc(const float* __restrict__ fcW, const float* __restrict__ fcb,
     float* __restrict__ out, int n_graphs) {
    __shared__ float sW[FDIM * 64];
    for (int l = threadIdx.x; l < FDIM * 64; l += 256) sW[l] = fcW[l];
    __syncthreads();
    int g = blockIdx.x * 4 + (threadIdx.x >> 6);
    int c = threadIdx.x & 63;
    if (g >= n_graphs) return;
    float inv = 1.0f / fmaxf(g_cnt[g], 1.0f);
    float acc = 0.f;
#pragma unroll 16
    for (int k = 0; k < FDIM; k++) acc += g_pool[(size_t)g * FDIM + k] * sW[k * 64 + c];
    out[(size_t)g * 64 + c] = acc * inv + fcb[c];
}

// ---------------- launch ---------------------------------------------------------
extern "C" void kernel_launch(void* const* d_in, const int* in_sizes, int n_in,
                              void* d_out, int out_size) {
    const float* x     = (const float*)d_in[0];
    const int*   ei    = (const int*)d_in[1];
    const int*   batch = (const int*)d_in[2];
    const float* W1 = (const float*)d_in[3];
    const float* b1 = (const float*)d_in[4];
    const float* g1 = (const float*)d_in[5];
    const float* be1 = (const float*)d_in[6];
    const float* W2 = (const float*)d_in[7];
    const float* b2 = (const float*)d_in[8];
    const float* g2 = (const float*)d_in[9];
    const float* be2 = (const float*)d_in[10];
    const float* W3 = (const float*)d_in[11];
    const float* b3 = (const float*)d_in[12];
    const float* g3 = (const float*)d_in[13];
    const float* be3 = (const float*)d_in[14];
    const float* fcW = (const float*)d_in[15];
    const float* fcb = (const float*)d_in[16];
    float* out = (float*)d_out;

    const int n_nodes  = in_sizes[0] / FDIM;
    const int n_edges  = in_sizes[1] / 2;
    const int n_graphs = out_size / 64;
    const int* src = ei;
    const int* dst = ei + n_edges;
    const int nblocks = (n_nodes + SCAN_B - 1) / SCAN_B;

    static int smem_set = 0;
    if (!smem_set) {
        cudaFuncSetAttribute(k_gemm_wm, cudaFuncAttributeMaxDynamicSharedMemorySize,
                             SMEM_WM);
        smem_set = 1;
    }

    // ---- CSR build + W split (once per call) ----
    {
        int work = n_graphs * FDIM;
        if (n_nodes > work) work = n_nodes;
        k_zero<<<(work + 255) / 256, 256>>>(n_nodes, n_graphs);
    }
    k_wsplit<<<3, 256>>>(W1, W2, W3);
    k_deg<<<(n_edges + 255) / 256, 256>>>(dst, n_edges);
    k_dinv<<<(n_nodes + 255) / 256, 256>>>(n_nodes);
    k_bsum<<<nblocks, SCAN_B>>>(n_nodes);
    k_bscan<<<1, MAX_BLK>>>(nblocks);
    k_scanfin<<<nblocks, SCAN_B>>>(n_nodes);
    k_fill<<<(n_edges + 255) / 256, 256>>>(src, dst, n_edges);

    const int gemm_grid   = (n_nodes + 127) / 128;
    const int gather_grid = 1184;

    const float* bs[3]  = {b1, b2, b3};
    const float* gs[3]  = {g1, g2, g3};
    const float* bes[3] = {be1, be2, be3};

    for (int layer = 0; layer < 3; layer++) {
        k_gemm_wm<<<gemm_grid, 256, SMEM_WM>>>(layer == 0 ? x : nullptr,
                                               layer == 0 ? 0 : 1, layer, n_nodes);
        k_zero_stats<<<1, 256>>>();
        k_gather<<<gather_grid, 256>>>(bs[layer], n_nodes);
        k_bnfin<<<1, 128>>>(gs[layer], bes[layer], n_nodes);
    }

    k_pool<<<(n_nodes * 32 + 255) / 256, 256>>>(batch, n_nodes);
    k_fc<<<(n_graphs + 3) / 4, 256>>>(fcW, fcb, out, n_graphs);
}

// round 14
// speedup vs baseline: 3.1531x; 1.0401x over previous
#include <cuda_runtime.h>
#include <cuda_bf16.h>
#include <cuda_fp16.h>
#include <mma.h>
#include <cstdint>

using namespace nvcuda;

#define MAX_N 100000
#define MAX_E 1600000
#define MAX_G 4096
#define FDIM 128
#define BN_EPS 1e-5f
#define SCAN_B 1024
#define MAX_BLK 128
#define LDS_T 136   // smem row stride in bf16 elements

// ---------------- scratch (device globals; no allocation allowed) -------------
__device__ __half g_Hh[(size_t)(MAX_N + 128) * FDIM];   // fp16 H (padded tiles)
__device__ __half g_AGGh[(size_t)MAX_N * FDIM];         // fp16 AGG
__device__ float g_dinv[MAX_N];
__device__ int   g_deg[MAX_N];
__device__ int   g_rowptr[MAX_N + 1];
__device__ int   g_cursor[MAX_N];
__device__ int   g_bsum[MAX_BLK];
__device__ int   g_boff[MAX_BLK];
__device__ int   g_csr_src[MAX_E];
__device__ float g_csr_nrm[MAX_E];
__device__ float g_stats[2 * FDIM];
__device__ float g_scale[FDIM];
__device__ float g_shift[FDIM];
__device__ float g_pool[(size_t)MAX_G * FDIM];
__device__ float g_cnt[MAX_G];
// W bf16 hi/lo images, plain row-major [k][n]
__device__ __align__(16) __nv_bfloat16 g_Bimg[3][2][FDIM * FDIM];

// ---------------- helpers -----------------------------------------------------
__device__ __forceinline__ void red_add_f32(float* p, float v) {
    asm volatile("red.global.add.f32 [%0], %1;" :: "l"(p), "f"(v) : "memory");
}
__device__ __forceinline__ float4 h4_from_u2(uint2 raw) {
    __half2 p0 = *reinterpret_cast<__half2*>(&raw.x);
    __half2 p1 = *reinterpret_cast<__half2*>(&raw.y);
    float2 f0 = __half22float2(p0);
    float2 f1 = __half22float2(p1);
    return make_float4(f0.x, f0.y, f1.x, f1.y);
}
__device__ __forceinline__ uint2 u2_from_f4(float4 v) {
    __half2 h0 = __floats2half2_rn(v.x, v.y);
    __half2 h1 = __floats2half2_rn(v.z, v.w);
    return make_uint2(*reinterpret_cast<uint32_t*>(&h0),
                      *reinterpret_cast<uint32_t*>(&h1));
}

// ---------------- init ----------------------------------------------------------
__global__ void k_zero(int n_nodes, int n_graphs) {
    int i = blockIdx.x * blockDim.x + threadIdx.x;
    if (i < n_nodes) g_deg[i] = 0;
    if (i < n_graphs * FDIM) g_pool[i] = 0.f;
    if (i < n_graphs) g_cnt[i] = 0.f;
    if (i < 2 * FDIM) g_stats[i] = 0.f;
}
__global__ void k_deg(const int* __restrict__ dst, int n_edges) {
    int e = blockIdx.x * blockDim.x + threadIdx.x;
    if (e < n_edges) atomicAdd(&g_deg[dst[e]], 1);
}
__global__ void k_dinv(int n_nodes) {
    int i = blockIdx.x * blockDim.x + threadIdx.x;
    if (i < n_nodes) g_dinv[i] = rsqrtf((float)g_deg[i] + 1.0f);
}

// ---------------- W split: bf16 hi/lo, row-major [k][n] ------------------------
__global__ void k_wsplit(const float* __restrict__ W0, const float* __restrict__ W1,
                         const float* __restrict__ W2) {
    const float* W = (blockIdx.x == 0) ? W0 : (blockIdx.x == 1) ? W1 : W2;
    __nv_bfloat16* bh = g_Bimg[blockIdx.x][0];
    __nv_bfloat16* bl = g_Bimg[blockIdx.x][1];
    for (int idx = threadIdx.x; idx < FDIM * FDIM; idx += 256) {
        float w = W[idx];
        __nv_bfloat16 hi = __float2bfloat16(w);
        __nv_bfloat16 lo = __float2bfloat16(w - __bfloat162float(hi));
        bh[idx] = hi;
        bl[idx] = lo;
    }
}

// ---------------- parallel scan --------------------------------------------------
__global__ void __launch_bounds__(SCAN_B)
k_bsum(int n_nodes) {
    int i = blockIdx.x * SCAN_B + threadIdx.x;
    int v = (i < n_nodes) ? g_deg[i] : 0;
    for (int off = 16; off > 0; off >>= 1) v += __shfl_down_sync(0xffffffffu, v, off);
    __shared__ int ws[32];
    int lane = threadIdx.x & 31, w = threadIdx.x >> 5;
    if (lane == 0) ws[w] = v;
    __syncthreads();
    if (w == 0) {
        int s = ws[lane];
        for (int off = 16; off > 0; off >>= 1) s += __shfl_down_sync(0xffffffffu, s, off);
        if (lane == 0) g_bsum[blockIdx.x] = s;
    }
}
__global__ void k_bscan(int nblocks) {
    __shared__ int s[MAX_BLK];
    int tid = threadIdx.x;
    int v = (tid < nblocks) ? g_bsum[tid] : 0;
    s[tid] = v;
    __syncthreads();
#pragma unroll
    for (int off = 1; off < MAX_BLK; off <<= 1) {
        int t = (tid >= off) ? s[tid - off] : 0;
        __syncthreads();
        s[tid] += t;
        __syncthreads();
    }
    g_boff[tid] = (tid > 0) ? s[tid - 1] : 0;
}
__global__ void __launch_bounds__(SCAN_B)
k_scanfin(int n_nodes) {
    int i = blockIdx.x * SCAN_B + threadIdx.x;
    int v = (i < n_nodes) ? g_deg[i] : 0;
    int lane = threadIdx.x & 31, w = threadIdx.x >> 5;
    int x = v;
#pragma unroll
    for (int off = 1; off < 32; off <<= 1) {
        int t = __shfl_up_sync(0xffffffffu, x, off);
        if (lane >= off) x += t;
    }
    __shared__ int ws[32];
    if (lane == 31) ws[w] = x;
    __syncthreads();
    if (w == 0) {
        int s = ws[lane];
#pragma unroll
        for (int off = 1; off < 32; off <<= 1) {
            int t = __shfl_up_sync(0xffffffffu, s, off);
            if (lane >= off) s += t;
        }
        ws[lane] = s;
    }
    __syncthreads();
    int incl = x + ((w > 0) ? ws[w - 1] : 0) + g_boff[blockIdx.x];
    if (i < n_nodes) {
        g_rowptr[i + 1] = incl;
        g_cursor[i] = incl - v;
    }
    if (i == 0) g_rowptr[0] = 0;
}
__global__ void k_fill(const int* __restrict__ src, const int* __restrict__ dst,
                       int n_edges) {
    int e = blockIdx.x * blockDim.x + threadIdx.x;
    if (e >= n_edges) return;
    int s = src[e];
    int d = dst[e];
    int pos = atomicAdd(&g_cursor[d], 1);
    g_csr_src[pos] = s;
    g_csr_nrm[pos] = g_dinv[s] * g_dinv[d];
}

// ---------------- wmma GEMM: Hh = act(in) @ W (2-term bf16 split, fp16 out) ----
// mode 0: in = Xin (fp32). mode 1: in = g_AGGh (fp16) with fused BN+ReLU.
#define SMEM_WM (4 * 128 * LDS_T * 2)   // bytes = 139264

__global__ void __launch_bounds__(256)
k_gemm_wm(const float* __restrict__ Xin, int mode, int layer, int n_nodes) {
    extern __shared__ __align__(16) __nv_bfloat16 sm[];
    __nv_bfloat16* sAh = sm;
    __nv_bfloat16* sAl = sm + 128 * LDS_T;
    __nv_bfloat16* sBh = sm + 2 * 128 * LDS_T;
    __nv_bfloat16* sBl = sm + 3 * 128 * LDS_T;
    __shared__ float sSc[FDIM];
    __shared__ float sSh[FDIM];

    const int tid = threadIdx.x;
    const int wid = tid >> 5;
    const int lane = tid & 31;
    const int row0 = blockIdx.x * 128;

    if (mode && tid < FDIM) { sSc[tid] = g_scale[tid]; sSh[tid] = g_shift[tid]; }

    // load B hi/lo (row-major [k][n]) into padded smem
    {
        const uint4* bh = reinterpret_cast<const uint4*>(g_Bimg[layer][0]);
        const uint4* bl = reinterpret_cast<const uint4*>(g_Bimg[layer][1]);
        for (int i = tid; i < FDIM * FDIM / 8; i += 256) {
            int r = i >> 4;
            int c8 = (i & 15) * 8;
            *reinterpret_cast<uint4*>(&sBh[r * LDS_T + c8]) = bh[i];
            *reinterpret_cast<uint4*>(&sBl[r * LDS_T + c8]) = bl[i];
        }
    }
    if (mode) __syncthreads();

    // load + (BN+ReLU) + split A tile
    for (int i4 = tid; i4 < 4096; i4 += 256) {
        int m = i4 >> 5;
        int q = i4 & 31;
        int k0 = q * 4;
        int gr = row0 + m;
        float4 v = make_float4(0.f, 0.f, 0.f, 0.f);
        if (gr < n_nodes) {
            if (mode) {
                uint2 raw = reinterpret_cast<const uint2*>(g_AGGh)[(size_t)gr * 32 + q];
                v = h4_from_u2(raw);
                v.x = fmaxf(v.x * sSc[k0 + 0] + sSh[k0 + 0], 0.f);
                v.y = fmaxf(v.y * sSc[k0 + 1] + sSh[k0 + 1], 0.f);
                v.z = fmaxf(v.z * sSc[k0 + 2] + sSh[k0 + 2], 0.f);
                v.w = fmaxf(v.w * sSc[k0 + 3] + sSh[k0 + 3], 0.f);
            } else {
                v = reinterpret_cast<const float4*>(Xin)[(size_t)gr * 32 + q];
            }
        }
        float f[4] = {v.x, v.y, v.z, v.w};
        unsigned short hh[4], ll[4];
#pragma unroll
        for (int j = 0; j < 4; j++) {
            __nv_bfloat16 hi = __float2bfloat16(f[j]);
            __nv_bfloat16 lo = __float2bfloat16(f[j] - __bfloat162float(hi));
            hh[j] = *reinterpret_cast<unsigned short*>(&hi);
            ll[j] = *reinterpret_cast<unsigned short*>(&lo);
        }
        uint2 hp = make_uint2((uint32_t)hh[0] | ((uint32_t)hh[1] << 16),
                              (uint32_t)hh[2] | ((uint32_t)hh[3] << 16));
        uint2 lp = make_uint2((uint32_t)ll[0] | ((uint32_t)ll[1] << 16),
                              (uint32_t)ll[2] | ((uint32_t)ll[3] << 16));
        *reinterpret_cast<uint2*>(&sAh[m * LDS_T + k0]) = hp;
        *reinterpret_cast<uint2*>(&sAl[m * LDS_T + k0]) = lp;
    }
    __syncthreads();

    const int rt = (wid & 3) * 32;
    const int ctb = (wid >> 2) * 64;

    wmma::fragment<wmma::accumulator, 16, 16, 16, float> acc[2][4];
#pragma unroll
    for (int r = 0; r < 2; r++)
#pragma unroll
        for (int c = 0; c < 4; c++) wmma::fill_fragment(acc[r][c], 0.f);

#pragma unroll
    for (int ks = 0; ks < 8; ks++) {
        const int k0 = ks * 16;
        wmma::fragment<wmma::matrix_a, 16, 16, 16, __nv_bfloat16, wmma::row_major> ah[2], al[2];
        wmma::load_matrix_sync(ah[0], &sAh[(rt + 0) * LDS_T + k0], LDS_T);
        wmma::load_matrix_sync(ah[1], &sAh[(rt + 16) * LDS_T + k0], LDS_T);
        wmma::load_matrix_sync(al[0], &sAl[(rt + 0) * LDS_T + k0], LDS_T);
        wmma::load_matrix_sync(al[1], &sAl[(rt + 16) * LDS_T + k0], LDS_T);
#pragma unroll
        for (int c = 0; c < 4; c++) {
            wmma::fragment<wmma::matrix_b, 16, 16, 16, __nv_bfloat16, wmma::row_major> bh, bl;
            wmma::load_matrix_sync(bh, &sBh[k0 * LDS_T + ctb + c * 16], LDS_T);
            wmma::load_matrix_sync(bl, &sBl[k0 * LDS_T + ctb + c * 16], LDS_T);
#pragma unroll
            for (int r = 0; r < 2; r++) {
                wmma::mma_sync(acc[r][c], ah[r], bh, acc[r][c]);
                wmma::mma_sync(acc[r][c], al[r], bh, acc[r][c]);
                wmma::mma_sync(acc[r][c], ah[r], bl, acc[r][c]);
            }
        }
    }

    // epilogue: stage fp32 accs through smem, emit fp16
    __syncthreads();
    float* stage = reinterpret_cast<float*>(sm) + wid * 2048;   // 32x64 floats/warp
#pragma unroll
    for (int r = 0; r < 2; r++)
#pragma unroll
        for (int c = 0; c < 4; c++)
            wmma::store_matrix_sync(&stage[r * 16 * 64 + c * 16], acc[r][c], 64,
                                    wmma::mem_row_major);
    __syncwarp();
#pragma unroll
    for (int it = 0; it < 16; it++) {
        int r  = it * 2 + (lane >> 4);
        int c4 = (lane & 15) * 4;
        float4 v = *reinterpret_cast<const float4*>(&stage[r * 64 + c4]);
        size_t m = (size_t)(row0 + rt + r);
        *reinterpret_cast<uint2*>(&g_Hh[m * FDIM + ctb + c4]) = u2_from_f4(v);
    }
}

// ---------------- gather: AGGh[d] = sum_in Hh[s]*nrm + Hh[d]*dinv^2 + b --------
__device__ __forceinline__ float4 h4_load(const __half* base, int node, int lane) {
    return h4_from_u2(reinterpret_cast<const uint2*>(base + (size_t)node * FDIM)[lane]);
}

__global__ void __launch_bounds__(256)
k_gather(const float* __restrict__ b, int n_nodes) {
    __shared__ float ssum[FDIM];
    __shared__ float ssq[FDIM];
    if (threadIdx.x < FDIM) { ssum[threadIdx.x] = 0.f; ssq[threadIdx.x] = 0.f; }
    __syncthreads();

    const int lane = threadIdx.x & 31;
    const int warp = threadIdx.x >> 5;
    const int nwarps = gridDim.x * 8;
    const float4 b4 = *reinterpret_cast<const float4*>(&b[lane * 4]);
    const __half* H = g_Hh;

    float4 sacc = make_float4(0.f, 0.f, 0.f, 0.f);
    float4 qacc = make_float4(0.f, 0.f, 0.f, 0.f);

    for (int d = blockIdx.x * 8 + warp; d < n_nodes; d += nwarps) {
        const int rs = g_rowptr[d];
        const int re = g_rowptr[d + 1];
        const float di = g_dinv[d];
        const float d2 = di * di;

        float4 h = h4_load(H, d, lane);
        float4 acc = make_float4(h.x * d2 + b4.x, h.y * d2 + b4.y,
                                 h.z * d2 + b4.z, h.w * d2 + b4.w);

        int e0 = rs;
        for (; e0 + 32 <= re; e0 += 32) {
            int   sl = g_csr_src[e0 + lane];
            float nl = g_csr_nrm[e0 + lane];
#pragma unroll
            for (int j = 0; j < 32; j++) {
                int   sj = __shfl_sync(0xffffffffu, sl, j);
                float nj = __shfl_sync(0xffffffffu, nl, j);
                float4 v = h4_load(H, sj, lane);
                acc.x += v.x * nj; acc.y += v.y * nj;
                acc.z += v.z * nj; acc.w += v.w * nj;
            }
        }
        if (e0 < re) {
            int cnt = re - e0;
            int   sl = (lane < cnt) ? g_csr_src[e0 + lane] : 0;
            float nl = (lane < cnt) ? g_csr_nrm[e0 + lane] : 0.f;
            for (int j0 = 0; j0 < cnt; j0 += 8) {
#pragma unroll
                for (int jj = 0; jj < 8; jj++) {
                    int j = j0 + jj;
                    int   sj = __shfl_sync(0xffffffffu, sl, j & 31);
                    float nj = __shfl_sync(0xffffffffu, nl, j & 31);
                    if (j < cnt) {
                        float4 v = h4_load(H, sj, lane);
                        acc.x += v.x * nj; acc.y += v.y * nj;
                        acc.z += v.z * nj; acc.w += v.w * nj;
                    }
                }
            }
        }

        reinterpret_cast<uint2*>(g_AGGh)[(size_t)d * 32 + lane] = u2_from_f4(acc);
        sacc.x += acc.x; sacc.y += acc.y; sacc.z += acc.z; sacc.w += acc.w;
        qacc.x += acc.x * acc.x; qacc.y += acc.y * acc.y;
        qacc.z += acc.z * acc.z; qacc.w += acc.w * acc.w;
    }

    int c = lane * 4;
    atomicAdd(&ssum[c + 0], sacc.x); atomicAdd(&ssum[c + 1], sacc.y);
    atomicAdd(&ssum[c + 2], sacc.z); atomicAdd(&ssum[c + 3], sacc.w);
    atomicAdd(&ssq[c + 0], qacc.x);  atomicAdd(&ssq[c + 1], qacc.y);
    atomicAdd(&ssq[c + 2], qacc.z);  atomicAdd(&ssq[c + 3], qacc.w);
    __syncthreads();
    if (threadIdx.x < FDIM) {
        atomicAdd(&g_stats[threadIdx.x], ssum[threadIdx.x]);
        atomicAdd(&g_stats[FDIM + threadIdx.x], ssq[threadIdx.x]);
    }
}

// ---------------- BN finalize (self-resetting stats) ---------------------------
__global__ void k_bnfin(const float* __restrict__ gma, const float* __restrict__ bta,
                        int n_nodes) {
    int c = threadIdx.x;
    float inv_n = 1.0f / (float)n_nodes;
    float mu = g_stats[c] * inv_n;
    float var = g_stats[FDIM + c] * inv_n - mu * mu;
    float rstd = rsqrtf(var + BN_EPS);
    float sc = rstd * gma[c];
    g_scale[c] = sc;
    g_shift[c] = bta[c] - mu * sc;
    g_stats[c] = 0.f;            // reset for next layer / next call
    g_stats[FDIM + c] = 0.f;
}

// ---------------- pool with fused BN+ReLU (warp per node) ----------------------
__global__ void __launch_bounds__(256)
k_pool(const int* __restrict__ batch, int n_nodes) {
    int w = (blockIdx.x * blockDim.x + threadIdx.x) >> 5;
    int lane = threadIdx.x & 31;
    if (w >= n_nodes) return;
    int g = batch[w];
    int c = lane * 4;
    float4 v = h4_from_u2(reinterpret_cast<const uint2*>(g_AGGh)[(size_t)w * 32 + lane]);
    float4 sc = *reinterpret_cast<const float4*>(&g_scale[c]);
    float4 sh = *reinterpret_cast<const float4*>(&g_shift[c]);
    v.x = fmaxf(v.x * sc.x + sh.x, 0.f);
    v.y = fmaxf(v.y * sc.y + sh.y, 0.f);
    v.z = fmaxf(v.z * sc.z + sh.z, 0.f);
    v.w = fmaxf(v.w * sc.w + sh.w, 0.f);
    float* p = &g_pool[(size_t)g * FDIM + c];
    red_add_f32(p + 0, v.x);
    red_add_f32(p + 1, v.y);
    red_add_f32(p + 2, v.z);
    red_add_f32(p + 3, v.w);
    if (lane == 0) atomicAdd(&g_cnt[g], 1.0f);
}

// ---------------- final FC ------------------------------------------------------
__global__ void __launch_bounds__(256)
k_fc(const float* __restrict__ fcW, const float* __restrict__ fcb,
     float* __restrict__ out, int n_graphs) {
    __shared__ float sW[FDIM * 64];
    for (int l = threadIdx.x; l < FDIM * 64; l += 256) sW[l] = fcW[l];
    __syncthreads();
    int g = blockIdx.x * 4 + (threadIdx.x >> 6);
    int c = threadIdx.x & 63;
    if (g >= n_graphs) return;
    float inv = 1.0f / fmaxf(g_cnt[g], 1.0f);
    float acc = 0.f;
#pragma unroll 16
    for (int k = 0; k < FDIM; k++) acc += g_pool[(size_t)g * FDIM + k] * sW[k * 64 + c];
    out[(size_t)g * 64 + c] = acc * inv + fcb[c];
}

// ---------------- launch ---------------------------------------------------------
extern "C" void kernel_launch(void* const* d_in, const int* in_sizes, int n_in,
                              void* d_out, int out_size) {
    const float* x     = (const float*)d_in[0];
    const int*   ei    = (const int*)d_in[1];
    const int*   batch = (const int*)d_in[2];
    const float* W1 = (const float*)d_in[3];
    const float* b1 = (const float*)d_in[4];
    const float* g1 = (const float*)d_in[5];
    const float* be1 = (const float*)d_in[6];
    const float* W2 = (const float*)d_in[7];
    const float* b2 = (const float*)d_in[8];
    const float* g2 = (const float*)d_in[9];
    const float* be2 = (const float*)d_in[10];
    const float* W3 = (const float*)d_in[11];
    const float* b3 = (const float*)d_in[12];
    const float* g3 = (const float*)d_in[13];
    const float* be3 = (const float*)d_in[14];
    const float* fcW = (const float*)d_in[15];
    const float* fcb = (const float*)d_in[16];
    float* out = (float*)d_out;

    const int n_nodes  = in_sizes[0] / FDIM;
    const int n_edges  = in_sizes[1] / 2;
    const int n_graphs = out_size / 64;
    const int* src = ei;
    const int* dst = ei + n_edges;
    const int nblocks = (n_nodes + SCAN_B - 1) / SCAN_B;

    static cudaStream_t s2 = nullptr;
    static cudaEvent_t evF = nullptr, evJ = nullptr;
    if (!s2) {
        cudaFuncSetAttribute(k_gemm_wm, cudaFuncAttributeMaxDynamicSharedMemorySize,
                             SMEM_WM);
        cudaStreamCreateWithFlags(&s2, cudaStreamNonBlocking);
        cudaEventCreateWithFlags(&evF, cudaEventDisableTiming);
        cudaEventCreateWithFlags(&evJ, cudaEventDisableTiming);
    }

    // ---- init (main stream) ----
    {
        int work = n_graphs * FDIM;
        if (n_nodes > work) work = n_nodes;
        k_zero<<<(work + 255) / 256, 256>>>(n_nodes, n_graphs);
    }

    // ---- fork: CSR build on s2, concurrent with wsplit + gemm0 ----
    cudaEventRecord(evF, 0);
    cudaStreamWaitEvent(s2, evF, 0);
    k_deg<<<(n_edges + 255) / 256, 256, 0, s2>>>(dst, n_edges);
    k_dinv<<<(n_nodes + 255) / 256, 256, 0, s2>>>(n_nodes);
    k_bsum<<<nblocks, SCAN_B, 0, s2>>>(n_nodes);
    k_bscan<<<1, MAX_BLK, 0, s2>>>(nblocks);
    k_scanfin<<<nblocks, SCAN_B, 0, s2>>>(n_nodes);
    k_fill<<<(n_edges + 255) / 256, 256, 0, s2>>>(src, dst, n_edges);
    cudaEventRecord(evJ, s2);

    const int gemm_grid   = (n_nodes + 127) / 128;
    const int gather_grid = 1184;

    k_wsplit<<<3, 256>>>(W1, W2, W3);
    k_gemm_wm<<<gemm_grid, 256, SMEM_WM>>>(x, 0, 0, n_nodes);  // layer 0 GEMM

    cudaStreamWaitEvent(0, evJ, 0);   // join: gather needs CSR

    const float* bs[3]  = {b1, b2, b3};
    const float* gs[3]  = {g1, g2, g3};
    const float* bes[3] = {be1, be2, be3};

    for (int layer = 0; layer < 3; layer++) {
        if (layer > 0)
            k_gemm_wm<<<gemm_grid, 256, SMEM_WM>>>(nullptr, 1, layer, n_nodes);
        k_gather<<<gather_grid, 256>>>(bs[layer], n_nodes);
        k_bnfin<<<1, 128>>>(gs[layer], bes[layer], n_nodes);
    }

    k_pool<<<(n_nodes * 32 + 255) / 256, 256>>>(batch, n_nodes);
    k_fc<<<(n_graphs + 3) / 4, 256>>>(fcW, fcb, out, n_graphs);
}

// round 15
// speedup vs baseline: 3.9058x; 1.2387x over previous
#include <cuda_runtime.h>
#include <cuda_bf16.h>
#include <cuda_fp16.h>
#include <mma.h>
#include <cstdint>

using namespace nvcuda;

#define MAX_N 100000
#define MAX_E 1600000
#define MAX_G 4096
#define FDIM 128
#define BN_EPS 1e-5f
#define SCAN_B 1024
#define MAX_BLK 128
#define LDS_T 136   // smem row stride in half elements

// ---------------- scratch (device globals; no allocation allowed) -------------
__device__ __half g_Hh[(size_t)(MAX_N + 128) * FDIM];   // fp16 H (padded tiles)
__device__ __half g_AGGh[(size_t)MAX_N * FDIM];         // fp16 AGG
__device__ float g_dinv[MAX_N];
__device__ int   g_deg[MAX_N];
__device__ int   g_rowptr[MAX_N + 1];
__device__ int   g_cursor[MAX_N];
__device__ int   g_bsum[MAX_BLK];
__device__ int   g_boff[MAX_BLK];
__device__ int   g_csr_src[MAX_E];
__device__ float g_csr_nrm[MAX_E];
__device__ float g_stats[2 * FDIM];
__device__ float g_scale[FDIM];
__device__ float g_shift[FDIM];
__device__ float g_pool[(size_t)MAX_G * FDIM];
__device__ float g_cnt[MAX_G];
// W fp16 hi/lo images, plain row-major [k][n]
__device__ __align__(16) __half g_Bimg[3][2][FDIM * FDIM];

// ---------------- helpers -----------------------------------------------------
__device__ __forceinline__ void red_add_f32(float* p, float v) {
    asm volatile("red.global.add.f32 [%0], %1;" :: "l"(p), "f"(v) : "memory");
}
__device__ __forceinline__ float4 h4_from_u2(uint2 raw) {
    __half2 p0 = *reinterpret_cast<__half2*>(&raw.x);
    __half2 p1 = *reinterpret_cast<__half2*>(&raw.y);
    float2 f0 = __half22float2(p0);
    float2 f1 = __half22float2(p1);
    return make_float4(f0.x, f0.y, f1.x, f1.y);
}
__device__ __forceinline__ uint2 u2_from_f4(float4 v) {
    __half2 h0 = __floats2half2_rn(v.x, v.y);
    __half2 h1 = __floats2half2_rn(v.z, v.w);
    return make_uint2(*reinterpret_cast<uint32_t*>(&h0),
                      *reinterpret_cast<uint32_t*>(&h1));
}

// ---------------- init ----------------------------------------------------------
__global__ void k_zero(int n_nodes, int n_graphs) {
    int i = blockIdx.x * blockDim.x + threadIdx.x;
    if (i < n_nodes) g_deg[i] = 0;
    if (i < n_graphs * FDIM) g_pool[i] = 0.f;
    if (i < n_graphs) g_cnt[i] = 0.f;
    if (i < 2 * FDIM) g_stats[i] = 0.f;
}
__global__ void k_deg(const int* __restrict__ dst, int n_edges) {
    int e = blockIdx.x * blockDim.x + threadIdx.x;
    if (e < n_edges) atomicAdd(&g_deg[dst[e]], 1);
}
__global__ void k_dinv(int n_nodes) {
    int i = blockIdx.x * blockDim.x + threadIdx.x;
    if (i < n_nodes) g_dinv[i] = rsqrtf((float)g_deg[i] + 1.0f);
}

// ---------------- W split: fp16 hi/lo, row-major [k][n] ------------------------
__global__ void k_wsplit(const float* __restrict__ W0, const float* __restrict__ W1,
                         const float* __restrict__ W2) {
    const float* W = (blockIdx.x == 0) ? W0 : (blockIdx.x == 1) ? W1 : W2;
    __half* bh = g_Bimg[blockIdx.x][0];
    __half* bl = g_Bimg[blockIdx.x][1];
    for (int idx = threadIdx.x; idx < FDIM * FDIM; idx += 256) {
        float w = W[idx];
        __half hi = __float2half_rn(w);
        __half lo = __float2half_rn(w - __half2float(hi));
        bh[idx] = hi;
        bl[idx] = lo;
    }
}

// ---------------- parallel scan --------------------------------------------------
__global__ void __launch_bounds__(SCAN_B)
k_bsum(int n_nodes) {
    int i = blockIdx.x * SCAN_B + threadIdx.x;
    int v = (i < n_nodes) ? g_deg[i] : 0;
    for (int off = 16; off > 0; off >>= 1) v += __shfl_down_sync(0xffffffffu, v, off);
    __shared__ int ws[32];
    int lane = threadIdx.x & 31, w = threadIdx.x >> 5;
    if (lane == 0) ws[w] = v;
    __syncthreads();
    if (w == 0) {
        int s = ws[lane];
        for (int off = 16; off > 0; off >>= 1) s += __shfl_down_sync(0xffffffffu, s, off);
        if (lane == 0) g_bsum[blockIdx.x] = s;
    }
}
__global__ void k_bscan(int nblocks) {
    __shared__ int s[MAX_BLK];
    int tid = threadIdx.x;
    int v = (tid < nblocks) ? g_bsum[tid] : 0;
    s[tid] = v;
    __syncthreads();
#pragma unroll
    for (int off = 1; off < MAX_BLK; off <<= 1) {
        int t = (tid >= off) ? s[tid - off] : 0;
        __syncthreads();
        s[tid] += t;
        __syncthreads();
    }
    g_boff[tid] = (tid > 0) ? s[tid - 1] : 0;
}
__global__ void __launch_bounds__(SCAN_B)
k_scanfin(int n_nodes) {
    int i = blockIdx.x * SCAN_B + threadIdx.x;
    int v = (i < n_nodes) ? g_deg[i] : 0;
    int lane = threadIdx.x & 31, w = threadIdx.x >> 5;
    int x = v;
#pragma unroll
    for (int off = 1; off < 32; off <<= 1) {
        int t = __shfl_up_sync(0xffffffffu, x, off);
        if (lane >= off) x += t;
    }
    __shared__ int ws[32];
    if (lane == 31) ws[w] = x;
    __syncthreads();
    if (w == 0) {
        int s = ws[lane];
#pragma unroll
        for (int off = 1; off < 32; off <<= 1) {
            int t = __shfl_up_sync(0xffffffffu, s, off);
            if (lane >= off) s += t;
        }
        ws[lane] = s;
    }
    __syncthreads();
    int incl = x + ((w > 0) ? ws[w - 1] : 0) + g_boff[blockIdx.x];
    if (i < n_nodes) {
        g_rowptr[i + 1] = incl;
        g_cursor[i] = incl - v;
    }
    if (i == 0) g_rowptr[0] = 0;
}
__global__ void k_fill(const int* __restrict__ src, const int* __restrict__ dst,
                       int n_edges) {
    int e = blockIdx.x * blockDim.x + threadIdx.x;
    if (e >= n_edges) return;
    int s = src[e];
    int d = dst[e];
    int pos = atomicAdd(&g_cursor[d], 1);
    g_csr_src[pos] = s;
    g_csr_nrm[pos] = g_dinv[s] * g_dinv[d];
}

// ---------------- wmma GEMM: Hh = act(in) @ W (A fp16, B fp16 hi/lo) -----------
// mode 0: in = Xin (fp32). mode 1: in = g_AGGh (fp16) with fused BN+ReLU.
#define SMEM_WM (3 * 128 * LDS_T * 2)   // bytes = 104448

__global__ void __launch_bounds__(256)
k_gemm_wm(const float* __restrict__ Xin, int mode, int layer, int n_nodes) {
    extern __shared__ __align__(16) __half sm[];
    __half* sA  = sm;
    __half* sBh = sm + 128 * LDS_T;
    __half* sBl = sm + 2 * 128 * LDS_T;
    __shared__ float sSc[FDIM];
    __shared__ float sSh[FDIM];

    const int tid = threadIdx.x;
    const int wid = tid >> 5;
    const int lane = tid & 31;
    const int row0 = blockIdx.x * 128;

    if (mode && tid < FDIM) { sSc[tid] = g_scale[tid]; sSh[tid] = g_shift[tid]; }

    // load B hi/lo (row-major [k][n]) into padded smem
    {
        const uint4* bh = reinterpret_cast<const uint4*>(g_Bimg[layer][0]);
        const uint4* bl = reinterpret_cast<const uint4*>(g_Bimg[layer][1]);
        for (int i = tid; i < FDIM * FDIM / 8; i += 256) {
            int r = i >> 4;
            int c8 = (i & 15) * 8;
            *reinterpret_cast<uint4*>(&sBh[r * LDS_T + c8]) = bh[i];
            *reinterpret_cast<uint4*>(&sBl[r * LDS_T + c8]) = bl[i];
        }
    }
    if (mode) __syncthreads();

    // load + (BN+ReLU) A tile -> fp16
    for (int i4 = tid; i4 < 4096; i4 += 256) {
        int m = i4 >> 5;
        int q = i4 & 31;
        int k0 = q * 4;
        int gr = row0 + m;
        float4 v = make_float4(0.f, 0.f, 0.f, 0.f);
        if (gr < n_nodes) {
            if (mode) {
                uint2 raw = reinterpret_cast<const uint2*>(g_AGGh)[(size_t)gr * 32 + q];
                v = h4_from_u2(raw);
                v.x = fmaxf(v.x * sSc[k0 + 0] + sSh[k0 + 0], 0.f);
                v.y = fmaxf(v.y * sSc[k0 + 1] + sSh[k0 + 1], 0.f);
                v.z = fmaxf(v.z * sSc[k0 + 2] + sSh[k0 + 2], 0.f);
                v.w = fmaxf(v.w * sSc[k0 + 3] + sSh[k0 + 3], 0.f);
            } else {
                v = reinterpret_cast<const float4*>(Xin)[(size_t)gr * 32 + q];
            }
        }
        *reinterpret_cast<uint2*>(&sA[m * LDS_T + k0]) = u2_from_f4(v);
    }
    __syncthreads();

    const int rt = (wid & 3) * 32;
    const int ctb = (wid >> 2) * 64;

    wmma::fragment<wmma::accumulator, 16, 16, 16, float> acc[2][4];
#pragma unroll
    for (int r = 0; r < 2; r++)
#pragma unroll
        for (int c = 0; c < 4; c++) wmma::fill_fragment(acc[r][c], 0.f);

#pragma unroll
    for (int ks = 0; ks < 8; ks++) {
        const int k0 = ks * 16;
        wmma::fragment<wmma::matrix_a, 16, 16, 16, __half, wmma::row_major> a[2];
        wmma::load_matrix_sync(a[0], &sA[(rt + 0) * LDS_T + k0], LDS_T);
        wmma::load_matrix_sync(a[1], &sA[(rt + 16) * LDS_T + k0], LDS_T);
#pragma unroll
        for (int c = 0; c < 4; c++) {
            wmma::fragment<wmma::matrix_b, 16, 16, 16, __half, wmma::row_major> bh, bl;
            wmma::load_matrix_sync(bh, &sBh[k0 * LDS_T + ctb + c * 16], LDS_T);
            wmma::load_matrix_sync(bl, &sBl[k0 * LDS_T + ctb + c * 16], LDS_T);
#pragma unroll
            for (int r = 0; r < 2; r++) {
                wmma::mma_sync(acc[r][c], a[r], bh, acc[r][c]);
                wmma::mma_sync(acc[r][c], a[r], bl, acc[r][c]);
            }
        }
    }

    // epilogue: stage fp32 accs through smem, emit fp16
    __syncthreads();
    float* stage = reinterpret_cast<float*>(sm) + wid * 2048;   // 32x64 floats/warp
#pragma unroll
    for (int r = 0; r < 2; r++)
#pragma unroll
        for (int c = 0; c < 4; c++)
            wmma::store_matrix_sync(&stage[r * 16 * 64 + c * 16], acc[r][c], 64,
                                    wmma::mem_row_major);
    __syncwarp();
#pragma unroll
    for (int it = 0; it < 16; it++) {
        int r  = it * 2 + (lane >> 4);
        int c4 = (lane & 15) * 4;
        float4 v = *reinterpret_cast<const float4*>(&stage[r * 64 + c4]);
        size_t m = (size_t)(row0 + rt + r);
        *reinterpret_cast<uint2*>(&g_Hh[m * FDIM + ctb + c4]) = u2_from_f4(v);
    }
}

// ---------------- gather: AGGh[d] = sum_in Hh[s]*nrm + Hh[d]*dinv^2 + b --------
__device__ __forceinline__ float4 h4_load(const __half* base, int node, int lane) {
    return h4_from_u2(reinterpret_cast<const uint2*>(base + (size_t)node * FDIM)[lane]);
}

__global__ void __launch_bounds__(256)
k_gather(const float* __restrict__ b, int n_nodes) {
    __shared__ float ssum[FDIM];
    __shared__ float ssq[FDIM];
    if (threadIdx.x < FDIM) { ssum[threadIdx.x] = 0.f; ssq[threadIdx.x] = 0.f; }
    __syncthreads();

    const int lane = threadIdx.x & 31;
    const int warp = threadIdx.x >> 5;
    const int nwarps = gridDim.x * 8;
    const float4 b4 = *reinterpret_cast<const float4*>(&b[lane * 4]);
    const __half* H = g_Hh;

    float4 sacc = make_float4(0.f, 0.f, 0.f, 0.f);
    float4 qacc = make_float4(0.f, 0.f, 0.f, 0.f);

    for (int d = blockIdx.x * 8 + warp; d < n_nodes; d += nwarps) {
        const int rs = g_rowptr[d];
        const int re = g_rowptr[d + 1];
        const float di = g_dinv[d];
        const float d2 = di * di;

        float4 h = h4_load(H, d, lane);
        float4 acc = make_float4(h.x * d2 + b4.x, h.y * d2 + b4.y,
                                 h.z * d2 + b4.z, h.w * d2 + b4.w);

        int e0 = rs;
        for (; e0 + 32 <= re; e0 += 32) {
            int   sl = g_csr_src[e0 + lane];
            float nl = g_csr_nrm[e0 + lane];
#pragma unroll
            for (int j = 0; j < 32; j++) {
                int   sj = __shfl_sync(0xffffffffu, sl, j);
                float nj = __shfl_sync(0xffffffffu, nl, j);
                float4 v = h4_load(H, sj, lane);
                acc.x += v.x * nj; acc.y += v.y * nj;
                acc.z += v.z * nj; acc.w += v.w * nj;
            }
        }
        if (e0 < re) {
            int cnt = re - e0;
            int   sl = (lane < cnt) ? g_csr_src[e0 + lane] : 0;
            float nl = (lane < cnt) ? g_csr_nrm[e0 + lane] : 0.f;
            for (int j0 = 0; j0 < cnt; j0 += 8) {
#pragma unroll
                for (int jj = 0; jj < 8; jj++) {
                    int j = j0 + jj;
                    int   sj = __shfl_sync(0xffffffffu, sl, j & 31);
                    float nj = __shfl_sync(0xffffffffu, nl, j & 31);
                    if (j < cnt) {
                        float4 v = h4_load(H, sj, lane);
                        acc.x += v.x * nj; acc.y += v.y * nj;
                        acc.z += v.z * nj; acc.w += v.w * nj;
                    }
                }
            }
        }

        reinterpret_cast<uint2*>(g_AGGh)[(size_t)d * 32 + lane] = u2_from_f4(acc);
        sacc.x += acc.x; sacc.y += acc.y; sacc.z += acc.z; sacc.w += acc.w;
        qacc.x += acc.x * acc.x; qacc.y += acc.y * acc.y;
        qacc.z += acc.z * acc.z; qacc.w += acc.w * acc.w;
    }

    int c = lane * 4;
    atomicAdd(&ssum[c + 0], sacc.x); atomicAdd(&ssum[c + 1], sacc.y);
    atomicAdd(&ssum[c + 2], sacc.z); atomicAdd(&ssum[c + 3], sacc.w);
    atomicAdd(&ssq[c + 0], qacc.x);  atomicAdd(&ssq[c + 1], qacc.y);
    atomicAdd(&ssq[c + 2], qacc.z);  atomicAdd(&ssq[c + 3], qacc.w);
    __syncthreads();
    if (threadIdx.x < FDIM) {
        atomicAdd(&g_stats[threadIdx.x], ssum[threadIdx.x]);
        atomicAdd(&g_stats[FDIM + threadIdx.x], ssq[threadIdx.x]);
    }
}

// ---------------- BN finalize (self-resetting stats) ---------------------------
__global__ void k_bnfin(const float* __restrict__ gma, const float* __restrict__ bta,
                        int n_nodes) {
    int c = threadIdx.x;
    float inv_n = 1.0f / (float)n_nodes;
    float mu = g_stats[c] * inv_n;
    float var = g_stats[FDIM + c] * inv_n - mu * mu;
    float rstd = rsqrtf(var + BN_EPS);
    float sc = rstd * gma[c];
    g_scale[c] = sc;
    g_shift[c] = bta[c] - mu * sc;
    g_stats[c] = 0.f;
    g_stats[FDIM + c] = 0.f;
}

// ---------------- pool with fused BN+ReLU (warp per node) ----------------------
__global__ void __launch_bounds__(256)
k_pool(const int* __restrict__ batch, int n_nodes) {
    int w = (blockIdx.x * blockDim.x + threadIdx.x) >> 5;
    int lane = threadIdx.x & 31;
    if (w >= n_nodes) return;
    int g = batch[w];
    int c = lane * 4;
    float4 v = h4_from_u2(reinterpret_cast<const uint2*>(g_AGGh)[(size_t)w * 32 + lane]);
    float4 sc = *reinterpret_cast<const float4*>(&g_scale[c]);
    float4 sh = *reinterpret_cast<const float4*>(&g_shift[c]);
    v.x = fmaxf(v.x * sc.x + sh.x, 0.f);
    v.y = fmaxf(v.y * sc.y + sh.y, 0.f);
    v.z = fmaxf(v.z * sc.z + sh.z, 0.f);
    v.w = fmaxf(v.w * sc.w + sh.w, 0.f);
    float* p = &g_pool[(size_t)g * FDIM + c];
    red_add_f32(p + 0, v.x);
    red_add_f32(p + 1, v.y);
    red_add_f32(p + 2, v.z);
    red_add_f32(p + 3, v.w);
    if (lane == 0) atomicAdd(&g_cnt[g], 1.0f);
}

// ---------------- final FC ------------------------------------------------------
__global__ void __launch_bounds__(256)
k_fc(const float* __restrict__ fcW, const float* __restrict__ fcb,
     float* __restrict__ out, int n_graphs) {
    __shared__ float sW[FDIM * 64];
    for (int l = threadIdx.x; l < FDIM * 64; l += 256) sW[l] = fcW[l];
    __syncthreads();
    int g = blockIdx.x * 4 + (threadIdx.x >> 6);
    int c = threadIdx.x & 63;
    if (g >= n_graphs) return;
    float inv = 1.0f / fmaxf(g_cnt[g], 1.0f);
    float acc = 0.f;
#pragma unroll 16
    for (int k = 0; k < FDIM; k++) acc += g_pool[(size_t)g * FDIM + k] * sW[k * 64 + c];
    out[(size_t)g * 64 + c] = acc * inv + fcb[c];
}

// ---------------- launch ---------------------------------------------------------
extern "C" void kernel_launch(void* const* d_in, const int* in_sizes, int n_in,
                              void* d_out, int out_size) {
    const float* x     = (const float*)d_in[0];
    const int*   ei    = (const int*)d_in[1];
    const int*   batch = (const int*)d_in[2];
    const float* W1 = (const float*)d_in[3];
    const float* b1 = (const float*)d_in[4];
    const float* g1 = (const float*)d_in[5];
    const float* be1 = (const float*)d_in[6];
    const float* W2 = (const float*)d_in[7];
    const float* b2 = (const float*)d_in[8];
    const float* g2 = (const float*)d_in[9];
    const float* be2 = (const float*)d_in[10];
    const float* W3 = (const float*)d_in[11];
    const float* b3 = (const float*)d_in[12];
    const float* g3 = (const float*)d_in[13];
    const float* be3 = (const float*)d_in[14];
    const float* fcW = (const float*)d_in[15];
    const float* fcb = (const float*)d_in[16];
    float* out = (float*)d_out;

    const int n_nodes  = in_sizes[0] / FDIM;
    const int n_edges  = in_sizes[1] / 2;
    const int n_graphs = out_size / 64;
    const int* src = ei;
    const int* dst = ei + n_edges;
    const int nblocks = (n_nodes + SCAN_B - 1) / SCAN_B;

    static cudaStream_t s2 = nullptr;
    static cudaEvent_t evF = nullptr, evJ = nullptr;
    if (!s2) {
        cudaFuncSetAttribute(k_gemm_wm, cudaFuncAttributeMaxDynamicSharedMemorySize,
                             SMEM_WM);
        cudaStreamCreateWithFlags(&s2, cudaStreamNonBlocking);
        cudaEventCreateWithFlags(&evF, cudaEventDisableTiming);
        cudaEventCreateWithFlags(&evJ, cudaEventDisableTiming);
    }

    // ---- init (main stream) ----
    {
        int work = n_graphs * FDIM;
        if (n_nodes > work) work = n_nodes;
        k_zero<<<(work + 255) / 256, 256>>>(n_nodes, n_graphs);
    }

    // ---- fork: CSR build on s2, concurrent with wsplit + gemm0 ----
    cudaEventRecord(evF, 0);
    cudaStreamWaitEvent(s2, evF, 0);
    k_deg<<<(n_edges + 255) / 256, 256, 0, s2>>>(dst, n_edges);
    k_dinv<<<(n_nodes + 255) / 256, 256, 0, s2>>>(n_nodes);
    k_bsum<<<nblocks, SCAN_B, 0, s2>>>(n_nodes);
    k_bscan<<<1, MAX_BLK, 0, s2>>>(nblocks);
    k_scanfin<<<nblocks, SCAN_B, 0, s2>>>(n_nodes);
    k_fill<<<(n_edges + 255) / 256, 256, 0, s2>>>(src, dst, n_edges);
    cudaEventRecord(evJ, s2);

    const int gemm_grid   = (n_nodes + 127) / 128;
    const int gather_grid = 1184;

    k_wsplit<<<3, 256>>>(W1, W2, W3);
    k_gemm_wm<<<gemm_grid, 256, SMEM_WM>>>(x, 0, 0, n_nodes);  // layer 0 GEMM

    cudaStreamWaitEvent(0, evJ, 0);   // join: gather needs CSR

    const float* bs[3]  = {b1, b2, b3};
    const float* gs[3]  = {g1, g2, g3};
    const float* bes[3] = {be1, be2, be3};

    for (int layer = 0; layer < 3; layer++) {
        if (layer > 0)
            k_gemm_wm<<<gemm_grid, 256, SMEM_WM>>>(nullptr, 1, layer, n_nodes);
        k_gather<<<gather_grid, 256>>>(bs[layer], n_nodes);
        k_bnfin<<<1, 128>>>(gs[layer], bes[layer], n_nodes);
    }

    k_pool<<<(n_nodes * 32 + 255) / 256, 256>>>(batch, n_nodes);
    k_fc<<<(n_graphs + 3) / 4, 256>>>(fcW, fcb, out, n_graphs);
}

// round 16
// speedup vs baseline: 4.1077x; 1.0517x over previous
#include <cuda_runtime.h>
#include <cuda_bf16.h>
#include <cuda_fp16.h>
#include <mma.h>
#include <cstdint>

using namespace nvcuda;

#define MAX_N 100000
#define MAX_E 1600000
#define MAX_G 4096
#define FDIM 128
#define BN_EPS 1e-5f
#define SCAN_B 1024
#define MAX_BLK 128
#define LDS_T 136   // smem row stride in half elements

// ---------------- scratch (device globals; no allocation allowed) -------------
__device__ __half g_Hh[(size_t)(MAX_N + 128) * FDIM];   // fp16 H (padded tiles)
__device__ __half g_AGGh[(size_t)MAX_N * FDIM];         // fp16 AGG
__device__ float g_dinv[MAX_N];
__device__ int   g_deg[MAX_N];
__device__ int   g_rowptr[MAX_N + 1];
__device__ int   g_cursor[MAX_N];
__device__ int   g_bsum[MAX_BLK];
__device__ int   g_boff[MAX_BLK];
__device__ int   g_csr_src[MAX_E];
__device__ float g_csr_nrm[MAX_E];
__device__ int   g_gcnt[MAX_G];
__device__ int   g_gptr[MAX_G + 1];
__device__ float g_stats[2 * FDIM];
__device__ float g_scale[FDIM];
__device__ float g_shift[FDIM];
__device__ float g_pool[(size_t)MAX_G * FDIM];
// W fp16 hi/lo images, plain row-major [k][n]
__device__ __align__(16) __half g_Bimg[3][2][FDIM * FDIM];

// ---------------- helpers -----------------------------------------------------
__device__ __forceinline__ float4 h4_from_u2(uint2 raw) {
    __half2 p0 = *reinterpret_cast<__half2*>(&raw.x);
    __half2 p1 = *reinterpret_cast<__half2*>(&raw.y);
    float2 f0 = __half22float2(p0);
    float2 f1 = __half22float2(p1);
    return make_float4(f0.x, f0.y, f1.x, f1.y);
}
__device__ __forceinline__ uint2 u2_from_f4(float4 v) {
    __half2 h0 = __floats2half2_rn(v.x, v.y);
    __half2 h1 = __floats2half2_rn(v.z, v.w);
    return make_uint2(*reinterpret_cast<uint32_t*>(&h0),
                      *reinterpret_cast<uint32_t*>(&h1));
}

// ---------------- init ----------------------------------------------------------
__global__ void k_zero(int n_nodes, int n_graphs) {
    int i = blockIdx.x * blockDim.x + threadIdx.x;
    if (i < n_nodes) g_deg[i] = 0;
    if (i < n_graphs) g_gcnt[i] = 0;
    if (i < 2 * FDIM) g_stats[i] = 0.f;
}
__global__ void k_deg(const int* __restrict__ dst, int n_edges) {
    int e = blockIdx.x * blockDim.x + threadIdx.x;
    if (e < n_edges) atomicAdd(&g_deg[dst[e]], 1);
}
__global__ void k_dinv(int n_nodes) {
    int i = blockIdx.x * blockDim.x + threadIdx.x;
    if (i < n_nodes) g_dinv[i] = rsqrtf((float)g_deg[i] + 1.0f);
}
__global__ void k_gcnt(const int* __restrict__ batch, int n_nodes) {
    int i = blockIdx.x * blockDim.x + threadIdx.x;
    if (i < n_nodes) atomicAdd(&g_gcnt[batch[i]], 1);
}
// one-block scan of graph counts -> g_gptr (4096 = 1024 threads x 4)
__global__ void __launch_bounds__(1024)
k_gscan(int n_graphs) {
    __shared__ int s[1024];
    int t = threadIdx.x;
    int base = t * 4;
    int c[4];
#pragma unroll
    for (int j = 0; j < 4; j++)
        c[j] = (base + j < n_graphs) ? g_gcnt[base + j] : 0;
    int tot = c[0] + c[1] + c[2] + c[3];
    s[t] = tot;
    __syncthreads();
#pragma unroll
    for (int off = 1; off < 1024; off <<= 1) {
        int v = (t >= off) ? s[t - off] : 0;
        __syncthreads();
        s[t] += v;
        __syncthreads();
    }
    int off = (t > 0) ? s[t - 1] : 0;
    if (t == 0) g_gptr[0] = 0;
    int run = off;
#pragma unroll
    for (int j = 0; j < 4; j++) {
        run += c[j];
        if (base + j < n_graphs) g_gptr[base + j + 1] = run;
    }
}

// ---------------- W split: fp16 hi/lo, row-major [k][n] ------------------------
__global__ void k_wsplit(const float* __restrict__ W0, const float* __restrict__ W1,
                         const float* __restrict__ W2) {
    const float* W = (blockIdx.x == 0) ? W0 : (blockIdx.x == 1) ? W1 : W2;
    __half* bh = g_Bimg[blockIdx.x][0];
    __half* bl = g_Bimg[blockIdx.x][1];
    for (int idx = threadIdx.x; idx < FDIM * FDIM; idx += 256) {
        float w = W[idx];
        __half hi = __float2half_rn(w);
        __half lo = __float2half_rn(w - __half2float(hi));
        bh[idx] = hi;
        bl[idx] = lo;
    }
}

// ---------------- parallel scan (CSR rowptr) ------------------------------------
__global__ void __launch_bounds__(SCAN_B)
k_bsum(int n_nodes) {
    int i = blockIdx.x * SCAN_B + threadIdx.x;
    int v = (i < n_nodes) ? g_deg[i] : 0;
    for (int off = 16; off > 0; off >>= 1) v += __shfl_down_sync(0xffffffffu, v, off);
    __shared__ int ws[32];
    int lane = threadIdx.x & 31, w = threadIdx.x >> 5;
    if (lane == 0) ws[w] = v;
    __syncthreads();
    if (w == 0) {
        int s = ws[lane];
        for (int off = 16; off > 0; off >>= 1) s += __shfl_down_sync(0xffffffffu, s, off);
        if (lane == 0) g_bsum[blockIdx.x] = s;
    }
}
__global__ void k_bscan(int nblocks) {
    __shared__ int s[MAX_BLK];
    int tid = threadIdx.x;
    int v = (tid < nblocks) ? g_bsum[tid] : 0;
    s[tid] = v;
    __syncthreads();
#pragma unroll
    for (int off = 1; off < MAX_BLK; off <<= 1) {
        int t = (tid >= off) ? s[tid - off] : 0;
        __syncthreads();
        s[tid] += t;
        __syncthreads();
    }
    g_boff[tid] = (tid > 0) ? s[tid - 1] : 0;
}
__global__ void __launch_bounds__(SCAN_B)
k_scanfin(int n_nodes) {
    int i = blockIdx.x * SCAN_B + threadIdx.x;
    int v = (i < n_nodes) ? g_deg[i] : 0;
    int lane = threadIdx.x & 31, w = threadIdx.x >> 5;
    int x = v;
#pragma unroll
    for (int off = 1; off < 32; off <<= 1) {
        int t = __shfl_up_sync(0xffffffffu, x, off);
        if (lane >= off) x += t;
    }
    __shared__ int ws[32];
    if (lane == 31) ws[w] = x;
    __syncthreads();
    if (w == 0) {
        int s = ws[lane];
#pragma unroll
        for (int off = 1; off < 32; off <<= 1) {
            int t = __shfl_up_sync(0xffffffffu, s, off);
            if (lane >= off) s += t;
        }
        ws[lane] = s;
    }
    __syncthreads();
    int incl = x + ((w > 0) ? ws[w - 1] : 0) + g_boff[blockIdx.x];
    if (i < n_nodes) {
        g_rowptr[i + 1] = incl;
        g_cursor[i] = incl - v;
    }
    if (i == 0) g_rowptr[0] = 0;
}
__global__ void k_fill(const int* __restrict__ src, const int* __restrict__ dst,
                       int n_edges) {
    int e = blockIdx.x * blockDim.x + threadIdx.x;
    if (e >= n_edges) return;
    int s = src[e];
    int d = dst[e];
    int pos = atomicAdd(&g_cursor[d], 1);
    g_csr_src[pos] = s;
    g_csr_nrm[pos] = g_dinv[s] * g_dinv[d];
}

// ---------------- wmma GEMM: Hh = act(in) @ W (A fp16, B fp16 hi/lo) -----------
// mode 0: in = Xin (fp32). mode 1: in = g_AGGh (fp16) with fused BN+ReLU.
#define SMEM_WM (3 * 128 * LDS_T * 2)   // bytes = 104448

__global__ void __launch_bounds__(256)
k_gemm_wm(const float* __restrict__ Xin, int mode, int layer, int n_nodes) {
    extern __shared__ __align__(16) __half sm[];
    __half* sA  = sm;
    __half* sBh = sm + 128 * LDS_T;
    __half* sBl = sm + 2 * 128 * LDS_T;
    __shared__ float sSc[FDIM];
    __shared__ float sSh[FDIM];

    const int tid = threadIdx.x;
    const int wid = tid >> 5;
    const int lane = tid & 31;
    const int row0 = blockIdx.x * 128;

    if (mode && tid < FDIM) { sSc[tid] = g_scale[tid]; sSh[tid] = g_shift[tid]; }

    // load B hi/lo (row-major [k][n]) into padded smem
    {
        const uint4* bh = reinterpret_cast<const uint4*>(g_Bimg[layer][0]);
        const uint4* bl = reinterpret_cast<const uint4*>(g_Bimg[layer][1]);
        for (int i = tid; i < FDIM * FDIM / 8; i += 256) {
            int r = i >> 4;
            int c8 = (i & 15) * 8;
            *reinterpret_cast<uint4*>(&sBh[r * LDS_T + c8]) = bh[i];
            *reinterpret_cast<uint4*>(&sBl[r * LDS_T + c8]) = bl[i];
        }
    }
    if (mode) __syncthreads();

    // load + (BN+ReLU) A tile -> fp16
    for (int i4 = tid; i4 < 4096; i4 += 256) {
        int m = i4 >> 5;
        int q = i4 & 31;
        int k0 = q * 4;
        int gr = row0 + m;
        float4 v = make_float4(0.f, 0.f, 0.f, 0.f);
        if (gr < n_nodes) {
            if (mode) {
                uint2 raw = reinterpret_cast<const uint2*>(g_AGGh)[(size_t)gr * 32 + q];
                v = h4_from_u2(raw);
                v.x = fmaxf(v.x * sSc[k0 + 0] + sSh[k0 + 0], 0.f);
                v.y = fmaxf(v.y * sSc[k0 + 1] + sSh[k0 + 1], 0.f);
                v.z = fmaxf(v.z * sSc[k0 + 2] + sSh[k0 + 2], 0.f);
                v.w = fmaxf(v.w * sSc[k0 + 3] + sSh[k0 + 3], 0.f);
            } else {
                v = reinterpret_cast<const float4*>(Xin)[(size_t)gr * 32 + q];
            }
        }
        *reinterpret_cast<uint2*>(&sA[m * LDS_T + k0]) = u2_from_f4(v);
    }
    __syncthreads();

    const int rt = (wid & 3) * 32;
    const int ctb = (wid >> 2) * 64;

    wmma::fragment<wmma::accumulator, 16, 16, 16, float> acc[2][4];
#pragma unroll
    for (int r = 0; r < 2; r++)
#pragma unroll
        for (int c = 0; c < 4; c++) wmma::fill_fragment(acc[r][c], 0.f);

#pragma unroll
    for (int ks = 0; ks < 8; ks++) {
        const int k0 = ks * 16;
        wmma::fragment<wmma::matrix_a, 16, 16, 16, __half, wmma::row_major> a[2];
        wmma::load_matrix_sync(a[0], &sA[(rt + 0) * LDS_T + k0], LDS_T);
        wmma::load_matrix_sync(a[1], &sA[(rt + 16) * LDS_T + k0], LDS_T);
#pragma unroll
        for (int c = 0; c < 4; c++) {
            wmma::fragment<wmma::matrix_b, 16, 16, 16, __half, wmma::row_major> bh, bl;
            wmma::load_matrix_sync(bh, &sBh[k0 * LDS_T + ctb + c * 16], LDS_T);
            wmma::load_matrix_sync(bl, &sBl[k0 * LDS_T + ctb + c * 16], LDS_T);
#pragma unroll
            for (int r = 0; r < 2; r++) {
                wmma::mma_sync(acc[r][c], a[r], bh, acc[r][c]);
                wmma::mma_sync(acc[r][c], a[r], bl, acc[r][c]);
            }
        }
    }

    // epilogue: stage fp32 accs through smem, emit fp16
    __syncthreads();
    float* stage = reinterpret_cast<float*>(sm) + wid * 2048;   // 32x64 floats/warp
#pragma unroll
    for (int r = 0; r < 2; r++)
#pragma unroll
        for (int c = 0; c < 4; c++)
            wmma::store_matrix_sync(&stage[r * 16 * 64 + c * 16], acc[r][c], 64,
                                    wmma::mem_row_major);
    __syncwarp();
#pragma unroll
    for (int it = 0; it < 16; it++) {
        int r  = it * 2 + (lane >> 4);
        int c4 = (lane & 15) * 4;
        float4 v = *reinterpret_cast<const float4*>(&stage[r * 64 + c4]);
        size_t m = (size_t)(row0 + rt + r);
        *reinterpret_cast<uint2*>(&g_Hh[m * FDIM + ctb + c4]) = u2_from_f4(v);
    }
}

// ---------------- gather: AGGh[d] = sum_in Hh[s]*nrm + Hh[d]*dinv^2 + b --------
__device__ __forceinline__ float4 h4_load(const __half* base, int node, int lane) {
    return h4_from_u2(reinterpret_cast<const uint2*>(base + (size_t)node * FDIM)[lane]);
}

__global__ void __launch_bounds__(256)
k_gather(const float* __restrict__ b, int n_nodes) {
    __shared__ float ssum[FDIM];
    __shared__ float ssq[FDIM];
    if (threadIdx.x < FDIM) { ssum[threadIdx.x] = 0.f; ssq[threadIdx.x] = 0.f; }
    __syncthreads();

    const int lane = threadIdx.x & 31;
    const int warp = threadIdx.x >> 5;
    const int nwarps = gridDim.x * 8;
    const float4 b4 = *reinterpret_cast<const float4*>(&b[lane * 4]);
    const __half* H = g_Hh;

    float4 sacc = make_float4(0.f, 0.f, 0.f, 0.f);
    float4 qacc = make_float4(0.f, 0.f, 0.f, 0.f);

    for (int d = blockIdx.x * 8 + warp; d < n_nodes; d += nwarps) {
        const int rs = g_rowptr[d];
        const int re = g_rowptr[d + 1];
        const float di = g_dinv[d];
        const float d2 = di * di;

        float4 h = h4_load(H, d, lane);
        float4 acc = make_float4(h.x * d2 + b4.x, h.y * d2 + b4.y,
                                 h.z * d2 + b4.z, h.w * d2 + b4.w);

        int e0 = rs;
        for (; e0 + 32 <= re; e0 += 32) {
            int   sl = g_csr_src[e0 + lane];
            float nl = g_csr_nrm[e0 + lane];
#pragma unroll
            for (int j = 0; j < 32; j++) {
                int   sj = __shfl_sync(0xffffffffu, sl, j);
                float nj = __shfl_sync(0xffffffffu, nl, j);
                float4 v = h4_load(H, sj, lane);
                acc.x += v.x * nj; acc.y += v.y * nj;
                acc.z += v.z * nj; acc.w += v.w * nj;
            }
        }
        if (e0 < re) {
            int cnt = re - e0;
            int   sl = (lane < cnt) ? g_csr_src[e0 + lane] : 0;
            float nl = (lane < cnt) ? g_csr_nrm[e0 + lane] : 0.f;
            for (int j0 = 0; j0 < cnt; j0 += 8) {
#pragma unroll
                for (int jj = 0; jj < 8; jj++) {
                    int j = j0 + jj;
                    int   sj = __shfl_sync(0xffffffffu, sl, j & 31);
                    float nj = __shfl_sync(0xffffffffu, nl, j & 31);
                    if (j < cnt) {
                        float4 v = h4_load(H, sj, lane);
                        acc.x += v.x * nj; acc.y += v.y * nj;
                        acc.z += v.z * nj; acc.w += v.w * nj;
                    }
                }
            }
        }

        reinterpret_cast<uint2*>(g_AGGh)[(size_t)d * 32 + lane] = u2_from_f4(acc);
        sacc.x += acc.x; sacc.y += acc.y; sacc.z += acc.z; sacc.w += acc.w;
        qacc.x += acc.x * acc.x; qacc.y += acc.y * acc.y;
        qacc.z += acc.z * acc.z; qacc.w += acc.w * acc.w;
    }

    int c = lane * 4;
    atomicAdd(&ssum[c + 0], sacc.x); atomicAdd(&ssum[c + 1], sacc.y);
    atomicAdd(&ssum[c + 2], sacc.z); atomicAdd(&ssum[c + 3], sacc.w);
    atomicAdd(&ssq[c + 0], qacc.x);  atomicAdd(&ssq[c + 1], qacc.y);
    atomicAdd(&ssq[c + 2], qacc.z);  atomicAdd(&ssq[c + 3], qacc.w);
    __syncthreads();
    if (threadIdx.x < FDIM) {
        atomicAdd(&g_stats[threadIdx.x], ssum[threadIdx.x]);
        atomicAdd(&g_stats[FDIM + threadIdx.x], ssq[threadIdx.x]);
    }
}

// ---------------- BN finalize (self-resetting stats) ---------------------------
__global__ void k_bnfin(const float* __restrict__ gma, const float* __restrict__ bta,
                        int n_nodes) {
    int c = threadIdx.x;
    float inv_n = 1.0f / (float)n_nodes;
    float mu = g_stats[c] * inv_n;
    float var = g_stats[FDIM + c] * inv_n - mu * mu;
    float rstd = rsqrtf(var + BN_EPS);
    float sc = rstd * gma[c];
    g_scale[c] = sc;
    g_shift[c] = bta[c] - mu * sc;
    g_stats[c] = 0.f;
    g_stats[FDIM + c] = 0.f;
}

// ---------------- pool: warp per graph, atomic-free (batch sorted) -------------
__global__ void __launch_bounds__(256)
k_pool2(int n_graphs) {
    int g = blockIdx.x * 8 + (threadIdx.x >> 5);
    int lane = threadIdx.x & 31;
    if (g >= n_graphs) return;
    int s = g_gptr[g], e = g_gptr[g + 1];
    int c = lane * 4;
    float4 sc = *reinterpret_cast<const float4*>(&g_scale[c]);
    float4 sh = *reinterpret_cast<const float4*>(&g_shift[c]);
    float4 acc = make_float4(0.f, 0.f, 0.f, 0.f);
    for (int n = s; n < e; n++) {
        float4 v = h4_from_u2(reinterpret_cast<const uint2*>(g_AGGh)[(size_t)n * 32 + lane]);
        acc.x += fmaxf(v.x * sc.x + sh.x, 0.f);
        acc.y += fmaxf(v.y * sc.y + sh.y, 0.f);
        acc.z += fmaxf(v.z * sc.z + sh.z, 0.f);
        acc.w += fmaxf(v.w * sc.w + sh.w, 0.f);
    }
    float inv = 1.0f / fmaxf((float)(e - s), 1.0f);
    float4 o = make_float4(acc.x * inv, acc.y * inv, acc.z * inv, acc.w * inv);
    *reinterpret_cast<float4*>(&g_pool[(size_t)g * FDIM + c]) = o;
}

// ---------------- final FC ------------------------------------------------------
__global__ void __launch_bounds__(256)
k_fc(const float* __restrict__ fcW, const float* __restrict__ fcb,
     float* __restrict__ out, int n_graphs) {
    __shared__ float sW[FDIM * 64];
    for (int l = threadIdx.x; l < FDIM * 64; l += 256) sW[l] = fcW[l];
    __syncthreads();
    int g = blockIdx.x * 4 + (threadIdx.x >> 6);
    int c = threadIdx.x & 63;
    if (g >= n_graphs) return;
    float acc = 0.f;
#pragma unroll 16
    for (int k = 0; k < FDIM; k++) acc += g_pool[(size_t)g * FDIM + k] * sW[k * 64 + c];
    out[(size_t)g * 64 + c] = acc + fcb[c];
}

// ---------------- launch ---------------------------------------------------------
extern "C" void kernel_launch(void* const* d_in, const int* in_sizes, int n_in,
                              void* d_out, int out_size) {
    const float* x     = (const float*)d_in[0];
    const int*   ei    = (const int*)d_in[1];
    const int*   batch = (const int*)d_in[2];
    const float* W1 = (const float*)d_in[3];
    const float* b1 = (const float*)d_in[4];
    const float* g1 = (const float*)d_in[5];
    const float* be1 = (const float*)d_in[6];
    const float* W2 = (const float*)d_in[7];
    const float* b2 = (const float*)d_in[8];
    const float* g2 = (const float*)d_in[9];
    const float* be2 = (const float*)d_in[10];
    const float* W3 = (const float*)d_in[11];
    const float* b3 = (const float*)d_in[12];
    const float* g3 = (const float*)d_in[13];
    const float* be3 = (const float*)d_in[14];
    const float* fcW = (const float*)d_in[15];
    const float* fcb = (const float*)d_in[16];
    float* out = (float*)d_out;

    const int n_nodes  = in_sizes[0] / FDIM;
    const int n_edges  = in_sizes[1] / 2;
    const int n_graphs = out_size / 64;
    const int* src = ei;
    const int* dst = ei + n_edges;
    const int nblocks = (n_nodes + SCAN_B - 1) / SCAN_B;

    static cudaStream_t s2 = nullptr;
    static cudaEvent_t evF = nullptr, evJ = nullptr;
    if (!s2) {
        cudaFuncSetAttribute(k_gemm_wm, cudaFuncAttributeMaxDynamicSharedMemorySize,
                             SMEM_WM);
        cudaStreamCreateWithFlags(&s2, cudaStreamNonBlocking);
        cudaEventCreateWithFlags(&evF, cudaEventDisableTiming);
        cudaEventCreateWithFlags(&evJ, cudaEventDisableTiming);
    }

    // ---- init (main stream) ----
    {
        int work = n_nodes;
        if (n_graphs > work) work = n_graphs;
        k_zero<<<(work + 255) / 256, 256>>>(n_nodes, n_graphs);
    }

    // ---- fork: CSR + graph-ptr build on s2, concurrent with wsplit + gemm0 ----
    cudaEventRecord(evF, 0);
    cudaStreamWaitEvent(s2, evF, 0);
    k_deg<<<(n_edges + 255) / 256, 256, 0, s2>>>(dst, n_edges);
    k_dinv<<<(n_nodes + 255) / 256, 256, 0, s2>>>(n_nodes);
    k_bsum<<<nblocks, SCAN_B, 0, s2>>>(n_nodes);
    k_bscan<<<1, MAX_BLK, 0, s2>>>(nblocks);
    k_scanfin<<<nblocks, SCAN_B, 0, s2>>>(n_nodes);
    k_fill<<<(n_edges + 255) / 256, 256, 0, s2>>>(src, dst, n_edges);
    k_gcnt<<<(n_nodes + 255) / 256, 256, 0, s2>>>(batch, n_nodes);
    k_gscan<<<1, 1024, 0, s2>>>(n_graphs);
    cudaEventRecord(evJ, s2);

    const int gemm_grid   = (n_nodes + 127) / 128;
    const int gather_grid = 1184;

    k_wsplit<<<3, 256>>>(W1, W2, W3);
    k_gemm_wm<<<gemm_grid, 256, SMEM_WM>>>(x, 0, 0, n_nodes);  // layer 0 GEMM

    cudaStreamWaitEvent(0, evJ, 0);   // join: gather needs CSR

    const float* bs[3]  = {b1, b2, b3};
    const float* gs[3]  = {g1, g2, g3};
    const float* bes[3] = {be1, be2, be3};

    for (int layer = 0; layer < 3; layer++) {
        if (layer > 0)
            k_gemm_wm<<<gemm_grid, 256, SMEM_WM>>>(nullptr, 1, layer, n_nodes);
        k_gather<<<gather_grid, 256>>>(bs[layer], n_nodes);
        k_bnfin<<<1, 128>>>(gs[layer], bes[layer], n_nodes);
    }

    k_pool2<<<(n_graphs + 7) / 8, 256>>>(n_graphs);
    k_fc<<<(n_graphs + 3) / 4, 256>>>(fcW, fcb, out, n_graphs);
}

// round 17
// speedup vs baseline: 4.2514x; 1.0350x over previous
#include <cuda_runtime.h>
#include <cuda_bf16.h>
#include <cuda_fp16.h>
#include <mma.h>
#include <cstdint>

using namespace nvcuda;

#define MAX_N 100000
#define MAX_E 1600000
#define MAX_G 4096
#define FDIM 128
#define BN_EPS 1e-5f
#define SCAN_B 1024
#define MAX_BLK 128
#define LDS_T 136   // smem row stride in half elements

// ---------------- scratch (device globals; no allocation allowed) -------------
__device__ __half g_Hh[(size_t)(MAX_N + 128) * FDIM];   // fp16 H (padded tiles)
__device__ __half g_AGGh[(size_t)MAX_N * FDIM];         // fp16 AGG
__device__ float g_dinv[MAX_N];
__device__ int   g_deg[MAX_N];
__device__ int   g_rowptr[MAX_N + 1];
__device__ int   g_cursor[MAX_N];
__device__ int   g_bsum[MAX_BLK];
__device__ int   g_boff[MAX_BLK];
__device__ int2  g_csr[MAX_E];              // packed (src, nrm-bits)
__device__ int   g_gcnt[MAX_G];
__device__ int   g_gptr[MAX_G + 1];
__device__ float g_stats3[3][2 * FDIM];     // per-layer sum/sumsq
__device__ float g_pool[(size_t)MAX_G * FDIM];
// W fp16 hi/lo images, plain row-major [k][n]
__device__ __align__(16) __half g_Bimg[3][2][FDIM * FDIM];

// ---------------- helpers -----------------------------------------------------
__device__ __forceinline__ float4 h4_from_u2(uint2 raw) {
    __half2 p0 = *reinterpret_cast<__half2*>(&raw.x);
    __half2 p1 = *reinterpret_cast<__half2*>(&raw.y);
    float2 f0 = __half22float2(p0);
    float2 f1 = __half22float2(p1);
    return make_float4(f0.x, f0.y, f1.x, f1.y);
}
__device__ __forceinline__ uint2 u2_from_f4(float4 v) {
    __half2 h0 = __floats2half2_rn(v.x, v.y);
    __half2 h1 = __floats2half2_rn(v.z, v.w);
    return make_uint2(*reinterpret_cast<uint32_t*>(&h0),
                      *reinterpret_cast<uint32_t*>(&h1));
}
__device__ __forceinline__ float4 h4_load(const __half* base, int node, int lane) {
    return h4_from_u2(reinterpret_cast<const uint2*>(base + (size_t)node * FDIM)[lane]);
}

// ---------------- init ----------------------------------------------------------
__global__ void k_zero(int n_nodes, int n_graphs) {
    int i = blockIdx.x * blockDim.x + threadIdx.x;
    if (i < n_nodes) g_deg[i] = 0;
    if (i < n_graphs) g_gcnt[i] = 0;
    if (i < 3 * 2 * FDIM) (&g_stats3[0][0])[i] = 0.f;
}
__global__ void k_deg(const int* __restrict__ dst, int n_edges) {
    int e = blockIdx.x * blockDim.x + threadIdx.x;
    if (e < n_edges) atomicAdd(&g_deg[dst[e]], 1);
}
__global__ void k_dinv(int n_nodes) {
    int i = blockIdx.x * blockDim.x + threadIdx.x;
    if (i < n_nodes) g_dinv[i] = rsqrtf((float)g_deg[i] + 1.0f);
}
__global__ void k_gcnt(const int* __restrict__ batch, int n_nodes) {
    int i = blockIdx.x * blockDim.x + threadIdx.x;
    if (i < n_nodes) atomicAdd(&g_gcnt[batch[i]], 1);
}
__global__ void __launch_bounds__(1024)
k_gscan(int n_graphs) {
    __shared__ int s[1024];
    int t = threadIdx.x;
    int base = t * 4;
    int c[4];
#pragma unroll
    for (int j = 0; j < 4; j++)
        c[j] = (base + j < n_graphs) ? g_gcnt[base + j] : 0;
    int tot = c[0] + c[1] + c[2] + c[3];
    s[t] = tot;
    __syncthreads();
#pragma unroll
    for (int off = 1; off < 1024; off <<= 1) {
        int v = (t >= off) ? s[t - off] : 0;
        __syncthreads();
        s[t] += v;
        __syncthreads();
    }
    int off = (t > 0) ? s[t - 1] : 0;
    if (t == 0) g_gptr[0] = 0;
    int run = off;
#pragma unroll
    for (int j = 0; j < 4; j++) {
        run += c[j];
        if (base + j < n_graphs) g_gptr[base + j + 1] = run;
    }
}

// ---------------- W split: fp16 hi/lo, row-major [k][n] ------------------------
__global__ void k_wsplit(const float* __restrict__ W0, const float* __restrict__ W1,
                         const float* __restrict__ W2) {
    const float* W = (blockIdx.x == 0) ? W0 : (blockIdx.x == 1) ? W1 : W2;
    __half* bh = g_Bimg[blockIdx.x][0];
    __half* bl = g_Bimg[blockIdx.x][1];
    for (int idx = threadIdx.x; idx < FDIM * FDIM; idx += 256) {
        float w = W[idx];
        __half hi = __float2half_rn(w);
        __half lo = __float2half_rn(w - __half2float(hi));
        bh[idx] = hi;
        bl[idx] = lo;
    }
}

// ---------------- parallel scan (CSR rowptr) ------------------------------------
__global__ void __launch_bounds__(SCAN_B)
k_bsum(int n_nodes) {
    int i = blockIdx.x * SCAN_B + threadIdx.x;
    int v = (i < n_nodes) ? g_deg[i] : 0;
    for (int off = 16; off > 0; off >>= 1) v += __shfl_down_sync(0xffffffffu, v, off);
    __shared__ int ws[32];
    int lane = threadIdx.x & 31, w = threadIdx.x >> 5;
    if (lane == 0) ws[w] = v;
    __syncthreads();
    if (w == 0) {
        int s = ws[lane];
        for (int off = 16; off > 0; off >>= 1) s += __shfl_down_sync(0xffffffffu, s, off);
        if (lane == 0) g_bsum[blockIdx.x] = s;
    }
}
__global__ void k_bscan(int nblocks) {
    __shared__ int s[MAX_BLK];
    int tid = threadIdx.x;
    int v = (tid < nblocks) ? g_bsum[tid] : 0;
    s[tid] = v;
    __syncthreads();
#pragma unroll
    for (int off = 1; off < MAX_BLK; off <<= 1) {
        int t = (tid >= off) ? s[tid - off] : 0;
        __syncthreads();
        s[tid] += t;
        __syncthreads();
    }
    g_boff[tid] = (tid > 0) ? s[tid - 1] : 0;
}
__global__ void __launch_bounds__(SCAN_B)
k_scanfin(int n_nodes) {
    int i = blockIdx.x * SCAN_B + threadIdx.x;
    int v = (i < n_nodes) ? g_deg[i] : 0;
    int lane = threadIdx.x & 31, w = threadIdx.x >> 5;
    int x = v;
#pragma unroll
    for (int off = 1; off < 32; off <<= 1) {
        int t = __shfl_up_sync(0xffffffffu, x, off);
        if (lane >= off) x += t;
    }
    __shared__ int ws[32];
    if (lane == 31) ws[w] = x;
    __syncthreads();
    if (w == 0) {
        int s = ws[lane];
#pragma unroll
        for (int off = 1; off < 32; off <<= 1) {
            int t = __shfl_up_sync(0xffffffffu, s, off);
            if (lane >= off) s += t;
        }
        ws[lane] = s;
    }
    __syncthreads();
    int incl = x + ((w > 0) ? ws[w - 1] : 0) + g_boff[blockIdx.x];
    if (i < n_nodes) {
        g_rowptr[i + 1] = incl;
        g_cursor[i] = incl - v;
    }
    if (i == 0) g_rowptr[0] = 0;
}
__global__ void k_fill(const int* __restrict__ src, const int* __restrict__ dst,
                       int n_edges) {
    int e = blockIdx.x * blockDim.x + threadIdx.x;
    if (e >= n_edges) return;
    int s = src[e];
    int d = dst[e];
    int pos = atomicAdd(&g_cursor[d], 1);
    float nrm = g_dinv[s] * g_dinv[d];
    g_csr[pos] = make_int2(s, __float_as_int(nrm));
}

// ---------------- wmma GEMM: Hh = act(in) @ W (A fp16, B fp16 hi/lo) -----------
// mode 0: in = Xin (fp32). mode 1: in = g_AGGh (fp16) + BN(from stats[layer-1])+ReLU.
#define SMEM_WM (3 * 128 * LDS_T * 2)   // bytes = 104448

__global__ void __launch_bounds__(256)
k_gemm_wm(const float* __restrict__ Xin, int mode, int layer,
          const float* __restrict__ gma, const float* __restrict__ bta,
          float inv_n, int n_nodes) {
    extern __shared__ __align__(16) __half sm[];
    __half* sA  = sm;
    __half* sBh = sm + 128 * LDS_T;
    __half* sBl = sm + 2 * 128 * LDS_T;
    __shared__ float sSc[FDIM];
    __shared__ float sSh[FDIM];

    const int tid = threadIdx.x;
    const int wid = tid >> 5;
    const int lane = tid & 31;
    const int row0 = blockIdx.x * 128;

    if (mode && tid < FDIM) {
        const float* st = g_stats3[layer - 1];
        float mu = st[tid] * inv_n;
        float var = st[FDIM + tid] * inv_n - mu * mu;
        float rstd = rsqrtf(var + BN_EPS);
        float sc = rstd * gma[tid];
        sSc[tid] = sc;
        sSh[tid] = bta[tid] - mu * sc;
    }

    // load B hi/lo (row-major [k][n]) into padded smem
    {
        const uint4* bh = reinterpret_cast<const uint4*>(g_Bimg[layer][0]);
        const uint4* bl = reinterpret_cast<const uint4*>(g_Bimg[layer][1]);
        for (int i = tid; i < FDIM * FDIM / 8; i += 256) {
            int r = i >> 4;
            int c8 = (i & 15) * 8;
            *reinterpret_cast<uint4*>(&sBh[r * LDS_T + c8]) = bh[i];
            *reinterpret_cast<uint4*>(&sBl[r * LDS_T + c8]) = bl[i];
        }
    }
    if (mode) __syncthreads();

    // load + (BN+ReLU) A tile -> fp16
    for (int i4 = tid; i4 < 4096; i4 += 256) {
        int m = i4 >> 5;
        int q = i4 & 31;
        int k0 = q * 4;
        int gr = row0 + m;
        float4 v = make_float4(0.f, 0.f, 0.f, 0.f);
        if (gr < n_nodes) {
            if (mode) {
                uint2 raw = reinterpret_cast<const uint2*>(g_AGGh)[(size_t)gr * 32 + q];
                v = h4_from_u2(raw);
                v.x = fmaxf(v.x * sSc[k0 + 0] + sSh[k0 + 0], 0.f);
                v.y = fmaxf(v.y * sSc[k0 + 1] + sSh[k0 + 1], 0.f);
                v.z = fmaxf(v.z * sSc[k0 + 2] + sSh[k0 + 2], 0.f);
                v.w = fmaxf(v.w * sSc[k0 + 3] + sSh[k0 + 3], 0.f);
            } else {
                v = reinterpret_cast<const float4*>(Xin)[(size_t)gr * 32 + q];
            }
        }
        *reinterpret_cast<uint2*>(&sA[m * LDS_T + k0]) = u2_from_f4(v);
    }
    __syncthreads();

    const int rt = (wid & 3) * 32;
    const int ctb = (wid >> 2) * 64;

    wmma::fragment<wmma::accumulator, 16, 16, 16, float> acc[2][4];
#pragma unroll
    for (int r = 0; r < 2; r++)
#pragma unroll
        for (int c = 0; c < 4; c++) wmma::fill_fragment(acc[r][c], 0.f);

#pragma unroll
    for (int ks = 0; ks < 8; ks++) {
        const int k0 = ks * 16;
        wmma::fragment<wmma::matrix_a, 16, 16, 16, __half, wmma::row_major> a[2];
        wmma::load_matrix_sync(a[0], &sA[(rt + 0) * LDS_T + k0], LDS_T);
        wmma::load_matrix_sync(a[1], &sA[(rt + 16) * LDS_T + k0], LDS_T);
#pragma unroll
        for (int c = 0; c < 4; c++) {
            wmma::fragment<wmma::matrix_b, 16, 16, 16, __half, wmma::row_major> bh, bl;
            wmma::load_matrix_sync(bh, &sBh[k0 * LDS_T + ctb + c * 16], LDS_T);
            wmma::load_matrix_sync(bl, &sBl[k0 * LDS_T + ctb + c * 16], LDS_T);
#pragma unroll
            for (int r = 0; r < 2; r++) {
                wmma::mma_sync(acc[r][c], a[r], bh, acc[r][c]);
                wmma::mma_sync(acc[r][c], a[r], bl, acc[r][c]);
            }
        }
    }

    // epilogue: stage fp32 accs through smem, emit fp16
    __syncthreads();
    float* stage = reinterpret_cast<float*>(sm) + wid * 2048;   // 32x64 floats/warp
#pragma unroll
    for (int r = 0; r < 2; r++)
#pragma unroll
        for (int c = 0; c < 4; c++)
            wmma::store_matrix_sync(&stage[r * 16 * 64 + c * 16], acc[r][c], 64,
                                    wmma::mem_row_major);
    __syncwarp();
#pragma unroll
    for (int it = 0; it < 16; it++) {
        int r  = it * 2 + (lane >> 4);
        int c4 = (lane & 15) * 4;
        float4 v = *reinterpret_cast<const float4*>(&stage[r * 64 + c4]);
        size_t m = (size_t)(row0 + rt + r);
        *reinterpret_cast<uint2*>(&g_Hh[m * FDIM + ctb + c4]) = u2_from_f4(v);
    }
}

// ---------------- gather: AGGh[d] = sum_in Hh[s]*nrm + Hh[d]*dinv^2 + b --------
__global__ void __launch_bounds__(256)
k_gather(const float* __restrict__ b, int layer, int n_nodes) {
    __shared__ float ssum[FDIM];
    __shared__ float ssq[FDIM];
    if (threadIdx.x < FDIM) { ssum[threadIdx.x] = 0.f; ssq[threadIdx.x] = 0.f; }
    __syncthreads();

    const int lane = threadIdx.x & 31;
    const int warp = threadIdx.x >> 5;
    const int nwarps = gridDim.x * 8;
    const float4 b4 = *reinterpret_cast<const float4*>(&b[lane * 4]);
    const __half* H = g_Hh;
    const int2* __restrict__ csr = g_csr;

    float4 sacc = make_float4(0.f, 0.f, 0.f, 0.f);
    float4 qacc = make_float4(0.f, 0.f, 0.f, 0.f);

    for (int d = blockIdx.x * 8 + warp; d < n_nodes; d += nwarps) {
        const int rs = g_rowptr[d];
        const int re = g_rowptr[d + 1];
        const float di = g_dinv[d];
        const float d2 = di * di;

        float4 h = h4_load(H, d, lane);
        float4 acc = make_float4(h.x * d2 + b4.x, h.y * d2 + b4.y,
                                 h.z * d2 + b4.z, h.w * d2 + b4.w);

        int e = rs;
        // 4-wide pipelined: issue 4 descriptor loads + 4 row gathers, then consume
        for (; e + 4 <= re; e += 4) {
            int2 d0 = csr[e + 0];
            int2 d1 = csr[e + 1];
            int2 d2i = csr[e + 2];
            int2 d3 = csr[e + 3];
            float4 v0 = h4_load(H, d0.x, lane);
            float4 v1 = h4_load(H, d1.x, lane);
            float4 v2 = h4_load(H, d2i.x, lane);
            float4 v3 = h4_load(H, d3.x, lane);
            float n0 = __int_as_float(d0.y);
            float n1 = __int_as_float(d1.y);
            float n2 = __int_as_float(d2i.y);
            float n3 = __int_as_float(d3.y);
            acc.x += v0.x * n0; acc.y += v0.y * n0; acc.z += v0.z * n0; acc.w += v0.w * n0;
            acc.x += v1.x * n1; acc.y += v1.y * n1; acc.z += v1.z * n1; acc.w += v1.w * n1;
            acc.x += v2.x * n2; acc.y += v2.y * n2; acc.z += v2.z * n2; acc.w += v2.w * n2;
            acc.x += v3.x * n3; acc.y += v3.y * n3; acc.z += v3.z * n3; acc.w += v3.w * n3;
        }
        for (; e < re; e++) {
            int2 ed = csr[e];
            float4 v = h4_load(H, ed.x, lane);
            float nj = __int_as_float(ed.y);
            acc.x += v.x * nj; acc.y += v.y * nj;
            acc.z += v.z * nj; acc.w += v.w * nj;
        }

        reinterpret_cast<uint2*>(g_AGGh)[(size_t)d * 32 + lane] = u2_from_f4(acc);
        sacc.x += acc.x; sacc.y += acc.y; sacc.z += acc.z; sacc.w += acc.w;
        qacc.x += acc.x * acc.x; qacc.y += acc.y * acc.y;
        qacc.z += acc.z * acc.z; qacc.w += acc.w * acc.w;
    }

    int c = lane * 4;
    atomicAdd(&ssum[c + 0], sacc.x); atomicAdd(&ssum[c + 1], sacc.y);
    atomicAdd(&ssum[c + 2], sacc.z); atomicAdd(&ssum[c + 3], sacc.w);
    atomicAdd(&ssq[c + 0], qacc.x);  atomicAdd(&ssq[c + 1], qacc.y);
    atomicAdd(&ssq[c + 2], qacc.z);  atomicAdd(&ssq[c + 3], qacc.w);
    __syncthreads();
    if (threadIdx.x < FDIM) {
        atomicAdd(&g_stats3[layer][threadIdx.x], ssum[threadIdx.x]);
        atomicAdd(&g_stats3[layer][FDIM + threadIdx.x], ssq[threadIdx.x]);
    }
}

// ---------------- pool: warp per graph, atomic-free; BN from stats[2] ----------
__global__ void __launch_bounds__(256)
k_pool2(const float* __restrict__ gma, const float* __restrict__ bta,
        float inv_n, int n_graphs) {
    __shared__ float sSc[FDIM];
    __shared__ float sSh[FDIM];
    if (threadIdx.x < FDIM) {
        const float* st = g_stats3[2];
        float mu = st[threadIdx.x] * inv_n;
        float var = st[FDIM + threadIdx.x] * inv_n - mu * mu;
        float rstd = rsqrtf(var + BN_EPS);
        float sc = rstd * gma[threadIdx.x];
        sSc[threadIdx.x] = sc;
        sSh[threadIdx.x] = bta[threadIdx.x] - mu * sc;
    }
    __syncthreads();

    int g = blockIdx.x * 8 + (threadIdx.x >> 5);
    int lane = threadIdx.x & 31;
    if (g >= n_graphs) return;
    int s = g_gptr[g], e = g_gptr[g + 1];
    int c = lane * 4;
    float4 sc = *reinterpret_cast<const float4*>(&sSc[c]);
    float4 sh = *reinterpret_cast<const float4*>(&sSh[c]);
    float4 acc = make_float4(0.f, 0.f, 0.f, 0.f);
    for (int n = s; n < e; n++) {
        float4 v = h4_from_u2(reinterpret_cast<const uint2*>(g_AGGh)[(size_t)n * 32 + lane]);
        acc.x += fmaxf(v.x * sc.x + sh.x, 0.f);
        acc.y += fmaxf(v.y * sc.y + sh.y, 0.f);
        acc.z += fmaxf(v.z * sc.z + sh.z, 0.f);
        acc.w += fmaxf(v.w * sc.w + sh.w, 0.f);
    }
    float inv = 1.0f / fmaxf((float)(e - s), 1.0f);
    float4 o = make_float4(acc.x * inv, acc.y * inv, acc.z * inv, acc.w * inv);
    *reinterpret_cast<float4*>(&g_pool[(size_t)g * FDIM + c]) = o;
}

// ---------------- final FC ------------------------------------------------------
__global__ void __launch_bounds__(256)
k_fc(const float* __restrict__ fcW, const float* __restrict__ fcb,
     float* __restrict__ out, int n_graphs) {
    __shared__ float sW[FDIM * 64];
    for (int l = threadIdx.x; l < FDIM * 64; l += 256) sW[l] = fcW[l];
    __syncthreads();
    int g = blockIdx.x * 4 + (threadIdx.x >> 6);
    int c = threadIdx.x & 63;
    if (g >= n_graphs) return;
    float acc = 0.f;
#pragma unroll 16
    for (int k = 0; k < FDIM; k++) acc += g_pool[(size_t)g * FDIM + k] * sW[k * 64 + c];
    out[(size_t)g * 64 + c] = acc + fcb[c];
}

// ---------------- launch ---------------------------------------------------------
extern "C" void kernel_launch(void* const* d_in, const int* in_sizes, int n_in,
                              void* d_out, int out_size) {
    const float* x     = (const float*)d_in[0];
    const int*   ei    = (const int*)d_in[1];
    const int*   batch = (const int*)d_in[2];
    const float* W1 = (const float*)d_in[3];
    const float* b1 = (const float*)d_in[4];
    const float* g1 = (const float*)d_in[5];
    const float* be1 = (const float*)d_in[6];
    const float* W2 = (const float*)d_in[7];
    const float* b2 = (const float*)d_in[8];
    const float* g2 = (const float*)d_in[9];
    const float* be2 = (const float*)d_in[10];
    const float* W3 = (const float*)d_in[11];
    const float* b3 = (const float*)d_in[12];
    const float* g3 = (const float*)d_in[13];
    const float* be3 = (const float*)d_in[14];
    const float* fcW = (const float*)d_in[15];
    const float* fcb = (const float*)d_in[16];
    float* out = (float*)d_out;

    const int n_nodes  = in_sizes[0] / FDIM;
    const int n_edges  = in_sizes[1] / 2;
    const int n_graphs = out_size / 64;
    const int* src = ei;
    const int* dst = ei + n_edges;
    const int nblocks = (n_nodes + SCAN_B - 1) / SCAN_B;
    const float inv_n = 1.0f / (float)n_nodes;

    static cudaStream_t s2 = nullptr;
    static cudaEvent_t evF = nullptr, evJ = nullptr;
    if (!s2) {
        cudaFuncSetAttribute(k_gemm_wm, cudaFuncAttributeMaxDynamicSharedMemorySize,
                             SMEM_WM);
        cudaStreamCreateWithFlags(&s2, cudaStreamNonBlocking);
        cudaEventCreateWithFlags(&evF, cudaEventDisableTiming);
        cudaEventCreateWithFlags(&evJ, cudaEventDisableTiming);
    }

    // ---- init (main stream) ----
    {
        int work = n_nodes;
        if (n_graphs > work) work = n_graphs;
        k_zero<<<(work + 255) / 256, 256>>>(n_nodes, n_graphs);
    }

    // ---- fork: CSR + graph-ptr build on s2, concurrent with wsplit + gemm0 ----
    cudaEventRecord(evF, 0);
    cudaStreamWaitEvent(s2, evF, 0);
    k_deg<<<(n_edges + 255) / 256, 256, 0, s2>>>(dst, n_edges);
    k_dinv<<<(n_nodes + 255) / 256, 256, 0, s2>>>(n_nodes);
    k_bsum<<<nblocks, SCAN_B, 0, s2>>>(n_nodes);
    k_bscan<<<1, MAX_BLK, 0, s2>>>(nblocks);
    k_scanfin<<<nblocks, SCAN_B, 0, s2>>>(n_nodes);
    k_fill<<<(n_edges + 255) / 256, 256, 0, s2>>>(src, dst, n_edges);
    k_gcnt<<<(n_nodes + 255) / 256, 256, 0, s2>>>(batch, n_nodes);
    k_gscan<<<1, 1024, 0, s2>>>(n_graphs);
    cudaEventRecord(evJ, s2);

    const int gemm_grid   = (n_nodes + 127) / 128;
    const int gather_grid = 1184;

    k_wsplit<<<3, 256>>>(W1, W2, W3);
    k_gemm_wm<<<gemm_grid, 256, SMEM_WM>>>(x, 0, 0, g1, be1, inv_n, n_nodes);

    cudaStreamWaitEvent(0, evJ, 0);   // join: gather needs CSR

    const float* bs[3]  = {b1, b2, b3};
    const float* gs[3]  = {g1, g2, g3};
    const float* bes[3] = {be1, be2, be3};

    for (int layer = 0; layer < 3; layer++) {
        if (layer > 0)
            k_gemm_wm<<<gemm_grid, 256, SMEM_WM>>>(nullptr, 1, layer,
                                                   gs[layer - 1], bes[layer - 1],
                                                   inv_n, n_nodes);
        k_gather<<<gather_grid, 256>>>(bs[layer], layer, n_nodes);
    }

    k_pool2<<<(n_graphs + 7) / 8, 256>>>(g3, be3, inv_n, n_graphs);
    k_fc<<<(n_graphs + 3) / 4, 256>>>(fcW, fcb, out, n_graphs);
}